// round 7
// baseline (speedup 1.0000x reference)
#include <cuda_runtime.h>
#include <cuda_fp16.h>
#include <cstdint>

#define NMAX 100000

__device__ float    g_gcx[NMAX * 64];
__device__ float    g_gsx[NMAX * 64];
__device__ unsigned g_aggc[NMAX * 320];  // [q 0:128 | maxkey 128:192 | minkey 192:256 | ksum 256]
__device__ unsigned g_aggs[NMAX * 320];
__device__ float    g_p1[NMAX * 128];
__device__ float    g_p2[NMAX * 128];

__device__ __forceinline__ unsigned fkey(float f) {
    unsigned u = __float_as_uint(f);
    return (u & 0x80000000u) ? ~u : (u | 0x80000000u);
}
__device__ __forceinline__ float fdec(unsigned k) {
    unsigned u = (k & 0x80000000u) ? (k & 0x7FFFFFFFu) : ~k;
    return __uint_as_float(u);
}
__device__ __forceinline__ uint32_t smem_to_u32(const void* p) {
    uint32_t a;
    asm("{ .reg .u64 t; cvta.to.shared.u64 t, %1; cvt.u32.u64 %0, t; }" : "=r"(a) : "l"(p));
    return a;
}
__device__ __forceinline__ void ldsm_x4(uint32_t a[4], uint32_t addr) {
    asm volatile("ldmatrix.sync.aligned.m8n8.x4.shared.b16 {%0,%1,%2,%3}, [%4];"
        : "=r"(a[0]), "=r"(a[1]), "=r"(a[2]), "=r"(a[3]) : "r"(addr));
}
__device__ __forceinline__ void ldsm_x2(uint32_t b[2], uint32_t addr) {
    asm volatile("ldmatrix.sync.aligned.m8n8.x2.shared.b16 {%0,%1}, [%2];"
        : "=r"(b[0]), "=r"(b[1]) : "r"(addr));
}
__device__ __forceinline__ void mma_f16(float c[4], const uint32_t a[4], const uint32_t b[2]) {
    asm volatile("mma.sync.aligned.m16n8k16.row.col.f32.f16.f16.f32 "
        "{%0,%1,%2,%3}, {%4,%5,%6,%7}, {%8,%9}, {%0,%1,%2,%3};"
        : "+f"(c[0]), "+f"(c[1]), "+f"(c[2]), "+f"(c[3])
        : "r"(a[0]), "r"(a[1]), "r"(a[2]), "r"(a[3]), "r"(b[0]), "r"(b[1]));
}
__device__ __forceinline__ uint32_t packh(__half a, __half b) {
    return (uint32_t)__half_as_ushort(a) | ((uint32_t)__half_as_ushort(b) << 16);
}

// ---------------- embed + init ----------------
__global__ void embed_kernel(const float* __restrict__ nf, const float* __restrict__ w,
                             const float* __restrict__ b, float* __restrict__ out, int N, int F) {
    int idx = blockIdx.x * blockDim.x + threadIdx.x;
    if (idx >= N * 64) return;
    int n = idx >> 6, h = idx & 63;
    const float* row = nf + (size_t)n * F;
    float acc = b[h];
    for (int f = 0; f < F; f++) acc = fmaf(__ldg(row + f), __ldg(w + f * 64 + h), acc);
    out[idx] = acc;
}
__global__ void init_agg_kernel(unsigned* __restrict__ a, int total) {
    int idx = blockIdx.x * blockDim.x + threadIdx.x;
    if (idx < total) {
        int col = idx % 320;
        a[idx] = (col >= 192 && col < 256) ? 0xFFFFFFFFu : 0u;
    }
}

// ---------------- proj: out[n][0:128] = x[n][0:64] @ W(64x128) --------------
// smem bytes: s_w 32768 | s_x 8704
#define PR_SMEM 41472
__global__ void __launch_bounds__(256, 1) proj_kernel(
    const float* __restrict__ x, const float* __restrict__ w,
    float* __restrict__ out, int N) {
    extern __shared__ float sp[];
    float* s_w = sp;          // [64][128]
    float* s_x = sp + 8192;   // [32][68]
    const int tid = threadIdx.x;
    for (int i = tid; i < 2048; i += 256) ((float4*)s_w)[i] = ((const float4*)w)[i];
    __syncthreads();
    const int n = tid >> 3, jg = tid & 7;
    const int ntiles = (N + 31) >> 5;
    for (int tile = blockIdx.x; tile < ntiles; tile += gridDim.x) {
        const int n0 = tile * 32;
        __syncthreads();
        for (int idx = tid; idx < 2048; idx += 256) {
            int nn = idx >> 6, f = idx & 63, gn = n0 + nn;
            s_x[nn * 68 + f] = (gn < N) ? __ldg(x + (size_t)gn * 64 + f) : 0.f;
        }
        __syncthreads();
        float acc[16];
        #pragma unroll
        for (int t = 0; t < 16; t++) acc[t] = 0.f;
        const float* xr = s_x + n * 68;
        #pragma unroll 4
        for (int f = 0; f < 64; f++) {
            float xv = xr[f];
            const float* wr = s_w + f * 128 + jg * 16;
            #pragma unroll
            for (int t = 0; t < 16; t++) acc[t] = fmaf(xv, wr[t], acc[t]);
        }
        int gn = n0 + n;
        if (gn < N) {
            float* op = out + (size_t)gn * 128 + jg * 16;
            #pragma unroll
            for (int t = 0; t < 4; t++)
                ((float4*)op)[t] = make_float4(acc[4*t], acc[4*t+1], acc[4*t+2], acc[4*t+3]);
        }
    }
}

// ================= edge kernel: h=relu(p1[s]+p2[d]+b1); gate; q+=k*h;
//                  f2/f3 = (h @ W2[:,65:193] + b)*k -> atomicMax/Min ==========
#define PADH 136
#define EG_HH 0
#define EG_HL 34816
#define EG_W  69632
#define EG_WG 104448
#define EG_B1 104960
#define EG_B2 105472
#define EG_K  105984
#define EG_DST 106496
#define EG_BG 107008
#define EG_SMEM 107024

__global__ void __launch_bounds__(256, 1) edge_kernel(
    const float* __restrict__ p1, const float* __restrict__ p2,
    const int* __restrict__ src, const int* __restrict__ dst,
    const float* __restrict__ w2, const float* __restrict__ b1,
    const float* __restrict__ b2,
    unsigned* __restrict__ agg, int E) {
    extern __shared__ char sm[];
    const uint32_t smb = smem_to_u32(sm);
    const int tid = threadIdx.x, lane = tid & 31, wid = tid >> 5;
    __half* s_w = (__half*)(sm + EG_W);
    float* s_wg = (float*)(sm + EG_WG);
    float* s_b1 = (float*)(sm + EG_B1);
    float* s_b2f = (float*)(sm + EG_B2);
    float* s_k = (float*)(sm + EG_K);
    int* s_dst = (int*)(sm + EG_DST);
    float* s_bg = (float*)(sm + EG_BG);

    // stage W2 max/min cols (65..193) as fp16 [n=128][k=128]
    for (int idx = tid; idx < 128 * 128; idx += 256) {
        int n = idx & 127, k = idx >> 7;
        s_w[n * PADH + k] = __float2half_rn(__ldg(w2 + k * 257 + 65 + n));
    }
    if (tid < 128) {
        s_wg[tid] = __ldg(w2 + tid * 257);
        s_b1[tid] = __ldg(b1 + tid);
        s_b2f[tid] = __ldg(b2 + 65 + tid);
    }
    if (tid == 0) s_bg[0] = __ldg(b2);
    __syncthreads();

    // hoist B fragments (warp owns 16 cols)
    uint32_t Bw[2][8][2];
    #pragma unroll
    for (int nf = 0; nf < 2; nf++)
        #pragma unroll
        for (int kf = 0; kf < 8; kf++) {
            uint32_t off = (uint32_t)((wid * 16 + nf * 8 + (lane & 7)) * PADH
                            + kf * 16 + (((lane >> 3) & 1) << 3)) * 2;
            ldsm_x2(Bw[nf][kf], smb + EG_W + off);
        }

    const int eloc = tid >> 1, half = tid & 1;
    const int ntiles = (E + 127) >> 7;
    for (int t = blockIdx.x; t < ntiles; t += gridDim.x) {
        const int tb = t * 128;
        __syncthreads();
        const int e = tb + eloc;
        const bool valid = e < E;
        const int si = valid ? __ldg(src + e) : 0;
        const int di = valid ? __ldg(dst + e) : 0;
        if (half == 0) s_dst[eloc] = di;
        const float4* pa = (const float4*)(p1 + (size_t)si * 128 + half * 64);
        const float4* pb = (const float4*)(p2 + (size_t)di * 128 + half * 64);
        float h[64];
        float g = 0.f;
        #pragma unroll
        for (int q = 0; q < 16; q++) {
            float4 va = __ldg(pa + q), vb = __ldg(pb + q);
            float4 bv = ((const float4*)s_b1)[half * 16 + q];
            float4 wv = ((const float4*)s_wg)[half * 16 + q];
            float h0 = fmaxf(va.x + vb.x + bv.x, 0.f);
            float h1 = fmaxf(va.y + vb.y + bv.y, 0.f);
            float h2 = fmaxf(va.z + vb.z + bv.z, 0.f);
            float h3 = fmaxf(va.w + vb.w + bv.w, 0.f);
            g = fmaf(h0, wv.x, g); g = fmaf(h1, wv.y, g);
            g = fmaf(h2, wv.z, g); g = fmaf(h3, wv.w, g);
            h[q * 4] = h0; h[q * 4 + 1] = h1; h[q * 4 + 2] = h2; h[q * 4 + 3] = h3;
            __half a0 = __float2half_rn(h0), a1 = __float2half_rn(h1);
            __half a2 = __float2half_rn(h2), a3 = __float2half_rn(h3);
            __half l0 = __float2half_rn(h0 - __half2float(a0));
            __half l1 = __float2half_rn(h1 - __half2float(a1));
            __half l2 = __float2half_rn(h2 - __half2float(a2));
            __half l3 = __float2half_rn(h3 - __half2float(a3));
            uint32_t off = (uint32_t)(eloc * PADH + half * 64 + q * 4) * 2;
            *(uint32_t*)(sm + EG_HH + off) = packh(a0, a1);
            *(uint32_t*)(sm + EG_HH + off + 4) = packh(a2, a3);
            *(uint32_t*)(sm + EG_HL + off) = packh(l0, l1);
            *(uint32_t*)(sm + EG_HL + off + 4) = packh(l2, l3);
        }
        g += __shfl_xor_sync(0xffffffffu, g, 1);
        float kk = 1.f / (1.f + __expf(-(g + s_bg[0])));
        if (half == 0) s_k[eloc] = kk;
        if (valid) {
            float* qb = (float*)(agg + (size_t)di * 320) + half * 64;
            #pragma unroll
            for (int q2 = 0; q2 < 32; q2++)
                atomicAdd((float2*)(qb + q2 * 2), make_float2(kk * h[q2 * 2], kk * h[q2 * 2 + 1]));
            if (half == 0) atomicAdd((float*)(agg + (size_t)di * 320 + 256), kk);
        }
        __syncthreads();

        // mma: f2|f3 (128 cols), 2-term fp16
        #pragma unroll 1
        for (int mt = 0; mt < 8; mt++) {
            float c[2][4] = {};
            #pragma unroll
            for (int kf = 0; kf < 8; kf++) {
                uint32_t Ah[4], Al[4];
                uint32_t aoff = (uint32_t)((mt * 16 + (lane & 15)) * PADH
                                 + kf * 16 + ((lane >> 4) << 3)) * 2;
                ldsm_x4(Ah, smb + EG_HH + aoff);
                ldsm_x4(Al, smb + EG_HL + aoff);
                #pragma unroll
                for (int nf = 0; nf < 2; nf++) {
                    mma_f16(c[nf], Ah, Bw[nf][kf]);
                    mma_f16(c[nf], Al, Bw[nf][kf]);
                }
            }
            int r0 = mt * 16 + (lane >> 2), r1 = r0 + 8;
            bool v0 = tb + r0 < E, v1 = tb + r1 < E;
            float k0 = s_k[r0], k1 = s_k[r1];
            unsigned* row0 = agg + (size_t)s_dst[r0] * 320;
            unsigned* row1 = agg + (size_t)s_dst[r1] * 320;
            #pragma unroll
            for (int nf = 0; nf < 2; nf++) {
                int cm = wid * 16 + nf * 8 + (lane & 3) * 2;
                float ba = s_b2f[cm], bb = s_b2f[cm + 1];
                float v00 = (c[nf][0] + ba) * k0, v01 = (c[nf][1] + bb) * k0;
                float v10 = (c[nf][2] + ba) * k1, v11 = (c[nf][3] + bb) * k1;
                if (wid < 4) {  // f2 -> max, keys at 128+cm
                    if (v0) { atomicMax(row0 + 128 + cm, fkey(v00)); atomicMax(row0 + 129 + cm, fkey(v01)); }
                    if (v1) { atomicMax(row1 + 128 + cm, fkey(v10)); atomicMax(row1 + 129 + cm, fkey(v11)); }
                } else {        // f3 -> min, cm in [64,128) -> 128+cm = 192..255
                    if (v0) { atomicMin(row0 + 128 + cm, fkey(v00)); atomicMin(row0 + 129 + cm, fkey(v01)); }
                    if (v1) { atomicMin(row1 + 128 + cm, fkey(v10)); atomicMin(row1 + 129 + cm, fkey(v11)); }
                }
            }
        }
    }
}

// ---------------- finish: q -> [n1|n4] in place ----------------
// smem bytes: s_w1 32768 | s_w4 32768 | s_q 16896 | s_ks 128 | s_b 512
#define FIN_SMEM 83072
__global__ void __launch_bounds__(256, 1) finish_kernel(
    unsigned* __restrict__ agg, const float* __restrict__ w2,
    const float* __restrict__ b2, int N) {
    extern __shared__ float sf[];
    float* s_w1 = sf;            // [128][64]
    float* s_w4 = sf + 8192;     // [128][64]
    float* s_q  = sf + 16384;    // [32][132]
    float* s_ks = sf + 20608;    // [32]
    float* s_b  = sf + 20640;    // [128]
    const int tid = threadIdx.x;
    for (int idx = tid; idx < 128 * 64; idx += 256) {
        int k = idx >> 6, j = idx & 63;
        s_w1[idx] = __ldg(w2 + k * 257 + 1 + j);
        s_w4[idx] = __ldg(w2 + k * 257 + 193 + j);
    }
    if (tid < 64) { s_b[tid] = __ldg(b2 + 1 + tid); s_b[64 + tid] = __ldg(b2 + 193 + tid); }
    __syncthreads();
    const int n = tid >> 3, jg = tid & 7;
    const int ntiles = (N + 31) >> 5;
    for (int tile = blockIdx.x; tile < ntiles; tile += gridDim.x) {
        const int n0 = tile * 32;
        __syncthreads();
        for (int idx = tid; idx < 32 * 128; idx += 256) {
            int nn = idx >> 7, k = idx & 127, gn = n0 + nn;
            s_q[nn * 132 + k] = (gn < N) ? __uint_as_float(__ldg(agg + (size_t)gn * 320 + k)) : 0.f;
        }
        if (tid < 32) {
            int gn = n0 + tid;
            s_ks[tid] = (gn < N) ? __uint_as_float(__ldg(agg + (size_t)gn * 320 + 256)) : 0.f;
        }
        __syncthreads();
        float a1[8], a4[8];
        #pragma unroll
        for (int t = 0; t < 8; t++) { a1[t] = 0.f; a4[t] = 0.f; }
        const float* qr = s_q + n * 132;
        #pragma unroll 4
        for (int k = 0; k < 128; k++) {
            float qv = qr[k];
            const float* w1r = s_w1 + k * 64 + jg * 8;
            const float* w4r = s_w4 + k * 64 + jg * 8;
            #pragma unroll
            for (int t = 0; t < 8; t++) {
                a1[t] = fmaf(qv, w1r[t], a1[t]);
                a4[t] = fmaf(qv, w4r[t], a4[t]);
            }
        }
        float ks = s_ks[n];
        __syncthreads();
        int gn = n0 + n;
        if (gn < N) {
            float* row = (float*)(agg + (size_t)gn * 320);
            #pragma unroll
            for (int t = 0; t < 8; t++) {
                row[jg * 8 + t] = a1[t] + ks * s_b[jg * 8 + t];
                row[64 + jg * 8 + t] = a4[t] + ks * s_b[64 + jg * 8 + t];
            }
        }
    }
}

// ---------------- node kernel ----------------
#define NODE_SMEM_FLOATS (20480 + 8192 + 4096 + 64 + 64 + 64 + 32*321 + 32*68 + 32*132)
__global__ void __launch_bounds__(256, 1) node_kernel(
    const float* __restrict__ x, const unsigned* __restrict__ agg,
    const float* __restrict__ rw, const float* __restrict__ rb,
    const float* __restrict__ w1, const float* __restrict__ b1,
    const float* __restrict__ w2, const float* __restrict__ b2,
    float* __restrict__ out, int N) {
    extern __shared__ float smf[];
    float* s_rw = smf;
    float* s_w1 = smf + 20480;
    float* s_w2 = smf + 28672;
    float* s_rb = smf + 32768;
    float* s_b1 = smf + 32832;
    float* s_b2 = smf + 32896;
    float* s_z  = smf + 32960;
    float* s_nx = smf + 43232;
    float* s_h  = smf + 45408;

    const int tid = threadIdx.x;
    for (int i = tid; i < 5120; i += 256) ((float4*)s_rw)[i] = ((const float4*)rw)[i];
    for (int i = tid; i < 2048; i += 256) ((float4*)s_w1)[i] = ((const float4*)w1)[i];
    for (int i = tid; i < 1024; i += 256) ((float4*)s_w2)[i] = ((const float4*)w2)[i];
    if (tid < 64) { s_rb[tid] = rb[tid]; s_b1[tid] = b1[tid]; s_b2[tid] = b2[tid]; }
    __syncthreads();

    const int n = tid >> 3, jg = tid & 7;
    const int ntiles = (N + 31) >> 5;
    for (int tile = blockIdx.x; tile < ntiles; tile += gridDim.x) {
        const int n0 = tile * 32;
        for (int idx = tid; idx < 32 * 320; idx += 256) {
            int nn = idx / 320, i = idx - nn * 320;
            int gn = n0 + nn;
            float v = 0.f;
            if (gn < N) {
                if (i < 64) v = __ldg(x + (size_t)gn * 64 + i);
                else {
                    int c = i - 64;
                    const unsigned* row = agg + (size_t)gn * 320;
                    if (c < 64) v = __uint_as_float(__ldg(row + c));
                    else if (c < 128) { unsigned r = __ldg(row + 64 + c); v = r ? fdec(r) : 0.f; }
                    else if (c < 192) { unsigned r = __ldg(row + 64 + c); v = (r == 0xFFFFFFFFu) ? 0.f : fdec(r); }
                    else v = __uint_as_float(__ldg(row + c - 128));
                }
            }
            s_z[nn * 321 + i] = v;
        }
        __syncthreads();

        const float* zrow = s_z + n * 321;
        float4 A = ((float4*)s_rb)[jg * 2], B = ((float4*)s_rb)[jg * 2 + 1];
        #pragma unroll 4
        for (int i = 0; i < 320; i++) {
            float zz = zrow[i];
            float4 wA = ((float4*)s_rw)[i * 16 + jg * 2];
            float4 wB = ((float4*)s_rw)[i * 16 + jg * 2 + 1];
            A.x = fmaf(zz, wA.x, A.x); A.y = fmaf(zz, wA.y, A.y);
            A.z = fmaf(zz, wA.z, A.z); A.w = fmaf(zz, wA.w, A.w);
            B.x = fmaf(zz, wB.x, B.x); B.y = fmaf(zz, wB.y, B.y);
            B.z = fmaf(zz, wB.z, B.z); B.w = fmaf(zz, wB.w, B.w);
        }
        ((float4*)(s_nx + n * 68))[jg * 2] = A;
        ((float4*)(s_nx + n * 68))[jg * 2 + 1] = B;
        __syncwarp();

        float hacc[16];
        #pragma unroll
        for (int tt = 0; tt < 16; tt++) hacc[tt] = s_b1[jg * 16 + tt];
        #pragma unroll 2
        for (int i = 0; i < 64; i++) {
            float in = zrow[i];
            const float* wr = s_w1 + i * 64 + jg * 16;
            #pragma unroll
            for (int tt = 0; tt < 16; tt++) hacc[tt] = fmaf(in, wr[tt], hacc[tt]);
        }
        const float* nxrow = s_nx + n * 68;
        #pragma unroll 2
        for (int i = 0; i < 64; i++) {
            float in = nxrow[i];
            const float* wr = s_w1 + (64 + i) * 64 + jg * 16;
            #pragma unroll
            for (int tt = 0; tt < 16; tt++) hacc[tt] = fmaf(in, wr[tt], hacc[tt]);
        }
        #pragma unroll
        for (int tt = 0; tt < 16; tt++) s_h[n * 132 + jg * 16 + tt] = fmaxf(hacc[tt], 0.f);
        __syncwarp();

        float4 O0 = ((float4*)s_b2)[jg * 2], O1 = ((float4*)s_b2)[jg * 2 + 1];
        const float* hrow = s_h + n * 132;
        #pragma unroll 4
        for (int i = 0; i < 64; i++) {
            float hv = hrow[i];
            float4 wA = ((float4*)s_w2)[i * 16 + jg * 2];
            float4 wB = ((float4*)s_w2)[i * 16 + jg * 2 + 1];
            O0.x = fmaf(hv, wA.x, O0.x); O0.y = fmaf(hv, wA.y, O0.y);
            O0.z = fmaf(hv, wA.z, O0.z); O0.w = fmaf(hv, wA.w, O0.w);
            O1.x = fmaf(hv, wB.x, O1.x); O1.y = fmaf(hv, wB.y, O1.y);
            O1.w = O1.w; O1.z = fmaf(hv, wB.z, O1.z); O1.w = fmaf(hv, wB.w, O1.w);
        }
        int gn = n0 + n;
        if (gn < N) {
            ((float4*)(out + (size_t)gn * 64 + jg * 8))[0] = O0;
            ((float4*)(out + (size_t)gn * 64 + jg * 8))[1] = O1;
        }
        __syncthreads();
    }
}

// ---------------------------------------------------------------------------
extern "C" void kernel_launch(void* const* d_in, const int* in_sizes, int n_in,
                              void* d_out, int out_size) {
    const float* nf_gc  = (const float*)d_in[0];
    const float* nf_gs  = (const float*)d_in[1];
    const float* w_gc   = (const float*)d_in[2];
    const float* b_gc   = (const float*)d_in[3];
    const float* w_gs   = (const float*)d_in[4];
    const float* b_gs   = (const float*)d_in[5];
    const float* s2c_w1 = (const float*)d_in[6];
    const float* s2c_b1 = (const float*)d_in[7];
    const float* s2c_w2 = (const float*)d_in[8];
    const float* s2c_b2 = (const float*)d_in[9];
    const float* s2c_rw = (const float*)d_in[10];
    const float* s2c_rb = (const float*)d_in[11];
    const float* c2s_w1 = (const float*)d_in[12];
    const float* c2s_b1 = (const float*)d_in[13];
    const float* c2s_w2 = (const float*)d_in[14];
    const float* c2s_b2 = (const float*)d_in[15];
    const float* c2s_rw = (const float*)d_in[16];
    const float* c2s_rb = (const float*)d_in[17];
    const float* gc_w1  = (const float*)d_in[18];
    const float* gc_b1  = (const float*)d_in[19];
    const float* gc_w2  = (const float*)d_in[20];
    const float* gc_b2  = (const float*)d_in[21];
    const float* gs_w1  = (const float*)d_in[22];
    const float* gs_b1  = (const float*)d_in[23];
    const float* gs_w2  = (const float*)d_in[24];
    const float* gs_b2  = (const float*)d_in[25];
    const int* s2c_src  = (const int*)d_in[26];
    const int* s2c_dst  = (const int*)d_in[27];
    const int* c2s_src  = (const int*)d_in[28];
    const int* c2s_dst  = (const int*)d_in[29];

    const int FGC = in_sizes[2] / 64;
    const int FGS = in_sizes[4] / 64;
    const int NGC = in_sizes[0] / FGC;
    const int NGS = in_sizes[1] / FGS;
    const int E1 = in_sizes[26];
    const int E2 = in_sizes[28];

    float *gcx, *gsx, *p1, *p2;
    unsigned *aggc, *aggs;
    cudaGetSymbolAddress((void**)&gcx, g_gcx);
    cudaGetSymbolAddress((void**)&gsx, g_gsx);
    cudaGetSymbolAddress((void**)&aggc, g_aggc);
    cudaGetSymbolAddress((void**)&aggs, g_aggs);
    cudaGetSymbolAddress((void**)&p1, g_p1);
    cudaGetSymbolAddress((void**)&p2, g_p2);

    const int NODE_SMEM = NODE_SMEM_FLOATS * 4;
    cudaFuncSetAttribute(edge_kernel, cudaFuncAttributeMaxDynamicSharedMemorySize, EG_SMEM);
    cudaFuncSetAttribute(node_kernel, cudaFuncAttributeMaxDynamicSharedMemorySize, NODE_SMEM);
    cudaFuncSetAttribute(finish_kernel, cudaFuncAttributeMaxDynamicSharedMemorySize, FIN_SMEM);
    cudaFuncSetAttribute(proj_kernel, cudaFuncAttributeMaxDynamicSharedMemorySize, PR_SMEM);

    embed_kernel<<<(NGC * 64 + 255) / 256, 256>>>(nf_gc, w_gc, b_gc, gcx, NGC, FGC);
    embed_kernel<<<(NGS * 64 + 255) / 256, 256>>>(nf_gs, w_gs, b_gs, gsx, NGS, FGS);
    init_agg_kernel<<<(NGC * 320 + 255) / 256, 256>>>(aggc, NGC * 320);
    init_agg_kernel<<<(NGS * 320 + 255) / 256, 256>>>(aggs, NGS * 320);

    // dir 1: gs -> gc
    proj_kernel<<<152, 256, PR_SMEM>>>(gsx, s2c_w1, p1, NGS);
    proj_kernel<<<152, 256, PR_SMEM>>>(gcx, s2c_w1 + 64 * 128, p2, NGC);
    edge_kernel<<<152, 256, EG_SMEM>>>(p1, p2, s2c_src, s2c_dst,
                                       s2c_w2, s2c_b1, s2c_b2, aggc, E1);
    finish_kernel<<<152, 256, FIN_SMEM>>>(aggc, s2c_w2, s2c_b2, NGC);
    // dir 2: gc -> gs
    proj_kernel<<<152, 256, PR_SMEM>>>(gcx, c2s_w1, p1, NGC);
    proj_kernel<<<152, 256, PR_SMEM>>>(gsx, c2s_w1 + 64 * 128, p2, NGS);
    edge_kernel<<<152, 256, EG_SMEM>>>(p1, p2, c2s_src, c2s_dst,
                                       c2s_w2, c2s_b1, c2s_b2, aggs, E2);
    finish_kernel<<<152, 256, FIN_SMEM>>>(aggs, c2s_w2, c2s_b2, NGS);

    float* out = (float*)d_out;
    node_kernel<<<152, 256, NODE_SMEM>>>(gcx, aggc, s2c_rw, s2c_rb,
                                         gc_w1, gc_b1, gc_w2, gc_b2, out, NGC);
    node_kernel<<<152, 256, NODE_SMEM>>>(gsx, aggs, c2s_rw, c2s_rb,
                                         gs_w1, gs_b1, gs_w2, gs_b2, out + (size_t)NGC * 64, NGS);
}

// round 8
// speedup vs baseline: 1.2077x; 1.2077x over previous
#include <cuda_runtime.h>
#include <cuda_fp16.h>
#include <cstdint>

#define NMAX 100000

__device__ float    g_gcx[NMAX * 64];
__device__ float    g_gsx[NMAX * 64];
__device__ unsigned g_aggc[NMAX * 320];  // [q/n1n4 0:128 | maxkey 128:192 | minkey 192:256 | ksum 256]
__device__ unsigned g_aggs[NMAX * 320];

__device__ __forceinline__ unsigned fkey(float f) {
    unsigned u = __float_as_uint(f);
    return (u & 0x80000000u) ? ~u : (u | 0x80000000u);
}
__device__ __forceinline__ float fdec(unsigned k) {
    unsigned u = (k & 0x80000000u) ? (k & 0x7FFFFFFFu) : ~k;
    return __uint_as_float(u);
}
__device__ __forceinline__ uint32_t smem_to_u32(const void* p) {
    uint32_t a;
    asm("{ .reg .u64 t; cvta.to.shared.u64 t, %1; cvt.u32.u64 %0, t; }" : "=r"(a) : "l"(p));
    return a;
}
__device__ __forceinline__ void ldsm_x4(uint32_t a[4], uint32_t addr) {
    asm volatile("ldmatrix.sync.aligned.m8n8.x4.shared.b16 {%0,%1,%2,%3}, [%4];"
        : "=r"(a[0]), "=r"(a[1]), "=r"(a[2]), "=r"(a[3]) : "r"(addr));
}
__device__ __forceinline__ void ldsm_x2(uint32_t b[2], uint32_t addr) {
    asm volatile("ldmatrix.sync.aligned.m8n8.x2.shared.b16 {%0,%1}, [%2];"
        : "=r"(b[0]), "=r"(b[1]) : "r"(addr));
}
__device__ __forceinline__ void mma_f16(float c[4], const uint32_t a[4], const uint32_t b[2]) {
    asm volatile("mma.sync.aligned.m16n8k16.row.col.f32.f16.f16.f32 "
        "{%0,%1,%2,%3}, {%4,%5,%6,%7}, {%8,%9}, {%0,%1,%2,%3};"
        : "+f"(c[0]), "+f"(c[1]), "+f"(c[2]), "+f"(c[3])
        : "r"(a[0]), "r"(a[1]), "r"(a[2]), "r"(a[3]), "r"(b[0]), "r"(b[1]));
}
__device__ __forceinline__ uint32_t packh(__half a, __half b) {
    return (uint32_t)__half_as_ushort(a) | ((uint32_t)__half_as_ushort(b) << 16);
}
__device__ __forceinline__ float hlo(uint32_t u) {
    return __half2float(__ushort_as_half((unsigned short)(u & 0xffffu)));
}
__device__ __forceinline__ float hhi(uint32_t u) {
    return __half2float(__ushort_as_half((unsigned short)(u >> 16)));
}

// ---------------- embed + init ----------------
__global__ void embed_kernel(const float* __restrict__ nf, const float* __restrict__ w,
                             const float* __restrict__ b, float* __restrict__ out, int N, int F) {
    int idx = blockIdx.x * blockDim.x + threadIdx.x;
    if (idx >= N * 64) return;
    int n = idx >> 6, h = idx & 63;
    const float* row = nf + (size_t)n * F;
    float acc = b[h];
    for (int f = 0; f < F; f++) acc = fmaf(__ldg(row + f), __ldg(w + f * 64 + h), acc);
    out[idx] = acc;
}
__global__ void init_agg_kernel(unsigned* __restrict__ a, int total) {
    int idx = blockIdx.x * blockDim.x + threadIdx.x;
    if (idx < total) {
        int col = idx % 320;
        a[idx] = (col >= 192 && col < 256) ? 0xFFFFFFFFu : 0u;
    }
}

// ================= fused edge kernel ========================================
// Per 128-edge tile:
//  gather xe=[src|dst] fp16 hi/lo -> XH/XL
//  l1: h = relu(xe@w1+b1) via 3-term mma -> HH/HL (packed fp16 hi/lo)
//  gate k = sigmoid(h.wg + bg); q += k*h (float2 atomics); ksum += k
//  l2: f2|f3 = (h@W2[:,65:193]+b)*k via 2-term mma -> atomicMax/Min keys
// Weight SMEM is staged once, ldmatrix-hoisted to registers, then reused.
#define PADH 136
#define EX_XH 0
#define EX_XL 34816
#define EX_HH 69632
#define EX_HL 104448
#define EX_WG 139264
#define EX_B1 139776
#define EX_B2F 140288
#define EX_K  140800
#define EX_DST 141312
#define EX_BG 141824
#define EX_SMEM 141840

__global__ void __launch_bounds__(256, 1) edge_fused_kernel(
    const float* __restrict__ srcx, const float* __restrict__ dstx,
    const int* __restrict__ src, const int* __restrict__ dst,
    const float* __restrict__ w1, const float* __restrict__ w2,
    const float* __restrict__ b1, const float* __restrict__ b2,
    unsigned* __restrict__ agg, int E) {
    extern __shared__ char sm[];
    const uint32_t smb = smem_to_u32(sm);
    const int tid = threadIdx.x, lane = tid & 31, wid = tid >> 5;
    float* s_wg  = (float*)(sm + EX_WG);
    float* s_b1  = (float*)(sm + EX_B1);
    float* s_b2f = (float*)(sm + EX_B2F);
    float* s_k   = (float*)(sm + EX_K);
    int*   s_dst = (int*)(sm + EX_DST);
    float* s_bg  = (float*)(sm + EX_BG);

    // ---- stage weights (into XH/XL/HH regions, reused after hoist) ----
    // w1: global [k=128][n=128] -> [n][k] fp16 hi(XH) / lo(XL)
    for (int idx = tid; idx < 128 * 128; idx += 256) {
        int k = idx >> 7, n = idx & 127;
        float w = __ldg(w1 + idx);
        __half h = __float2half_rn(w);
        __half l = __float2half_rn(w - __half2float(h));
        ((__half*)(sm + EX_XH))[n * PADH + k] = h;
        ((__half*)(sm + EX_XL))[n * PADH + k] = l;
    }
    // w2 max/min cols (65..193) -> [n=128][k] fp16 (HH region)
    for (int idx = tid; idx < 128 * 128; idx += 256) {
        int n = idx & 127, k = idx >> 7;
        ((__half*)(sm + EX_HH))[n * PADH + k] = __float2half_rn(__ldg(w2 + k * 257 + 65 + n));
    }
    if (tid < 128) {
        s_wg[tid] = __ldg(w2 + tid * 257);
        s_b1[tid] = __ldg(b1 + tid);
        s_b2f[tid] = __ldg(b2 + 65 + tid);
    }
    if (tid == 0) s_bg[0] = __ldg(b2);
    __syncthreads();

    // hoist B fragments: warp owns 16 cols
    uint32_t B1h[2][8][2], B1l[2][8][2], B2w[2][8][2];
    #pragma unroll
    for (int nf = 0; nf < 2; nf++)
        #pragma unroll
        for (int kf = 0; kf < 8; kf++) {
            uint32_t off = (uint32_t)((wid * 16 + nf * 8 + (lane & 7)) * PADH
                            + kf * 16 + (((lane >> 3) & 1) << 3)) * 2;
            ldsm_x2(B1h[nf][kf], smb + EX_XH + off);
            ldsm_x2(B1l[nf][kf], smb + EX_XL + off);
            ldsm_x2(B2w[nf][kf], smb + EX_HH + off);
        }
    __syncthreads();  // weight smem now dead; buffers reusable

    const int eloc = tid >> 1, half2v = tid & 1;
    const float bg = s_bg[0];
    const int ntiles = (E + 127) >> 7;
    for (int t = blockIdx.x; t < ntiles; t += gridDim.x) {
        const int tb = t * 128;
        __syncthreads();  // prev tile fully consumed (incl. s_dst/s_k)

        // ---- gather xe=[src|dst], split fp16 hi/lo -> XH/XL ----
        for (int idx = tid; idx < 4096; idx += 256) {
            int row = idx >> 5, q = idx & 31;
            int e = tb + row;
            int hf = q >> 4, qq = q & 15;
            const float4* rp;
            if (hf == 0) {
                int si = (e < E) ? __ldg(src + e) : 0;
                rp = (const float4*)(srcx + (size_t)si * 64);
            } else {
                int di = (e < E) ? __ldg(dst + e) : 0;
                rp = (const float4*)(dstx + (size_t)di * 64);
            }
            float4 v = __ldg(rp + qq);
            int col = hf * 64 + qq * 4;
            __half h0 = __float2half_rn(v.x), h1 = __float2half_rn(v.y);
            __half h2 = __float2half_rn(v.z), h3 = __float2half_rn(v.w);
            __half l0 = __float2half_rn(v.x - __half2float(h0));
            __half l1 = __float2half_rn(v.y - __half2float(h1));
            __half l2 = __float2half_rn(v.z - __half2float(h2));
            __half l3 = __float2half_rn(v.w - __half2float(h3));
            uint32_t off = (uint32_t)(row * PADH + col) * 2;
            *(uint32_t*)(sm + EX_XH + off) = packh(h0, h1);
            *(uint32_t*)(sm + EX_XH + off + 4) = packh(h2, h3);
            *(uint32_t*)(sm + EX_XL + off) = packh(l0, l1);
            *(uint32_t*)(sm + EX_XL + off + 4) = packh(l2, l3);
        }
        if (tid < 128) {
            int e = tb + tid;
            s_dst[tid] = (e < E) ? __ldg(dst + e) : 0;
        }
        __syncthreads();

        // ---- layer1 MMA (3-term): h = relu(xe@w1+b1) -> HH/HL ----
        #pragma unroll 1
        for (int mt = 0; mt < 8; mt++) {
            float c[2][4] = {};
            #pragma unroll
            for (int kf = 0; kf < 8; kf++) {
                uint32_t Ah[4], Al[4];
                uint32_t aoff = (uint32_t)((mt * 16 + (lane & 15)) * PADH
                                 + kf * 16 + ((lane >> 4) << 3)) * 2;
                ldsm_x4(Ah, smb + EX_XH + aoff);
                ldsm_x4(Al, smb + EX_XL + aoff);
                #pragma unroll
                for (int nf = 0; nf < 2; nf++) {
                    mma_f16(c[nf], Ah, B1h[nf][kf]);
                    mma_f16(c[nf], Al, B1h[nf][kf]);
                    mma_f16(c[nf], Ah, B1l[nf][kf]);
                }
            }
            int r0 = mt * 16 + (lane >> 2), r1 = r0 + 8;
            #pragma unroll
            for (int nf = 0; nf < 2; nf++) {
                int cm = wid * 16 + nf * 8 + (lane & 3) * 2;
                float ba = s_b1[cm], bb = s_b1[cm + 1];
                float h00 = fmaxf(c[nf][0] + ba, 0.f), h01 = fmaxf(c[nf][1] + bb, 0.f);
                float h10 = fmaxf(c[nf][2] + ba, 0.f), h11 = fmaxf(c[nf][3] + bb, 0.f);
                __half a00 = __float2half_rn(h00), a01 = __float2half_rn(h01);
                __half a10 = __float2half_rn(h10), a11 = __float2half_rn(h11);
                __half q00 = __float2half_rn(h00 - __half2float(a00));
                __half q01 = __float2half_rn(h01 - __half2float(a01));
                __half q10 = __float2half_rn(h10 - __half2float(a10));
                __half q11 = __float2half_rn(h11 - __half2float(a11));
                uint32_t o0 = (uint32_t)(r0 * PADH + cm) * 2;
                uint32_t o1 = (uint32_t)(r1 * PADH + cm) * 2;
                *(uint32_t*)(sm + EX_HH + o0) = packh(a00, a01);
                *(uint32_t*)(sm + EX_HL + o0) = packh(q00, q01);
                *(uint32_t*)(sm + EX_HH + o1) = packh(a10, a11);
                *(uint32_t*)(sm + EX_HL + o1) = packh(q10, q11);
            }
        }
        __syncthreads();

        // ---- gate + q accumulation (2 threads per edge) ----
        {
            uint32_t base = (uint32_t)(eloc * PADH + half2v * 64) * 2;
            float g = 0.f;
            #pragma unroll 8
            for (int c = 0; c < 32; c++) {
                uint32_t uh = *(uint32_t*)(sm + EX_HH + base + c * 4);
                uint32_t ul = *(uint32_t*)(sm + EX_HL + base + c * 4);
                float h0 = hlo(uh) + hlo(ul);
                float h1 = hhi(uh) + hhi(ul);
                g = fmaf(h0, s_wg[half2v * 64 + c * 2], g);
                g = fmaf(h1, s_wg[half2v * 64 + c * 2 + 1], g);
            }
            g += __shfl_xor_sync(0xffffffffu, g, 1);
            float kk = 1.f / (1.f + __expf(-(g + bg)));
            if (half2v == 0) s_k[eloc] = kk;
            int e = tb + eloc;
            if (e < E) {
                int di = s_dst[eloc];
                float* qb = (float*)(agg + (size_t)di * 320) + half2v * 64;
                #pragma unroll 8
                for (int c = 0; c < 32; c++) {
                    uint32_t uh = *(uint32_t*)(sm + EX_HH + base + c * 4);
                    uint32_t ul = *(uint32_t*)(sm + EX_HL + base + c * 4);
                    float h0 = hlo(uh) + hlo(ul);
                    float h1 = hhi(uh) + hhi(ul);
                    atomicAdd((float2*)(qb + c * 2), make_float2(kk * h0, kk * h1));
                }
                if (half2v == 0) atomicAdd((float*)(agg + (size_t)di * 320 + 256), kk);
            }
        }
        __syncthreads();  // s_k ready for all warps

        // ---- layer2 MMA (2-term): f2|f3 -> atomicMax/Min ----
        #pragma unroll 1
        for (int mt = 0; mt < 8; mt++) {
            float c[2][4] = {};
            #pragma unroll
            for (int kf = 0; kf < 8; kf++) {
                uint32_t Ah[4], Al[4];
                uint32_t aoff = (uint32_t)((mt * 16 + (lane & 15)) * PADH
                                 + kf * 16 + ((lane >> 4) << 3)) * 2;
                ldsm_x4(Ah, smb + EX_HH + aoff);
                ldsm_x4(Al, smb + EX_HL + aoff);
                #pragma unroll
                for (int nf = 0; nf < 2; nf++) {
                    mma_f16(c[nf], Ah, B2w[nf][kf]);
                    mma_f16(c[nf], Al, B2w[nf][kf]);
                }
            }
            int r0 = mt * 16 + (lane >> 2), r1 = r0 + 8;
            bool v0 = tb + r0 < E, v1 = tb + r1 < E;
            float k0 = s_k[r0], k1 = s_k[r1];
            unsigned* row0 = agg + (size_t)s_dst[r0] * 320;
            unsigned* row1 = agg + (size_t)s_dst[r1] * 320;
            #pragma unroll
            for (int nf = 0; nf < 2; nf++) {
                int cm = wid * 16 + nf * 8 + (lane & 3) * 2;  // 0..127
                float ba = s_b2f[cm], bb = s_b2f[cm + 1];
                float v00 = (c[nf][0] + ba) * k0, v01 = (c[nf][1] + bb) * k0;
                float v10 = (c[nf][2] + ba) * k1, v11 = (c[nf][3] + bb) * k1;
                if (wid < 4) {   // f2 -> max keys at 128+cm (cm<64)
                    if (v0) { atomicMax(row0 + 128 + cm, fkey(v00)); atomicMax(row0 + 129 + cm, fkey(v01)); }
                    if (v1) { atomicMax(row1 + 128 + cm, fkey(v10)); atomicMax(row1 + 129 + cm, fkey(v11)); }
                } else {         // f3 -> min keys at 128+cm (cm in 64..127 -> 192..255)
                    if (v0) { atomicMin(row0 + 128 + cm, fkey(v00)); atomicMin(row0 + 129 + cm, fkey(v01)); }
                    if (v1) { atomicMin(row1 + 128 + cm, fkey(v10)); atomicMin(row1 + 129 + cm, fkey(v11)); }
                }
            }
        }
    }
}

// ---------------- finish: q -> [n1|n4] in place ----------------
#define FIN_SMEM 83072
__global__ void __launch_bounds__(256, 1) finish_kernel(
    unsigned* __restrict__ agg, const float* __restrict__ w2,
    const float* __restrict__ b2, int N) {
    extern __shared__ float sf[];
    float* s_w1 = sf;            // [128][64]
    float* s_w4 = sf + 8192;     // [128][64]
    float* s_q  = sf + 16384;    // [32][132]
    float* s_ks = sf + 20608;    // [32]
    float* s_b  = sf + 20640;    // [128]
    const int tid = threadIdx.x;
    for (int idx = tid; idx < 128 * 64; idx += 256) {
        int k = idx >> 6, j = idx & 63;
        s_w1[idx] = __ldg(w2 + k * 257 + 1 + j);
        s_w4[idx] = __ldg(w2 + k * 257 + 193 + j);
    }
    if (tid < 64) { s_b[tid] = __ldg(b2 + 1 + tid); s_b[64 + tid] = __ldg(b2 + 193 + tid); }
    __syncthreads();
    const int n = tid >> 3, jg = tid & 7;
    const int ntiles = (N + 31) >> 5;
    for (int tile = blockIdx.x; tile < ntiles; tile += gridDim.x) {
        const int n0 = tile * 32;
        __syncthreads();
        for (int idx = tid; idx < 32 * 128; idx += 256) {
            int nn = idx >> 7, k = idx & 127, gn = n0 + nn;
            s_q[nn * 132 + k] = (gn < N) ? __uint_as_float(__ldg(agg + (size_t)gn * 320 + k)) : 0.f;
        }
        if (tid < 32) {
            int gn = n0 + tid;
            s_ks[tid] = (gn < N) ? __uint_as_float(__ldg(agg + (size_t)gn * 320 + 256)) : 0.f;
        }
        __syncthreads();
        float a1[8], a4[8];
        #pragma unroll
        for (int t = 0; t < 8; t++) { a1[t] = 0.f; a4[t] = 0.f; }
        const float* qr = s_q + n * 132;
        #pragma unroll 4
        for (int k = 0; k < 128; k++) {
            float qv = qr[k];
            const float* w1r = s_w1 + k * 64 + jg * 8;
            const float* w4r = s_w4 + k * 64 + jg * 8;
            #pragma unroll
            for (int t = 0; t < 8; t++) {
                a1[t] = fmaf(qv, w1r[t], a1[t]);
                a4[t] = fmaf(qv, w4r[t], a4[t]);
            }
        }
        float ks = s_ks[n];
        int gn = n0 + n;
        if (gn < N) {
            float* row = (float*)(agg + (size_t)gn * 320);
            #pragma unroll
            for (int t = 0; t < 8; t++) {
                row[jg * 8 + t] = a1[t] + ks * s_b[jg * 8 + t];
                row[64 + jg * 8 + t] = a4[t] + ks * s_b[64 + jg * 8 + t];
            }
        }
    }
}

// ---------------- node kernel ----------------
#define NODE_SMEM_FLOATS (20480 + 8192 + 4096 + 64 + 64 + 64 + 32*321 + 32*68 + 32*132)
__global__ void __launch_bounds__(256, 1) node_kernel(
    const float* __restrict__ x, const unsigned* __restrict__ agg,
    const float* __restrict__ rw, const float* __restrict__ rb,
    const float* __restrict__ w1, const float* __restrict__ b1,
    const float* __restrict__ w2, const float* __restrict__ b2,
    float* __restrict__ out, int N) {
    extern __shared__ float smf[];
    float* s_rw = smf;
    float* s_w1 = smf + 20480;
    float* s_w2 = smf + 28672;
    float* s_rb = smf + 32768;
    float* s_b1 = smf + 32832;
    float* s_b2 = smf + 32896;
    float* s_z  = smf + 32960;
    float* s_nx = smf + 43232;
    float* s_h  = smf + 45408;

    const int tid = threadIdx.x;
    for (int i = tid; i < 5120; i += 256) ((float4*)s_rw)[i] = ((const float4*)rw)[i];
    for (int i = tid; i < 2048; i += 256) ((float4*)s_w1)[i] = ((const float4*)w1)[i];
    for (int i = tid; i < 1024; i += 256) ((float4*)s_w2)[i] = ((const float4*)w2)[i];
    if (tid < 64) { s_rb[tid] = rb[tid]; s_b1[tid] = b1[tid]; s_b2[tid] = b2[tid]; }
    __syncthreads();

    const int n = tid >> 3, jg = tid & 7;
    const int ntiles = (N + 31) >> 5;
    for (int tile = blockIdx.x; tile < ntiles; tile += gridDim.x) {
        const int n0 = tile * 32;
        for (int idx = tid; idx < 32 * 320; idx += 256) {
            int nn = idx / 320, i = idx - nn * 320;
            int gn = n0 + nn;
            float v = 0.f;
            if (gn < N) {
                if (i < 64) v = __ldg(x + (size_t)gn * 64 + i);
                else {
                    int c = i - 64;
                    const unsigned* row = agg + (size_t)gn * 320;
                    if (c < 64) v = __uint_as_float(__ldg(row + c));
                    else if (c < 128) { unsigned r = __ldg(row + 64 + c); v = r ? fdec(r) : 0.f; }
                    else if (c < 192) { unsigned r = __ldg(row + 64 + c); v = (r == 0xFFFFFFFFu) ? 0.f : fdec(r); }
                    else v = __uint_as_float(__ldg(row + c - 128));
                }
            }
            s_z[nn * 321 + i] = v;
        }
        __syncthreads();

        const float* zrow = s_z + n * 321;
        float4 A = ((float4*)s_rb)[jg * 2], B = ((float4*)s_rb)[jg * 2 + 1];
        #pragma unroll 4
        for (int i = 0; i < 320; i++) {
            float zz = zrow[i];
            float4 wA = ((float4*)s_rw)[i * 16 + jg * 2];
            float4 wB = ((float4*)s_rw)[i * 16 + jg * 2 + 1];
            A.x = fmaf(zz, wA.x, A.x); A.y = fmaf(zz, wA.y, A.y);
            A.z = fmaf(zz, wA.z, A.z); A.w = fmaf(zz, wA.w, A.w);
            B.x = fmaf(zz, wB.x, B.x); B.y = fmaf(zz, wB.y, B.y);
            B.z = fmaf(zz, wB.z, B.z); B.w = fmaf(zz, wB.w, B.w);
        }
        ((float4*)(s_nx + n * 68))[jg * 2] = A;
        ((float4*)(s_nx + n * 68))[jg * 2 + 1] = B;
        __syncwarp();

        float hacc[16];
        #pragma unroll
        for (int tt = 0; tt < 16; tt++) hacc[tt] = s_b1[jg * 16 + tt];
        #pragma unroll 2
        for (int i = 0; i < 64; i++) {
            float in = zrow[i];
            const float* wr = s_w1 + i * 64 + jg * 16;
            #pragma unroll
            for (int tt = 0; tt < 16; tt++) hacc[tt] = fmaf(in, wr[tt], hacc[tt]);
        }
        const float* nxrow = s_nx + n * 68;
        #pragma unroll 2
        for (int i = 0; i < 64; i++) {
            float in = nxrow[i];
            const float* wr = s_w1 + (64 + i) * 64 + jg * 16;
            #pragma unroll
            for (int tt = 0; tt < 16; tt++) hacc[tt] = fmaf(in, wr[tt], hacc[tt]);
        }
        #pragma unroll
        for (int tt = 0; tt < 16; tt++) s_h[n * 132 + jg * 16 + tt] = fmaxf(hacc[tt], 0.f);
        __syncwarp();

        float4 O0 = ((float4*)s_b2)[jg * 2], O1 = ((float4*)s_b2)[jg * 2 + 1];
        const float* hrow = s_h + n * 132;
        #pragma unroll 4
        for (int i = 0; i < 64; i++) {
            float hv = hrow[i];
            float4 wA = ((float4*)s_w2)[i * 16 + jg * 2];
            float4 wB = ((float4*)s_w2)[i * 16 + jg * 2 + 1];
            O0.x = fmaf(hv, wA.x, O0.x); O0.y = fmaf(hv, wA.y, O0.y);
            O0.z = fmaf(hv, wA.z, O0.z); O0.w = fmaf(hv, wA.w, O0.w);
            O1.x = fmaf(hv, wB.x, O1.x); O1.y = fmaf(hv, wB.y, O1.y);
            O1.z = fmaf(hv, wB.z, O1.z); O1.w = fmaf(hv, wB.w, O1.w);
        }
        int gn = n0 + n;
        if (gn < N) {
            ((float4*)(out + (size_t)gn * 64 + jg * 8))[0] = O0;
            ((float4*)(out + (size_t)gn * 64 + jg * 8))[1] = O1;
        }
        __syncthreads();
    }
}

// ---------------------------------------------------------------------------
extern "C" void kernel_launch(void* const* d_in, const int* in_sizes, int n_in,
                              void* d_out, int out_size) {
    const float* nf_gc  = (const float*)d_in[0];
    const float* nf_gs  = (const float*)d_in[1];
    const float* w_gc   = (const float*)d_in[2];
    const float* b_gc   = (const float*)d_in[3];
    const float* w_gs   = (const float*)d_in[4];
    const float* b_gs   = (const float*)d_in[5];
    const float* s2c_w1 = (const float*)d_in[6];
    const float* s2c_b1 = (const float*)d_in[7];
    const float* s2c_w2 = (const float*)d_in[8];
    const float* s2c_b2 = (const float*)d_in[9];
    const float* s2c_rw = (const float*)d_in[10];
    const float* s2c_rb = (const float*)d_in[11];
    const float* c2s_w1 = (const float*)d_in[12];
    const float* c2s_b1 = (const float*)d_in[13];
    const float* c2s_w2 = (const float*)d_in[14];
    const float* c2s_b2 = (const float*)d_in[15];
    const float* c2s_rw = (const float*)d_in[16];
    const float* c2s_rb = (const float*)d_in[17];
    const float* gc_w1  = (const float*)d_in[18];
    const float* gc_b1  = (const float*)d_in[19];
    const float* gc_w2  = (const float*)d_in[20];
    const float* gc_b2  = (const float*)d_in[21];
    const float* gs_w1  = (const float*)d_in[22];
    const float* gs_b1  = (const float*)d_in[23];
    const float* gs_w2  = (const float*)d_in[24];
    const float* gs_b2  = (const float*)d_in[25];
    const int* s2c_src  = (const int*)d_in[26];
    const int* s2c_dst  = (const int*)d_in[27];
    const int* c2s_src  = (const int*)d_in[28];
    const int* c2s_dst  = (const int*)d_in[29];

    const int FGC = in_sizes[2] / 64;
    const int FGS = in_sizes[4] / 64;
    const int NGC = in_sizes[0] / FGC;
    const int NGS = in_sizes[1] / FGS;
    const int E1 = in_sizes[26];
    const int E2 = in_sizes[28];

    float *gcx, *gsx;
    unsigned *aggc, *aggs;
    cudaGetSymbolAddress((void**)&gcx, g_gcx);
    cudaGetSymbolAddress((void**)&gsx, g_gsx);
    cudaGetSymbolAddress((void**)&aggc, g_aggc);
    cudaGetSymbolAddress((void**)&aggs, g_aggs);

    const int NODE_SMEM = NODE_SMEM_FLOATS * 4;
    cudaFuncSetAttribute(edge_fused_kernel, cudaFuncAttributeMaxDynamicSharedMemorySize, EX_SMEM);
    cudaFuncSetAttribute(node_kernel, cudaFuncAttributeMaxDynamicSharedMemorySize, NODE_SMEM);
    cudaFuncSetAttribute(finish_kernel, cudaFuncAttributeMaxDynamicSharedMemorySize, FIN_SMEM);

    embed_kernel<<<(NGC * 64 + 255) / 256, 256>>>(nf_gc, w_gc, b_gc, gcx, NGC, FGC);
    embed_kernel<<<(NGS * 64 + 255) / 256, 256>>>(nf_gs, w_gs, b_gs, gsx, NGS, FGS);
    init_agg_kernel<<<(NGC * 320 + 255) / 256, 256>>>(aggc, NGC * 320);
    init_agg_kernel<<<(NGS * 320 + 255) / 256, 256>>>(aggs, NGS * 320);

    // dir 1: gs -> gc
    edge_fused_kernel<<<152, 256, EX_SMEM>>>(gsx, gcx, s2c_src, s2c_dst,
                                             s2c_w1, s2c_w2, s2c_b1, s2c_b2, aggc, E1);
    finish_kernel<<<152, 256, FIN_SMEM>>>(aggc, s2c_w2, s2c_b2, NGC);
    // dir 2: gc -> gs
    edge_fused_kernel<<<152, 256, EX_SMEM>>>(gcx, gsx, c2s_src, c2s_dst,
                                             c2s_w1, c2s_w2, c2s_b1, c2s_b2, aggs, E2);
    finish_kernel<<<152, 256, FIN_SMEM>>>(aggs, c2s_w2, c2s_b2, NGS);

    float* out = (float*)d_out;
    node_kernel<<<152, 256, NODE_SMEM>>>(gcx, aggc, s2c_rw, s2c_rb,
                                         gc_w1, gc_b1, gc_w2, gc_b2, out, NGC);
    node_kernel<<<152, 256, NODE_SMEM>>>(gsx, aggs, c2s_rw, c2s_rb,
                                         gs_w1, gs_b1, gs_w2, gs_b2, out + (size_t)NGC * 64, NGS);
}

// round 9
// speedup vs baseline: 1.2404x; 1.0271x over previous
#include <cuda_runtime.h>
#include <cuda_fp16.h>
#include <cstdint>

#define NMAX 100000

__device__ float    g_gcx[NMAX * 64];
__device__ float    g_gsx[NMAX * 64];
__device__ unsigned g_aggc[NMAX * 320];  // [q/n1n4 0:128 | maxkey 128:192 | minkey 192:256 | ksum 256]
__device__ unsigned g_aggs[NMAX * 320];

__device__ __forceinline__ unsigned fkey(float f) {
    unsigned u = __float_as_uint(f);
    return (u & 0x80000000u) ? ~u : (u | 0x80000000u);
}
__device__ __forceinline__ float fdec(unsigned k) {
    unsigned u = (k & 0x80000000u) ? (k & 0x7FFFFFFFu) : ~k;
    return __uint_as_float(u);
}
__device__ __forceinline__ uint32_t smem_to_u32(const void* p) {
    uint32_t a;
    asm("{ .reg .u64 t; cvta.to.shared.u64 t, %1; cvt.u32.u64 %0, t; }" : "=r"(a) : "l"(p));
    return a;
}
__device__ __forceinline__ void ldsm_x4(uint32_t a[4], uint32_t addr) {
    asm volatile("ldmatrix.sync.aligned.m8n8.x4.shared.b16 {%0,%1,%2,%3}, [%4];"
        : "=r"(a[0]), "=r"(a[1]), "=r"(a[2]), "=r"(a[3]) : "r"(addr));
}
__device__ __forceinline__ void ldsm_x2(uint32_t b[2], uint32_t addr) {
    asm volatile("ldmatrix.sync.aligned.m8n8.x2.shared.b16 {%0,%1}, [%2];"
        : "=r"(b[0]), "=r"(b[1]) : "r"(addr));
}
__device__ __forceinline__ void mma_f16(float c[4], const uint32_t a[4], const uint32_t b[2]) {
    asm volatile("mma.sync.aligned.m16n8k16.row.col.f32.f16.f16.f32 "
        "{%0,%1,%2,%3}, {%4,%5,%6,%7}, {%8,%9}, {%0,%1,%2,%3};"
        : "+f"(c[0]), "+f"(c[1]), "+f"(c[2]), "+f"(c[3])
        : "r"(a[0]), "r"(a[1]), "r"(a[2]), "r"(a[3]), "r"(b[0]), "r"(b[1]));
}
__device__ __forceinline__ uint32_t packh(__half a, __half b) {
    return (uint32_t)__half_as_ushort(a) | ((uint32_t)__half_as_ushort(b) << 16);
}

// ---------------- embed + init ----------------
__global__ void embed_kernel(const float* __restrict__ nf, const float* __restrict__ w,
                             const float* __restrict__ b, float* __restrict__ out, int N, int F) {
    int idx = blockIdx.x * blockDim.x + threadIdx.x;
    if (idx >= N * 64) return;
    int n = idx >> 6, h = idx & 63;
    const float* row = nf + (size_t)n * F;
    float acc = b[h];
    for (int f = 0; f < F; f++) acc = fmaf(__ldg(row + f), __ldg(w + f * 64 + h), acc);
    out[idx] = acc;
}
__global__ void init_agg_kernel(unsigned* __restrict__ a, int total) {
    int idx = blockIdx.x * blockDim.x + threadIdx.x;
    if (idx < total) {
        int col = idx % 320;
        a[idx] = (col >= 192 && col < 256) ? 0xFFFFFFFFu : 0u;
    }
}

// ================= fused edge kernel v2 =====================================
// Per 128-edge tile:
//  gather xe=[src|dst] fp16 hi/lo -> XH/XL
//  l1 (3-term mma): h = relu(xe@w1+b1) -> HH as SINGLE fp16
//  gate via mma against wg-tile (row0=wg) -> s_k (one m-tile per warp)
//  q += k*h : 16 float4 atomics per half-edge; ksum += k
//  l2 (1-term mma): f2|f3 = (h@W2[:,65:193]+b)*k -> atomicMax/Min keys
#define PADH 136
#define EX_XH 0
#define EX_XL 34816
#define EX_HH 69632
#define EX_WGT 104448
#define EX_B1 106624
#define EX_B2F 107136
#define EX_K  107648
#define EX_DST 108160
#define EX_BG 108672
#define EX_SMEM 108688

__global__ void __launch_bounds__(256, 1) edge_fused_kernel(
    const float* __restrict__ srcx, const float* __restrict__ dstx,
    const int* __restrict__ src, const int* __restrict__ dst,
    const float* __restrict__ w1, const float* __restrict__ w2,
    const float* __restrict__ b1, const float* __restrict__ b2,
    unsigned* __restrict__ agg, int E) {
    extern __shared__ char sm[];
    const uint32_t smb = smem_to_u32(sm);
    const int tid = threadIdx.x, lane = tid & 31, wid = tid >> 5;
    float* s_b1  = (float*)(sm + EX_B1);
    float* s_b2f = (float*)(sm + EX_B2F);
    float* s_k   = (float*)(sm + EX_K);
    int*   s_dst = (int*)(sm + EX_DST);
    float* s_bg  = (float*)(sm + EX_BG);

    // ---- stage weights ----
    // w1: [k][n] -> [n][k] fp16 hi(XH)/lo(XL)
    for (int idx = tid; idx < 128 * 128; idx += 256) {
        int k = idx >> 7, n = idx & 127;
        float w = __ldg(w1 + idx);
        __half h = __float2half_rn(w);
        __half l = __float2half_rn(w - __half2float(h));
        ((__half*)(sm + EX_XH))[n * PADH + k] = h;
        ((__half*)(sm + EX_XL))[n * PADH + k] = l;
    }
    // w2 max/min cols (65..193) -> [n=128][k] fp16 in HH
    for (int idx = tid; idx < 128 * 128; idx += 256) {
        int n = idx & 127, k = idx >> 7;
        ((__half*)(sm + EX_HH))[n * PADH + k] = __float2half_rn(__ldg(w2 + k * 257 + 65 + n));
    }
    // wg tile: rows 0..7 x k=128 fp16, row0 = wg, rest 0 (persistent region)
    for (int idx = tid; idx < 8 * PADH; idx += 256)
        ((__half*)(sm + EX_WGT))[idx] = __float2half_rn(0.f);
    __syncthreads();
    if (tid < 128)
        ((__half*)(sm + EX_WGT))[tid] = __float2half_rn(__ldg(w2 + tid * 257));  // row 0
    if (tid < 128) {
        s_b1[tid] = __ldg(b1 + tid);
        s_b2f[tid] = __ldg(b2 + 65 + tid);
    }
    if (tid == 0) s_bg[0] = __ldg(b2);
    __syncthreads();

    // hoist B fragments
    uint32_t B1h[2][8][2], B1l[2][8][2], B2w[2][8][2], Bg[8][2];
    #pragma unroll
    for (int nf = 0; nf < 2; nf++)
        #pragma unroll
        for (int kf = 0; kf < 8; kf++) {
            uint32_t off = (uint32_t)((wid * 16 + nf * 8 + (lane & 7)) * PADH
                            + kf * 16 + (((lane >> 3) & 1) << 3)) * 2;
            ldsm_x2(B1h[nf][kf], smb + EX_XH + off);
            ldsm_x2(B1l[nf][kf], smb + EX_XL + off);
            ldsm_x2(B2w[nf][kf], smb + EX_HH + off);
        }
    #pragma unroll
    for (int kf = 0; kf < 8; kf++) {
        uint32_t off = (uint32_t)((lane & 7) * PADH
                        + kf * 16 + (((lane >> 3) & 1) << 3)) * 2;
        ldsm_x2(Bg[kf], smb + EX_WGT + off);
    }
    __syncthreads();  // weight staging smem now reusable

    const int eloc = tid >> 1, halfe = tid & 1;
    const float bg = s_bg[0];
    const int ntiles = (E + 127) >> 7;
    for (int t = blockIdx.x; t < ntiles; t += gridDim.x) {
        const int tb = t * 128;
        __syncthreads();  // prev tile fully consumed

        // ---- gather xe=[src|dst], split fp16 hi/lo -> XH/XL ----
        for (int idx = tid; idx < 4096; idx += 256) {
            int row = idx >> 5, q = idx & 31;
            int e = tb + row;
            int hf = q >> 4, qq = q & 15;
            const float4* rp;
            if (hf == 0) {
                int si = (e < E) ? __ldg(src + e) : 0;
                rp = (const float4*)(srcx + (size_t)si * 64);
            } else {
                int di = (e < E) ? __ldg(dst + e) : 0;
                rp = (const float4*)(dstx + (size_t)di * 64);
            }
            float4 v = __ldg(rp + qq);
            int col = hf * 64 + qq * 4;
            __half h0 = __float2half_rn(v.x), h1 = __float2half_rn(v.y);
            __half h2 = __float2half_rn(v.z), h3 = __float2half_rn(v.w);
            __half l0 = __float2half_rn(v.x - __half2float(h0));
            __half l1 = __float2half_rn(v.y - __half2float(h1));
            __half l2 = __float2half_rn(v.z - __half2float(h2));
            __half l3 = __float2half_rn(v.w - __half2float(h3));
            uint32_t off = (uint32_t)(row * PADH + col) * 2;
            *(uint32_t*)(sm + EX_XH + off) = packh(h0, h1);
            *(uint32_t*)(sm + EX_XH + off + 4) = packh(h2, h3);
            *(uint32_t*)(sm + EX_XL + off) = packh(l0, l1);
            *(uint32_t*)(sm + EX_XL + off + 4) = packh(l2, l3);
        }
        if (tid < 128) {
            int e = tb + tid;
            s_dst[tid] = (e < E) ? __ldg(dst + e) : 0;
        }
        __syncthreads();

        // ---- layer1 MMA (3-term): h = relu(xe@w1+b1) -> HH fp16 single ----
        #pragma unroll 1
        for (int mt = 0; mt < 8; mt++) {
            float c[2][4] = {};
            #pragma unroll
            for (int kf = 0; kf < 8; kf++) {
                uint32_t Ah[4], Al[4];
                uint32_t aoff = (uint32_t)((mt * 16 + (lane & 15)) * PADH
                                 + kf * 16 + ((lane >> 4) << 3)) * 2;
                ldsm_x4(Ah, smb + EX_XH + aoff);
                ldsm_x4(Al, smb + EX_XL + aoff);
                #pragma unroll
                for (int nf = 0; nf < 2; nf++) {
                    mma_f16(c[nf], Ah, B1h[nf][kf]);
                    mma_f16(c[nf], Al, B1h[nf][kf]);
                    mma_f16(c[nf], Ah, B1l[nf][kf]);
                }
            }
            int r0 = mt * 16 + (lane >> 2), r1 = r0 + 8;
            #pragma unroll
            for (int nf = 0; nf < 2; nf++) {
                int cm = wid * 16 + nf * 8 + (lane & 3) * 2;
                float ba = s_b1[cm], bb = s_b1[cm + 1];
                __half a00 = __float2half_rn(fmaxf(c[nf][0] + ba, 0.f));
                __half a01 = __float2half_rn(fmaxf(c[nf][1] + bb, 0.f));
                __half a10 = __float2half_rn(fmaxf(c[nf][2] + ba, 0.f));
                __half a11 = __float2half_rn(fmaxf(c[nf][3] + bb, 0.f));
                *(uint32_t*)(sm + EX_HH + (uint32_t)(r0 * PADH + cm) * 2) = packh(a00, a01);
                *(uint32_t*)(sm + EX_HH + (uint32_t)(r1 * PADH + cm) * 2) = packh(a10, a11);
            }
        }
        __syncthreads();

        // ---- gate via MMA: one m-tile per warp; col0 = h . wg ----
        {
            const int mt = wid;
            float c[4] = {0.f, 0.f, 0.f, 0.f};
            #pragma unroll
            for (int kf = 0; kf < 8; kf++) {
                uint32_t Ah[4];
                uint32_t aoff = (uint32_t)((mt * 16 + (lane & 15)) * PADH
                                 + kf * 16 + ((lane >> 4) << 3)) * 2;
                ldsm_x4(Ah, smb + EX_HH + aoff);
                mma_f16(c, Ah, Bg[kf]);
            }
            if ((lane & 3) == 0) {
                int r0 = mt * 16 + (lane >> 2);
                s_k[r0]     = 1.f / (1.f + __expf(-(c[0] + bg)));
                s_k[r0 + 8] = 1.f / (1.f + __expf(-(c[2] + bg)));
            }
        }
        __syncthreads();

        // ---- q += k*h (fp16 h), float4 atomics; ksum += k ----
        {
            int e = tb + eloc;
            if (e < E) {
                float kk = s_k[eloc];
                int di = s_dst[eloc];
                float* qb = (float*)(agg + (size_t)di * 320) + halfe * 64;
                uint32_t base = smb + EX_HH + (uint32_t)(eloc * PADH + halfe * 64) * 2;
                #pragma unroll 4
                for (int c4 = 0; c4 < 16; c4++) {
                    uint32_t u0 = *(uint32_t*)(sm + (base - smb) + c4 * 8);
                    uint32_t u1 = *(uint32_t*)(sm + (base - smb) + c4 * 8 + 4);
                    __half2 p0 = *(__half2*)&u0;
                    __half2 p1 = *(__half2*)&u1;
                    float2 f0 = __half22float2(p0);
                    float2 f1 = __half22float2(p1);
                    atomicAdd((float4*)(qb + c4 * 4),
                              make_float4(kk * f0.x, kk * f0.y, kk * f1.x, kk * f1.y));
                }
                if (halfe == 0) atomicAdd((float*)(agg + (size_t)di * 320 + 256), kk);
            }
        }

        // ---- layer2 MMA (1-term): f2|f3 -> atomicMax/Min ----
        #pragma unroll 1
        for (int mt = 0; mt < 8; mt++) {
            float c[2][4] = {};
            #pragma unroll
            for (int kf = 0; kf < 8; kf++) {
                uint32_t Ah[4];
                uint32_t aoff = (uint32_t)((mt * 16 + (lane & 15)) * PADH
                                 + kf * 16 + ((lane >> 4) << 3)) * 2;
                ldsm_x4(Ah, smb + EX_HH + aoff);
                #pragma unroll
                for (int nf = 0; nf < 2; nf++)
                    mma_f16(c[nf], Ah, B2w[nf][kf]);
            }
            int r0 = mt * 16 + (lane >> 2), r1 = r0 + 8;
            bool v0 = tb + r0 < E, v1 = tb + r1 < E;
            float k0 = s_k[r0], k1 = s_k[r1];
            unsigned* row0 = agg + (size_t)s_dst[r0] * 320;
            unsigned* row1 = agg + (size_t)s_dst[r1] * 320;
            #pragma unroll
            for (int nf = 0; nf < 2; nf++) {
                int cm = wid * 16 + nf * 8 + (lane & 3) * 2;  // 0..127
                float ba = s_b2f[cm], bb = s_b2f[cm + 1];
                float v00 = (c[nf][0] + ba) * k0, v01 = (c[nf][1] + bb) * k0;
                float v10 = (c[nf][2] + ba) * k1, v11 = (c[nf][3] + bb) * k1;
                if (wid < 4) {   // f2 -> max keys at 128+cm (cm<64)
                    if (v0) { atomicMax(row0 + 128 + cm, fkey(v00)); atomicMax(row0 + 129 + cm, fkey(v01)); }
                    if (v1) { atomicMax(row1 + 128 + cm, fkey(v10)); atomicMax(row1 + 129 + cm, fkey(v11)); }
                } else {         // f3 -> min keys (cm 64..127 -> 192..255)
                    if (v0) { atomicMin(row0 + 128 + cm, fkey(v00)); atomicMin(row0 + 129 + cm, fkey(v01)); }
                    if (v1) { atomicMin(row1 + 128 + cm, fkey(v10)); atomicMin(row1 + 129 + cm, fkey(v11)); }
                }
            }
        }
    }
}

// ---------------- finish: q -> [n1|n4] in place ----------------
#define FIN_SMEM 83072
__global__ void __launch_bounds__(256, 1) finish_kernel(
    unsigned* __restrict__ agg, const float* __restrict__ w2,
    const float* __restrict__ b2, int N) {
    extern __shared__ float sf[];
    float* s_w1 = sf;            // [128][64]
    float* s_w4 = sf + 8192;     // [128][64]
    float* s_q  = sf + 16384;    // [32][132]
    float* s_ks = sf + 20608;    // [32]
    float* s_b  = sf + 20640;    // [128]
    const int tid = threadIdx.x;
    for (int idx = tid; idx < 128 * 64; idx += 256) {
        int k = idx >> 6, j = idx & 63;
        s_w1[idx] = __ldg(w2 + k * 257 + 1 + j);
        s_w4[idx] = __ldg(w2 + k * 257 + 193 + j);
    }
    if (tid < 64) { s_b[tid] = __ldg(b2 + 1 + tid); s_b[64 + tid] = __ldg(b2 + 193 + tid); }
    __syncthreads();
    const int n = tid >> 3, jg = tid & 7;
    const int ntiles = (N + 31) >> 5;
    for (int tile = blockIdx.x; tile < ntiles; tile += gridDim.x) {
        const int n0 = tile * 32;
        __syncthreads();
        for (int idx = tid; idx < 32 * 128; idx += 256) {
            int nn = idx >> 7, k = idx & 127, gn = n0 + nn;
            s_q[nn * 132 + k] = (gn < N) ? __uint_as_float(__ldg(agg + (size_t)gn * 320 + k)) : 0.f;
        }
        if (tid < 32) {
            int gn = n0 + tid;
            s_ks[tid] = (gn < N) ? __uint_as_float(__ldg(agg + (size_t)gn * 320 + 256)) : 0.f;
        }
        __syncthreads();
        float a1[8], a4[8];
        #pragma unroll
        for (int t = 0; t < 8; t++) { a1[t] = 0.f; a4[t] = 0.f; }
        const float* qr = s_q + n * 132;
        #pragma unroll 4
        for (int k = 0; k < 128; k++) {
            float qv = qr[k];
            const float* w1r = s_w1 + k * 64 + jg * 8;
            const float* w4r = s_w4 + k * 64 + jg * 8;
            #pragma unroll
            for (int t = 0; t < 8; t++) {
                a1[t] = fmaf(qv, w1r[t], a1[t]);
                a4[t] = fmaf(qv, w4r[t], a4[t]);
            }
        }
        float ks = s_ks[n];
        int gn = n0 + n;
        if (gn < N) {
            float* row = (float*)(agg + (size_t)gn * 320);
            #pragma unroll
            for (int t = 0; t < 8; t++) {
                row[jg * 8 + t] = a1[t] + ks * s_b[jg * 8 + t];
                row[64 + jg * 8 + t] = a4[t] + ks * s_b[64 + jg * 8 + t];
            }
        }
    }
}

// ---------------- node kernel ----------------
#define NODE_SMEM_FLOATS (20480 + 8192 + 4096 + 64 + 64 + 64 + 32*321 + 32*68 + 32*132)
__global__ void __launch_bounds__(256, 1) node_kernel(
    const float* __restrict__ x, const unsigned* __restrict__ agg,
    const float* __restrict__ rw, const float* __restrict__ rb,
    const float* __restrict__ w1, const float* __restrict__ b1,
    const float* __restrict__ w2, const float* __restrict__ b2,
    float* __restrict__ out, int N) {
    extern __shared__ float smf[];
    float* s_rw = smf;
    float* s_w1 = smf + 20480;
    float* s_w2 = smf + 28672;
    float* s_rb = smf + 32768;
    float* s_b1 = smf + 32832;
    float* s_b2 = smf + 32896;
    float* s_z  = smf + 32960;
    float* s_nx = smf + 43232;
    float* s_h  = smf + 45408;

    const int tid = threadIdx.x;
    for (int i = tid; i < 5120; i += 256) ((float4*)s_rw)[i] = ((const float4*)rw)[i];
    for (int i = tid; i < 2048; i += 256) ((float4*)s_w1)[i] = ((const float4*)w1)[i];
    for (int i = tid; i < 1024; i += 256) ((float4*)s_w2)[i] = ((const float4*)w2)[i];
    if (tid < 64) { s_rb[tid] = rb[tid]; s_b1[tid] = b1[tid]; s_b2[tid] = b2[tid]; }
    __syncthreads();

    const int n = tid >> 3, jg = tid & 7;
    const int ntiles = (N + 31) >> 5;
    for (int tile = blockIdx.x; tile < ntiles; tile += gridDim.x) {
        const int n0 = tile * 32;
        for (int idx = tid; idx < 32 * 320; idx += 256) {
            int nn = idx / 320, i = idx - nn * 320;
            int gn = n0 + nn;
            float v = 0.f;
            if (gn < N) {
                if (i < 64) v = __ldg(x + (size_t)gn * 64 + i);
                else {
                    int c = i - 64;
                    const unsigned* row = agg + (size_t)gn * 320;
                    if (c < 64) v = __uint_as_float(__ldg(row + c));
                    else if (c < 128) { unsigned r = __ldg(row + 64 + c); v = r ? fdec(r) : 0.f; }
                    else if (c < 192) { unsigned r = __ldg(row + 64 + c); v = (r == 0xFFFFFFFFu) ? 0.f : fdec(r); }
                    else v = __uint_as_float(__ldg(row + c - 128));
                }
            }
            s_z[nn * 321 + i] = v;
        }
        __syncthreads();

        const float* zrow = s_z + n * 321;
        float4 A = ((float4*)s_rb)[jg * 2], B = ((float4*)s_rb)[jg * 2 + 1];
        #pragma unroll 4
        for (int i = 0; i < 320; i++) {
            float zz = zrow[i];
            float4 wA = ((float4*)s_rw)[i * 16 + jg * 2];
            float4 wB = ((float4*)s_rw)[i * 16 + jg * 2 + 1];
            A.x = fmaf(zz, wA.x, A.x); A.y = fmaf(zz, wA.y, A.y);
            A.z = fmaf(zz, wA.z, A.z); A.w = fmaf(zz, wA.w, A.w);
            B.x = fmaf(zz, wB.x, B.x); B.y = fmaf(zz, wB.y, B.y);
            B.z = fmaf(zz, wB.z, B.z); B.w = fmaf(zz, wB.w, B.w);
        }
        ((float4*)(s_nx + n * 68))[jg * 2] = A;
        ((float4*)(s_nx + n * 68))[jg * 2 + 1] = B;
        __syncwarp();

        float hacc[16];
        #pragma unroll
        for (int tt = 0; tt < 16; tt++) hacc[tt] = s_b1[jg * 16 + tt];
        #pragma unroll 2
        for (int i = 0; i < 64; i++) {
            float in = zrow[i];
            const float* wr = s_w1 + i * 64 + jg * 16;
            #pragma unroll
            for (int tt = 0; tt < 16; tt++) hacc[tt] = fmaf(in, wr[tt], hacc[tt]);
        }
        const float* nxrow = s_nx + n * 68;
        #pragma unroll 2
        for (int i = 0; i < 64; i++) {
            float in = nxrow[i];
            const float* wr = s_w1 + (64 + i) * 64 + jg * 16;
            #pragma unroll
            for (int tt = 0; tt < 16; tt++) hacc[tt] = fmaf(in, wr[tt], hacc[tt]);
        }
        #pragma unroll
        for (int tt = 0; tt < 16; tt++) s_h[n * 132 + jg * 16 + tt] = fmaxf(hacc[tt], 0.f);
        __syncwarp();

        float4 O0 = ((float4*)s_b2)[jg * 2], O1 = ((float4*)s_b2)[jg * 2 + 1];
        const float* hrow = s_h + n * 132;
        #pragma unroll 4
        for (int i = 0; i < 64; i++) {
            float hv = hrow[i];
            float4 wA = ((float4*)s_w2)[i * 16 + jg * 2];
            float4 wB = ((float4*)s_w2)[i * 16 + jg * 2 + 1];
            O0.x = fmaf(hv, wA.x, O0.x); O0.y = fmaf(hv, wA.y, O0.y);
            O0.z = fmaf(hv, wA.z, O0.z); O0.w = fmaf(hv, wA.w, O0.w);
            O1.x = fmaf(hv, wB.x, O1.x); O1.y = fmaf(hv, wB.y, O1.y);
            O1.z = fmaf(hv, wB.z, O1.z); O1.w = fmaf(hv, wB.w, O1.w);
        }
        int gn = n0 + n;
        if (gn < N) {
            ((float4*)(out + (size_t)gn * 64 + jg * 8))[0] = O0;
            ((float4*)(out + (size_t)gn * 64 + jg * 8))[1] = O1;
        }
        __syncthreads();
    }
}

// ---------------------------------------------------------------------------
extern "C" void kernel_launch(void* const* d_in, const int* in_sizes, int n_in,
                              void* d_out, int out_size) {
    const float* nf_gc  = (const float*)d_in[0];
    const float* nf_gs  = (const float*)d_in[1];
    const float* w_gc   = (const float*)d_in[2];
    const float* b_gc   = (const float*)d_in[3];
    const float* w_gs   = (const float*)d_in[4];
    const float* b_gs   = (const float*)d_in[5];
    const float* s2c_w1 = (const float*)d_in[6];
    const float* s2c_b1 = (const float*)d_in[7];
    const float* s2c_w2 = (const float*)d_in[8];
    const float* s2c_b2 = (const float*)d_in[9];
    const float* s2c_rw = (const float*)d_in[10];
    const float* s2c_rb = (const float*)d_in[11];
    const float* c2s_w1 = (const float*)d_in[12];
    const float* c2s_b1 = (const float*)d_in[13];
    const float* c2s_w2 = (const float*)d_in[14];
    const float* c2s_b2 = (const float*)d_in[15];
    const float* c2s_rw = (const float*)d_in[16];
    const float* c2s_rb = (const float*)d_in[17];
    const float* gc_w1  = (const float*)d_in[18];
    const float* gc_b1  = (const float*)d_in[19];
    const float* gc_w2  = (const float*)d_in[20];
    const float* gc_b2  = (const float*)d_in[21];
    const float* gs_w1  = (const float*)d_in[22];
    const float* gs_b1  = (const float*)d_in[23];
    const float* gs_w2  = (const float*)d_in[24];
    const float* gs_b2  = (const float*)d_in[25];
    const int* s2c_src  = (const int*)d_in[26];
    const int* s2c_dst  = (const int*)d_in[27];
    const int* c2s_src  = (const int*)d_in[28];
    const int* c2s_dst  = (const int*)d_in[29];

    const int FGC = in_sizes[2] / 64;
    const int FGS = in_sizes[4] / 64;
    const int NGC = in_sizes[0] / FGC;
    const int NGS = in_sizes[1] / FGS;
    const int E1 = in_sizes[26];
    const int E2 = in_sizes[28];

    float *gcx, *gsx;
    unsigned *aggc, *aggs;
    cudaGetSymbolAddress((void**)&gcx, g_gcx);
    cudaGetSymbolAddress((void**)&gsx, g_gsx);
    cudaGetSymbolAddress((void**)&aggc, g_aggc);
    cudaGetSymbolAddress((void**)&aggs, g_aggs);

    const int NODE_SMEM = NODE_SMEM_FLOATS * 4;
    cudaFuncSetAttribute(edge_fused_kernel, cudaFuncAttributeMaxDynamicSharedMemorySize, EX_SMEM);
    cudaFuncSetAttribute(node_kernel, cudaFuncAttributeMaxDynamicSharedMemorySize, NODE_SMEM);
    cudaFuncSetAttribute(finish_kernel, cudaFuncAttributeMaxDynamicSharedMemorySize, FIN_SMEM);

    embed_kernel<<<(NGC * 64 + 255) / 256, 256>>>(nf_gc, w_gc, b_gc, gcx, NGC, FGC);
    embed_kernel<<<(NGS * 64 + 255) / 256, 256>>>(nf_gs, w_gs, b_gs, gsx, NGS, FGS);
    init_agg_kernel<<<(NGC * 320 + 255) / 256, 256>>>(aggc, NGC * 320);
    init_agg_kernel<<<(NGS * 320 + 255) / 256, 256>>>(aggs, NGS * 320);

    // dir 1: gs -> gc
    edge_fused_kernel<<<152, 256, EX_SMEM>>>(gsx, gcx, s2c_src, s2c_dst,
                                             s2c_w1, s2c_w2, s2c_b1, s2c_b2, aggc, E1);
    finish_kernel<<<152, 256, FIN_SMEM>>>(aggc, s2c_w2, s2c_b2, NGC);
    // dir 2: gc -> gs
    edge_fused_kernel<<<152, 256, EX_SMEM>>>(gcx, gsx, c2s_src, c2s_dst,
                                             c2s_w1, c2s_w2, c2s_b1, c2s_b2, aggs, E2);
    finish_kernel<<<152, 256, FIN_SMEM>>>(aggs, c2s_w2, c2s_b2, NGS);

    float* out = (float*)d_out;
    node_kernel<<<152, 256, NODE_SMEM>>>(gcx, aggc, s2c_rw, s2c_rb,
                                         gc_w1, gc_b1, gc_w2, gc_b2, out, NGC);
    node_kernel<<<152, 256, NODE_SMEM>>>(gsx, aggs, c2s_rw, c2s_rb,
                                         gs_w1, gs_b1, gs_w2, gs_b2, out + (size_t)NGC * 64, NGS);
}

// round 10
// speedup vs baseline: 1.3062x; 1.0531x over previous
#include <cuda_runtime.h>
#include <cuda_fp16.h>
#include <cstdint>

#define NMAX 100000

__device__ float    g_gcx[NMAX * 64];
__device__ float    g_gsx[NMAX * 64];
__device__ unsigned g_aggc[NMAX * 320];  // [q/n1n4 0:128 | maxkey 128:192 | minkey 192:256 | ksum 256]
__device__ unsigned g_aggs[NMAX * 320];

__device__ __forceinline__ unsigned fkey(float f) {
    unsigned u = __float_as_uint(f);
    return (u & 0x80000000u) ? ~u : (u | 0x80000000u);
}
__device__ __forceinline__ float fdec(unsigned k) {
    unsigned u = (k & 0x80000000u) ? (k & 0x7FFFFFFFu) : ~k;
    return __uint_as_float(u);
}
__device__ __forceinline__ uint32_t smem_to_u32(const void* p) {
    uint32_t a;
    asm("{ .reg .u64 t; cvta.to.shared.u64 t, %1; cvt.u32.u64 %0, t; }" : "=r"(a) : "l"(p));
    return a;
}
__device__ __forceinline__ void ldsm_x4(uint32_t a[4], uint32_t addr) {
    asm volatile("ldmatrix.sync.aligned.m8n8.x4.shared.b16 {%0,%1,%2,%3}, [%4];"
        : "=r"(a[0]), "=r"(a[1]), "=r"(a[2]), "=r"(a[3]) : "r"(addr));
}
__device__ __forceinline__ void ldsm_x2(uint32_t b[2], uint32_t addr) {
    asm volatile("ldmatrix.sync.aligned.m8n8.x2.shared.b16 {%0,%1}, [%2];"
        : "=r"(b[0]), "=r"(b[1]) : "r"(addr));
}
__device__ __forceinline__ void mma_f16(float c[4], const uint32_t a[4], const uint32_t b[2]) {
    asm volatile("mma.sync.aligned.m16n8k16.row.col.f32.f16.f16.f32 "
        "{%0,%1,%2,%3}, {%4,%5,%6,%7}, {%8,%9}, {%0,%1,%2,%3};"
        : "+f"(c[0]), "+f"(c[1]), "+f"(c[2]), "+f"(c[3])
        : "r"(a[0]), "r"(a[1]), "r"(a[2]), "r"(a[3]), "r"(b[0]), "r"(b[1]));
}
__device__ __forceinline__ uint32_t packh(__half a, __half b) {
    return (uint32_t)__half_as_ushort(a) | ((uint32_t)__half_as_ushort(b) << 16);
}

// ---------------- embed + init ----------------
__global__ void embed_kernel(const float* __restrict__ nf, const float* __restrict__ w,
                             const float* __restrict__ b, float* __restrict__ out, int N, int F) {
    int idx = blockIdx.x * blockDim.x + threadIdx.x;
    if (idx >= N * 64) return;
    int n = idx >> 6, h = idx & 63;
    const float* row = nf + (size_t)n * F;
    float acc = b[h];
    for (int f = 0; f < F; f++) acc = fmaf(__ldg(row + f), __ldg(w + f * 64 + h), acc);
    out[idx] = acc;
}
__global__ void init_agg_kernel(unsigned* __restrict__ a, int total) {
    int idx = blockIdx.x * blockDim.x + threadIdx.x;
    if (idx < total) {
        int col = idx % 320;
        a[idx] = (col >= 192 && col < 256) ? 0xFFFFFFFFu : 0u;
    }
}

// ================= fused edge kernel v3: 64-edge tiles, occupancy 2 =========
// Phases per tile: gather -> l1(3-term mma, B1 hoisted) -> gate(mma vs wg tile)
//                  -> q atomics -> l2(1-term mma, B from persistent smem tile)
#define PADH 136
#define EX_XH 0
#define EX_XL 17408
#define EX_HH 34816
#define EX_W2T 52224
#define EX_WGT 87040
#define EX_B1 89216
#define EX_B2F 89728
#define EX_K  90240
#define EX_DST 90496
#define EX_BG 90752
#define EX_SMEM 90768

__global__ void __launch_bounds__(256, 2) edge_fused_kernel(
    const float* __restrict__ srcx, const float* __restrict__ dstx,
    const int* __restrict__ src, const int* __restrict__ dst,
    const float* __restrict__ w1, const float* __restrict__ w2,
    const float* __restrict__ b1, const float* __restrict__ b2,
    unsigned* __restrict__ agg, int E) {
    extern __shared__ char sm[];
    const uint32_t smb = smem_to_u32(sm);
    const int tid = threadIdx.x, lane = tid & 31, wid = tid >> 5;
    float* s_b1  = (float*)(sm + EX_B1);
    float* s_b2f = (float*)(sm + EX_B2F);
    float* s_k   = (float*)(sm + EX_K);
    int*   s_dst = (int*)(sm + EX_DST);
    float* s_bg  = (float*)(sm + EX_BG);

    // ---- persistent weights: w2 max/min tile + wg tile ----
    for (int idx = tid; idx < 128 * 128; idx += 256) {
        int n = idx & 127, k = idx >> 7;
        ((__half*)(sm + EX_W2T))[n * PADH + k] = __float2half_rn(__ldg(w2 + k * 257 + 65 + n));
    }
    for (int idx = tid; idx < 8 * PADH; idx += 256)
        ((__half*)(sm + EX_WGT))[idx] = __float2half_rn(0.f);
    if (tid < 128) {
        s_b1[tid] = __ldg(b1 + tid);
        s_b2f[tid] = __ldg(b2 + 65 + tid);
    }
    if (tid == 0) s_bg[0] = __ldg(b2);
    __syncthreads();
    if (tid < 128)
        ((__half*)(sm + EX_WGT))[tid] = __float2half_rn(__ldg(w2 + tid * 257));  // row 0 = wg

    // ---- stage w1-hi through XH..XL (contiguous 128-row region), hoist B1h --
    uint32_t B1h[2][8][2], B1l[2][8][2];
    __syncthreads();
    for (int idx = tid; idx < 128 * 128; idx += 256) {
        int k = idx >> 7, n = idx & 127;
        ((__half*)(sm + EX_XH))[n * PADH + k] = __float2half_rn(__ldg(w1 + idx));
    }
    __syncthreads();
    #pragma unroll
    for (int nf = 0; nf < 2; nf++)
        #pragma unroll
        for (int kf = 0; kf < 8; kf++) {
            uint32_t off = (uint32_t)((wid * 16 + nf * 8 + (lane & 7)) * PADH
                            + kf * 16 + (((lane >> 3) & 1) << 3)) * 2;
            ldsm_x2(B1h[nf][kf], smb + EX_XH + off);
        }
    __syncthreads();
    // ---- stage w1-lo, hoist B1l ----
    for (int idx = tid; idx < 128 * 128; idx += 256) {
        int k = idx >> 7, n = idx & 127;
        float w = __ldg(w1 + idx);
        __half h = __float2half_rn(w);
        ((__half*)(sm + EX_XH))[n * PADH + k] = __float2half_rn(w - __half2float(h));
    }
    __syncthreads();
    #pragma unroll
    for (int nf = 0; nf < 2; nf++)
        #pragma unroll
        for (int kf = 0; kf < 8; kf++) {
            uint32_t off = (uint32_t)((wid * 16 + nf * 8 + (lane & 7)) * PADH
                            + kf * 16 + (((lane >> 3) & 1) << 3)) * 2;
            ldsm_x2(B1l[nf][kf], smb + EX_XH + off);
        }

    const int eloc = tid >> 2, quad = tid & 3;  // q-pass: 4 threads/edge
    const float bg = s_bg[0];
    const int ntiles = (E + 63) >> 6;
    for (int t = blockIdx.x; t < ntiles; t += gridDim.x) {
        const int tb = t * 64;
        __syncthreads();  // prev tile fully consumed

        // ---- gather 64 edges: xe=[src|dst] fp16 hi/lo -> XH/XL ----
        for (int idx = tid; idx < 2048; idx += 256) {
            int row = idx >> 5, q = idx & 31;
            int e = tb + row;
            int hf = q >> 4, qq = q & 15;
            const float4* rp;
            if (hf == 0) {
                int si = (e < E) ? __ldg(src + e) : 0;
                rp = (const float4*)(srcx + (size_t)si * 64);
            } else {
                int di = (e < E) ? __ldg(dst + e) : 0;
                rp = (const float4*)(dstx + (size_t)di * 64);
            }
            float4 v = __ldg(rp + qq);
            int col = hf * 64 + qq * 4;
            __half h0 = __float2half_rn(v.x), h1 = __float2half_rn(v.y);
            __half h2 = __float2half_rn(v.z), h3 = __float2half_rn(v.w);
            __half l0 = __float2half_rn(v.x - __half2float(h0));
            __half l1 = __float2half_rn(v.y - __half2float(h1));
            __half l2 = __float2half_rn(v.z - __half2float(h2));
            __half l3 = __float2half_rn(v.w - __half2float(h3));
            uint32_t off = (uint32_t)(row * PADH + col) * 2;
            *(uint32_t*)(sm + EX_XH + off) = packh(h0, h1);
            *(uint32_t*)(sm + EX_XH + off + 4) = packh(h2, h3);
            *(uint32_t*)(sm + EX_XL + off) = packh(l0, l1);
            *(uint32_t*)(sm + EX_XL + off + 4) = packh(l2, l3);
        }
        if (tid < 64) {
            int e = tb + tid;
            s_dst[tid] = (e < E) ? __ldg(dst + e) : 0;
        }
        __syncthreads();

        // ---- layer1 MMA (3-term): h = relu(xe@w1+b1) -> HH fp16 ----
        #pragma unroll
        for (int mt = 0; mt < 4; mt++) {
            float c[2][4] = {};
            #pragma unroll
            for (int kf = 0; kf < 8; kf++) {
                uint32_t Ah[4], Al[4];
                uint32_t aoff = (uint32_t)((mt * 16 + (lane & 15)) * PADH
                                 + kf * 16 + ((lane >> 4) << 3)) * 2;
                ldsm_x4(Ah, smb + EX_XH + aoff);
                ldsm_x4(Al, smb + EX_XL + aoff);
                #pragma unroll
                for (int nf = 0; nf < 2; nf++) {
                    mma_f16(c[nf], Ah, B1h[nf][kf]);
                    mma_f16(c[nf], Al, B1h[nf][kf]);
                    mma_f16(c[nf], Ah, B1l[nf][kf]);
                }
            }
            int r0 = mt * 16 + (lane >> 2), r1 = r0 + 8;
            #pragma unroll
            for (int nf = 0; nf < 2; nf++) {
                int cm = wid * 16 + nf * 8 + (lane & 3) * 2;
                float ba = s_b1[cm], bb = s_b1[cm + 1];
                __half a00 = __float2half_rn(fmaxf(c[nf][0] + ba, 0.f));
                __half a01 = __float2half_rn(fmaxf(c[nf][1] + bb, 0.f));
                __half a10 = __float2half_rn(fmaxf(c[nf][2] + ba, 0.f));
                __half a11 = __float2half_rn(fmaxf(c[nf][3] + bb, 0.f));
                *(uint32_t*)(sm + EX_HH + (uint32_t)(r0 * PADH + cm) * 2) = packh(a00, a01);
                *(uint32_t*)(sm + EX_HH + (uint32_t)(r1 * PADH + cm) * 2) = packh(a10, a11);
            }
        }
        __syncthreads();

        // ---- gate via MMA (warps 0-3, one m-tile each) ----
        if (wid < 4) {
            const int mt = wid;
            float c[4] = {0.f, 0.f, 0.f, 0.f};
            #pragma unroll
            for (int kf = 0; kf < 8; kf++) {
                uint32_t Ah[4], Bgf[2];
                uint32_t aoff = (uint32_t)((mt * 16 + (lane & 15)) * PADH
                                 + kf * 16 + ((lane >> 4) << 3)) * 2;
                ldsm_x4(Ah, smb + EX_HH + aoff);
                uint32_t goff = (uint32_t)((lane & 7) * PADH
                                 + kf * 16 + (((lane >> 3) & 1) << 3)) * 2;
                ldsm_x2(Bgf, smb + EX_WGT + goff);
                mma_f16(c, Ah, Bgf);
            }
            if ((lane & 3) == 0) {
                int r0 = mt * 16 + (lane >> 2);
                s_k[r0]     = 1.f / (1.f + __expf(-(c[0] + bg)));
                s_k[r0 + 8] = 1.f / (1.f + __expf(-(c[2] + bg)));
            }
        }
        __syncthreads();

        // ---- q += k*h (4 threads/edge, 4 float4 atomics each); ksum ----
        {
            int e = tb + eloc;
            if (e < E) {
                float kk = s_k[eloc];
                int di = s_dst[eloc];
                float* qb = (float*)(agg + (size_t)di * 320) + quad * 32;
                uint32_t base = (uint32_t)(eloc * PADH + quad * 32) * 2;
                #pragma unroll
                for (int c4 = 0; c4 < 8; c4++) {
                    uint32_t u0 = *(uint32_t*)(sm + EX_HH + base + c4 * 8);
                    uint32_t u1 = *(uint32_t*)(sm + EX_HH + base + c4 * 8 + 4);
                    float2 f0 = __half22float2(*(__half2*)&u0);
                    float2 f1 = __half22float2(*(__half2*)&u1);
                    if ((c4 & 1) == 0) {
                        atomicAdd((float4*)(qb + (c4 >> 1) * 8),
                                  make_float4(kk * f0.x, kk * f0.y, kk * f1.x, kk * f1.y));
                    } else {
                        atomicAdd((float4*)(qb + (c4 >> 1) * 8 + 4),
                                  make_float4(kk * f0.x, kk * f0.y, kk * f1.x, kk * f1.y));
                    }
                }
                if (quad == 0) atomicAdd((float*)(agg + (size_t)di * 320 + 256), kk);
            }
        }

        // ---- layer2 MMA (1-term, B from persistent smem): f2|f3 ----
        #pragma unroll
        for (int mt = 0; mt < 4; mt++) {
            float c[2][4] = {};
            #pragma unroll
            for (int kf = 0; kf < 8; kf++) {
                uint32_t Ah[4];
                uint32_t aoff = (uint32_t)((mt * 16 + (lane & 15)) * PADH
                                 + kf * 16 + ((lane >> 4) << 3)) * 2;
                ldsm_x4(Ah, smb + EX_HH + aoff);
                #pragma unroll
                for (int nf = 0; nf < 2; nf++) {
                    uint32_t Bf[2];
                    uint32_t boff = (uint32_t)((wid * 16 + nf * 8 + (lane & 7)) * PADH
                                     + kf * 16 + (((lane >> 3) & 1) << 3)) * 2;
                    ldsm_x2(Bf, smb + EX_W2T + boff);
                    mma_f16(c[nf], Ah, Bf);
                }
            }
            int r0 = mt * 16 + (lane >> 2), r1 = r0 + 8;
            bool v0 = tb + r0 < E, v1 = tb + r1 < E;
            float k0 = s_k[r0], k1 = s_k[r1];
            unsigned* row0 = agg + (size_t)s_dst[r0] * 320;
            unsigned* row1 = agg + (size_t)s_dst[r1] * 320;
            #pragma unroll
            for (int nf = 0; nf < 2; nf++) {
                int cm = wid * 16 + nf * 8 + (lane & 3) * 2;  // 0..127
                float ba = s_b2f[cm], bb = s_b2f[cm + 1];
                float v00 = (c[nf][0] + ba) * k0, v01 = (c[nf][1] + bb) * k0;
                float v10 = (c[nf][2] + ba) * k1, v11 = (c[nf][3] + bb) * k1;
                if (wid < 4) {   // f2 -> max keys at 128+cm (cm<64)
                    if (v0) { atomicMax(row0 + 128 + cm, fkey(v00)); atomicMax(row0 + 129 + cm, fkey(v01)); }
                    if (v1) { atomicMax(row1 + 128 + cm, fkey(v10)); atomicMax(row1 + 129 + cm, fkey(v11)); }
                } else {         // f3 -> min keys (cm 64..127 -> 192..255)
                    if (v0) { atomicMin(row0 + 128 + cm, fkey(v00)); atomicMin(row0 + 129 + cm, fkey(v01)); }
                    if (v1) { atomicMin(row1 + 128 + cm, fkey(v10)); atomicMin(row1 + 129 + cm, fkey(v11)); }
                }
            }
        }
    }
}

// ---------------- finish: q -> [n1|n4] in place ----------------
#define FIN_SMEM 83072
__global__ void __launch_bounds__(256, 1) finish_kernel(
    unsigned* __restrict__ agg, const float* __restrict__ w2,
    const float* __restrict__ b2, int N) {
    extern __shared__ float sf[];
    float* s_w1 = sf;            // [128][64]
    float* s_w4 = sf + 8192;     // [128][64]
    float* s_q  = sf + 16384;    // [32][132]
    float* s_ks = sf + 20608;    // [32]
    float* s_b  = sf + 20640;    // [128]
    const int tid = threadIdx.x;
    for (int idx = tid; idx < 128 * 64; idx += 256) {
        int k = idx >> 6, j = idx & 63;
        s_w1[idx] = __ldg(w2 + k * 257 + 1 + j);
        s_w4[idx] = __ldg(w2 + k * 257 + 193 + j);
    }
    if (tid < 64) { s_b[tid] = __ldg(b2 + 1 + tid); s_b[64 + tid] = __ldg(b2 + 193 + tid); }
    __syncthreads();
    const int n = tid >> 3, jg = tid & 7;
    const int ntiles = (N + 31) >> 5;
    for (int tile = blockIdx.x; tile < ntiles; tile += gridDim.x) {
        const int n0 = tile * 32;
        __syncthreads();
        for (int idx = tid; idx < 32 * 128; idx += 256) {
            int nn = idx >> 7, k = idx & 127, gn = n0 + nn;
            s_q[nn * 132 + k] = (gn < N) ? __uint_as_float(__ldg(agg + (size_t)gn * 320 + k)) : 0.f;
        }
        if (tid < 32) {
            int gn = n0 + tid;
            s_ks[tid] = (gn < N) ? __uint_as_float(__ldg(agg + (size_t)gn * 320 + 256)) : 0.f;
        }
        __syncthreads();
        float a1[8], a4[8];
        #pragma unroll
        for (int t = 0; t < 8; t++) { a1[t] = 0.f; a4[t] = 0.f; }
        const float* qr = s_q + n * 132;
        #pragma unroll 4
        for (int k = 0; k < 128; k++) {
            float qv = qr[k];
            const float* w1r = s_w1 + k * 64 + jg * 8;
            const float* w4r = s_w4 + k * 64 + jg * 8;
            #pragma unroll
            for (int t = 0; t < 8; t++) {
                a1[t] = fmaf(qv, w1r[t], a1[t]);
                a4[t] = fmaf(qv, w4r[t], a4[t]);
            }
        }
        float ks = s_ks[n];
        int gn = n0 + n;
        if (gn < N) {
            float* row = (float*)(agg + (size_t)gn * 320);
            #pragma unroll
            for (int t = 0; t < 8; t++) {
                row[jg * 8 + t] = a1[t] + ks * s_b[jg * 8 + t];
                row[64 + jg * 8 + t] = a4[t] + ks * s_b[64 + jg * 8 + t];
            }
        }
    }
}

// ---------------- node kernel ----------------
#define NODE_SMEM_FLOATS (20480 + 8192 + 4096 + 64 + 64 + 64 + 32*321 + 32*68 + 32*132)
__global__ void __launch_bounds__(256, 1) node_kernel(
    const float* __restrict__ x, const unsigned* __restrict__ agg,
    const float* __restrict__ rw, const float* __restrict__ rb,
    const float* __restrict__ w1, const float* __restrict__ b1,
    const float* __restrict__ w2, const float* __restrict__ b2,
    float* __restrict__ out, int N) {
    extern __shared__ float smf[];
    float* s_rw = smf;
    float* s_w1 = smf + 20480;
    float* s_w2 = smf + 28672;
    float* s_rb = smf + 32768;
    float* s_b1 = smf + 32832;
    float* s_b2 = smf + 32896;
    float* s_z  = smf + 32960;
    float* s_nx = smf + 43232;
    float* s_h  = smf + 45408;

    const int tid = threadIdx.x;
    for (int i = tid; i < 5120; i += 256) ((float4*)s_rw)[i] = ((const float4*)rw)[i];
    for (int i = tid; i < 2048; i += 256) ((float4*)s_w1)[i] = ((const float4*)w1)[i];
    for (int i = tid; i < 1024; i += 256) ((float4*)s_w2)[i] = ((const float4*)w2)[i];
    if (tid < 64) { s_rb[tid] = rb[tid]; s_b1[tid] = b1[tid]; s_b2[tid] = b2[tid]; }
    __syncthreads();

    const int n = tid >> 3, jg = tid & 7;
    const int ntiles = (N + 31) >> 5;
    for (int tile = blockIdx.x; tile < ntiles; tile += gridDim.x) {
        const int n0 = tile * 32;
        for (int idx = tid; idx < 32 * 320; idx += 256) {
            int nn = idx / 320, i = idx - nn * 320;
            int gn = n0 + nn;
            float v = 0.f;
            if (gn < N) {
                if (i < 64) v = __ldg(x + (size_t)gn * 64 + i);
                else {
                    int c = i - 64;
                    const unsigned* row = agg + (size_t)gn * 320;
                    if (c < 64) v = __uint_as_float(__ldg(row + c));
                    else if (c < 128) { unsigned r = __ldg(row + 64 + c); v = r ? fdec(r) : 0.f; }
                    else if (c < 192) { unsigned r = __ldg(row + 64 + c); v = (r == 0xFFFFFFFFu) ? 0.f : fdec(r); }
                    else v = __uint_as_float(__ldg(row + c - 128));
                }
            }
            s_z[nn * 321 + i] = v;
        }
        __syncthreads();

        const float* zrow = s_z + n * 321;
        float4 A = ((float4*)s_rb)[jg * 2], B = ((float4*)s_rb)[jg * 2 + 1];
        #pragma unroll 4
        for (int i = 0; i < 320; i++) {
            float zz = zrow[i];
            float4 wA = ((float4*)s_rw)[i * 16 + jg * 2];
            float4 wB = ((float4*)s_rw)[i * 16 + jg * 2 + 1];
            A.x = fmaf(zz, wA.x, A.x); A.y = fmaf(zz, wA.y, A.y);
            A.z = fmaf(zz, wA.z, A.z); A.w = fmaf(zz, wA.w, A.w);
            B.x = fmaf(zz, wB.x, B.x); B.y = fmaf(zz, wB.y, B.y);
            B.z = fmaf(zz, wB.z, B.z); B.w = fmaf(zz, wB.w, B.w);
        }
        ((float4*)(s_nx + n * 68))[jg * 2] = A;
        ((float4*)(s_nx + n * 68))[jg * 2 + 1] = B;
        __syncwarp();

        float hacc[16];
        #pragma unroll
        for (int tt = 0; tt < 16; tt++) hacc[tt] = s_b1[jg * 16 + tt];
        #pragma unroll 2
        for (int i = 0; i < 64; i++) {
            float in = zrow[i];
            const float* wr = s_w1 + i * 64 + jg * 16;
            #pragma unroll
            for (int tt = 0; tt < 16; tt++) hacc[tt] = fmaf(in, wr[tt], hacc[tt]);
        }
        const float* nxrow = s_nx + n * 68;
        #pragma unroll 2
        for (int i = 0; i < 64; i++) {
            float in = nxrow[i];
            const float* wr = s_w1 + (64 + i) * 64 + jg * 16;
            #pragma unroll
            for (int tt = 0; tt < 16; tt++) hacc[tt] = fmaf(in, wr[tt], hacc[tt]);
        }
        #pragma unroll
        for (int tt = 0; tt < 16; tt++) s_h[n * 132 + jg * 16 + tt] = fmaxf(hacc[tt], 0.f);
        __syncwarp();

        float4 O0 = ((float4*)s_b2)[jg * 2], O1 = ((float4*)s_b2)[jg * 2 + 1];
        const float* hrow = s_h + n * 132;
        #pragma unroll 4
        for (int i = 0; i < 64; i++) {
            float hv = hrow[i];
            float4 wA = ((float4*)s_w2)[i * 16 + jg * 2];
            float4 wB = ((float4*)s_w2)[i * 16 + jg * 2 + 1];
            O0.x = fmaf(hv, wA.x, O0.x); O0.y = fmaf(hv, wA.y, O0.y);
            O0.z = fmaf(hv, wA.z, O0.z); O0.w = fmaf(hv, wA.w, O0.w);
            O1.x = fmaf(hv, wB.x, O1.x); O1.y = fmaf(hv, wB.y, O1.y);
            O1.z = fmaf(hv, wB.z, O1.z); O1.w = fmaf(hv, wB.w, O1.w);
        }
        int gn = n0 + n;
        if (gn < N) {
            ((float4*)(out + (size_t)gn * 64 + jg * 8))[0] = O0;
            ((float4*)(out + (size_t)gn * 64 + jg * 8))[1] = O1;
        }
        __syncthreads();
    }
}

// ---------------------------------------------------------------------------
extern "C" void kernel_launch(void* const* d_in, const int* in_sizes, int n_in,
                              void* d_out, int out_size) {
    const float* nf_gc  = (const float*)d_in[0];
    const float* nf_gs  = (const float*)d_in[1];
    const float* w_gc   = (const float*)d_in[2];
    const float* b_gc   = (const float*)d_in[3];
    const float* w_gs   = (const float*)d_in[4];
    const float* b_gs   = (const float*)d_in[5];
    const float* s2c_w1 = (const float*)d_in[6];
    const float* s2c_b1 = (const float*)d_in[7];
    const float* s2c_w2 = (const float*)d_in[8];
    const float* s2c_b2 = (const float*)d_in[9];
    const float* s2c_rw = (const float*)d_in[10];
    const float* s2c_rb = (const float*)d_in[11];
    const float* c2s_w1 = (const float*)d_in[12];
    const float* c2s_b1 = (const float*)d_in[13];
    const float* c2s_w2 = (const float*)d_in[14];
    const float* c2s_b2 = (const float*)d_in[15];
    const float* c2s_rw = (const float*)d_in[16];
    const float* c2s_rb = (const float*)d_in[17];
    const float* gc_w1  = (const float*)d_in[18];
    const float* gc_b1  = (const float*)d_in[19];
    const float* gc_w2  = (const float*)d_in[20];
    const float* gc_b2  = (const float*)d_in[21];
    const float* gs_w1  = (const float*)d_in[22];
    const float* gs_b1  = (const float*)d_in[23];
    const float* gs_w2  = (const float*)d_in[24];
    const float* gs_b2  = (const float*)d_in[25];
    const int* s2c_src  = (const int*)d_in[26];
    const int* s2c_dst  = (const int*)d_in[27];
    const int* c2s_src  = (const int*)d_in[28];
    const int* c2s_dst  = (const int*)d_in[29];

    const int FGC = in_sizes[2] / 64;
    const int FGS = in_sizes[4] / 64;
    const int NGC = in_sizes[0] / FGC;
    const int NGS = in_sizes[1] / FGS;
    const int E1 = in_sizes[26];
    const int E2 = in_sizes[28];

    float *gcx, *gsx;
    unsigned *aggc, *aggs;
    cudaGetSymbolAddress((void**)&gcx, g_gcx);
    cudaGetSymbolAddress((void**)&gsx, g_gsx);
    cudaGetSymbolAddress((void**)&aggc, g_aggc);
    cudaGetSymbolAddress((void**)&aggs, g_aggs);

    const int NODE_SMEM = NODE_SMEM_FLOATS * 4;
    cudaFuncSetAttribute(edge_fused_kernel, cudaFuncAttributeMaxDynamicSharedMemorySize, EX_SMEM);
    cudaFuncSetAttribute(node_kernel, cudaFuncAttributeMaxDynamicSharedMemorySize, NODE_SMEM);
    cudaFuncSetAttribute(finish_kernel, cudaFuncAttributeMaxDynamicSharedMemorySize, FIN_SMEM);

    embed_kernel<<<(NGC * 64 + 255) / 256, 256>>>(nf_gc, w_gc, b_gc, gcx, NGC, FGC);
    embed_kernel<<<(NGS * 64 + 255) / 256, 256>>>(nf_gs, w_gs, b_gs, gsx, NGS, FGS);
    init_agg_kernel<<<(NGC * 320 + 255) / 256, 256>>>(aggc, NGC * 320);
    init_agg_kernel<<<(NGS * 320 + 255) / 256, 256>>>(aggs, NGS * 320);

    // dir 1: gs -> gc
    edge_fused_kernel<<<304, 256, EX_SMEM>>>(gsx, gcx, s2c_src, s2c_dst,
                                             s2c_w1, s2c_w2, s2c_b1, s2c_b2, aggc, E1);
    finish_kernel<<<152, 256, FIN_SMEM>>>(aggc, s2c_w2, s2c_b2, NGC);
    // dir 2: gc -> gs
    edge_fused_kernel<<<304, 256, EX_SMEM>>>(gcx, gsx, c2s_src, c2s_dst,
                                             c2s_w1, c2s_w2, c2s_b1, c2s_b2, aggs, E2);
    finish_kernel<<<152, 256, FIN_SMEM>>>(aggs, c2s_w2, c2s_b2, NGS);

    float* out = (float*)d_out;
    node_kernel<<<152, 256, NODE_SMEM>>>(gcx, aggc, s2c_rw, s2c_rb,
                                         gc_w1, gc_b1, gc_w2, gc_b2, out, NGC);
    node_kernel<<<152, 256, NODE_SMEM>>>(gsx, aggs, c2s_rw, c2s_rb,
                                         gs_w1, gs_b1, gs_w2, gs_b2, out + (size_t)NGC * 64, NGS);
}

// round 11
// speedup vs baseline: 1.3509x; 1.0342x over previous
#include <cuda_runtime.h>
#include <cuda_fp16.h>
#include <cstdint>

#define NMAX 100000

__device__ float    g_gcx[NMAX * 64];
__device__ float    g_gsx[NMAX * 64];
__device__ unsigned g_aggc[NMAX * 320];  // [q/n1n4 0:128 | maxkey 128:192 | minkey 192:256 | ksum 256]
__device__ unsigned g_aggs[NMAX * 320];

__device__ __forceinline__ unsigned fkey(float f) {
    unsigned u = __float_as_uint(f);
    return (u & 0x80000000u) ? ~u : (u | 0x80000000u);
}
__device__ __forceinline__ float fdec(unsigned k) {
    unsigned u = (k & 0x80000000u) ? (k & 0x7FFFFFFFu) : ~k;
    return __uint_as_float(u);
}
__device__ __forceinline__ uint32_t smem_to_u32(const void* p) {
    uint32_t a;
    asm("{ .reg .u64 t; cvta.to.shared.u64 t, %1; cvt.u32.u64 %0, t; }" : "=r"(a) : "l"(p));
    return a;
}
__device__ __forceinline__ void ldsm_x4(uint32_t a[4], uint32_t addr) {
    asm volatile("ldmatrix.sync.aligned.m8n8.x4.shared.b16 {%0,%1,%2,%3}, [%4];"
        : "=r"(a[0]), "=r"(a[1]), "=r"(a[2]), "=r"(a[3]) : "r"(addr));
}
__device__ __forceinline__ void ldsm_x2(uint32_t b[2], uint32_t addr) {
    asm volatile("ldmatrix.sync.aligned.m8n8.x2.shared.b16 {%0,%1}, [%2];"
        : "=r"(b[0]), "=r"(b[1]) : "r"(addr));
}
__device__ __forceinline__ void mma_f16(float c[4], const uint32_t a[4], const uint32_t b[2]) {
    asm volatile("mma.sync.aligned.m16n8k16.row.col.f32.f16.f16.f32 "
        "{%0,%1,%2,%3}, {%4,%5,%6,%7}, {%8,%9}, {%0,%1,%2,%3};"
        : "+f"(c[0]), "+f"(c[1]), "+f"(c[2]), "+f"(c[3])
        : "r"(a[0]), "r"(a[1]), "r"(a[2]), "r"(a[3]), "r"(b[0]), "r"(b[1]));
}
__device__ __forceinline__ uint32_t packh(__half a, __half b) {
    return (uint32_t)__half_as_ushort(a) | ((uint32_t)__half_as_ushort(b) << 16);
}

// ---------------- combined init (launch 0) ----------------
__global__ void init_all_kernel(unsigned* __restrict__ aggc, unsigned* __restrict__ aggs,
                                int totc, int tots) {
    int idx = blockIdx.x * blockDim.x + threadIdx.x;
    if (idx < totc) {
        int col = idx % 320;
        aggc[idx] = (col >= 192 && col < 256) ? 0xFFFFFFFFu : 0u;
    } else if (idx < totc + tots) {
        int j = idx - totc;
        int col = j % 320;
        aggs[j] = (col >= 192 && col < 256) ? 0xFFFFFFFFu : 0u;
    }
}

// ---------------- combined embed (launch 1) ----------------
__global__ void embed_all_kernel(
    const float* __restrict__ nfc, const float* __restrict__ wc,
    const float* __restrict__ bc, float* __restrict__ outc, int NC, int FC,
    const float* __restrict__ nfs, const float* __restrict__ ws,
    const float* __restrict__ bs, float* __restrict__ outs, int NS, int FS) {
    int idx = blockIdx.x * blockDim.x + threadIdx.x;
    if (idx < NC * 64) {
        int n = idx >> 6, h = idx & 63;
        const float* row = nfc + (size_t)n * FC;
        float acc = bc[h];
        for (int f = 0; f < FC; f++) acc = fmaf(__ldg(row + f), __ldg(wc + f * 64 + h), acc);
        outc[idx] = acc;
    } else if (idx < (NC + NS) * 64) {
        int j = idx - NC * 64;
        int n = j >> 6, h = j & 63;
        const float* row = nfs + (size_t)n * FS;
        float acc = bs[h];
        for (int f = 0; f < FS; f++) acc = fmaf(__ldg(row + f), __ldg(ws + f * 64 + h), acc);
        outs[j] = acc;
    }
}

// ================= fused edge kernel, BOTH directions (launch 2) ============
#define PADH 136
#define EX_XH 0
#define EX_XL 17408
#define EX_HH 34816
#define EX_W2T 52224
#define EX_WGT 87040
#define EX_B1 89216
#define EX_B2F 89728
#define EX_K  90240
#define EX_DST 90496
#define EX_BG 90752
#define EX_SMEM 90768
#define EDGE_HALF 304

__global__ void __launch_bounds__(256, 2) edge_both_kernel(
    const float* __restrict__ gcx, const float* __restrict__ gsx,
    const int* __restrict__ src1, const int* __restrict__ dst1,
    const float* __restrict__ w1a, const float* __restrict__ w2a,
    const float* __restrict__ b1a, const float* __restrict__ b2a,
    unsigned* __restrict__ agg1, int E1,
    const int* __restrict__ src2, const int* __restrict__ dst2,
    const float* __restrict__ w1b, const float* __restrict__ w2b,
    const float* __restrict__ b1b, const float* __restrict__ b2b,
    unsigned* __restrict__ agg2, int E2) {
    extern __shared__ char sm[];
    const uint32_t smb = smem_to_u32(sm);
    const int tid = threadIdx.x, lane = tid & 31, wid = tid >> 5;
    const bool d2 = blockIdx.x >= EDGE_HALF;
    const float* srcx = d2 ? gcx : gsx;
    const float* dstx = d2 ? gsx : gcx;
    const int* src = d2 ? src2 : src1;
    const int* dst = d2 ? dst2 : dst1;
    const float* w1 = d2 ? w1b : w1a;
    const float* w2 = d2 ? w2b : w2a;
    const float* b1 = d2 ? b1b : b1a;
    const float* b2 = d2 ? b2b : b2a;
    unsigned* agg = d2 ? agg2 : agg1;
    const int E = d2 ? E2 : E1;
    const int bid0 = blockIdx.x - (d2 ? EDGE_HALF : 0);

    float* s_b1  = (float*)(sm + EX_B1);
    float* s_b2f = (float*)(sm + EX_B2F);
    float* s_k   = (float*)(sm + EX_K);
    int*   s_dst = (int*)(sm + EX_DST);
    float* s_bg  = (float*)(sm + EX_BG);

    // ---- persistent weights: w2 max/min tile + wg tile ----
    for (int idx = tid; idx < 128 * 128; idx += 256) {
        int n = idx & 127, k = idx >> 7;
        ((__half*)(sm + EX_W2T))[n * PADH + k] = __float2half_rn(__ldg(w2 + k * 257 + 65 + n));
    }
    for (int idx = tid; idx < 8 * PADH; idx += 256)
        ((__half*)(sm + EX_WGT))[idx] = __float2half_rn(0.f);
    if (tid < 128) {
        s_b1[tid] = __ldg(b1 + tid);
        s_b2f[tid] = __ldg(b2 + 65 + tid);
    }
    if (tid == 0) s_bg[0] = __ldg(b2);
    __syncthreads();
    if (tid < 128)
        ((__half*)(sm + EX_WGT))[tid] = __float2half_rn(__ldg(w2 + tid * 257));  // row 0 = wg

    // ---- stage w1-hi through XH region, hoist B1h; then w1-lo, hoist B1l ----
    uint32_t B1h[2][8][2], B1l[2][8][2];
    __syncthreads();
    for (int idx = tid; idx < 128 * 128; idx += 256) {
        int k = idx >> 7, n = idx & 127;
        ((__half*)(sm + EX_XH))[n * PADH + k] = __float2half_rn(__ldg(w1 + idx));
    }
    __syncthreads();
    #pragma unroll
    for (int nf = 0; nf < 2; nf++)
        #pragma unroll
        for (int kf = 0; kf < 8; kf++) {
            uint32_t off = (uint32_t)((wid * 16 + nf * 8 + (lane & 7)) * PADH
                            + kf * 16 + (((lane >> 3) & 1) << 3)) * 2;
            ldsm_x2(B1h[nf][kf], smb + EX_XH + off);
        }
    __syncthreads();
    for (int idx = tid; idx < 128 * 128; idx += 256) {
        int k = idx >> 7, n = idx & 127;
        float w = __ldg(w1 + idx);
        __half h = __float2half_rn(w);
        ((__half*)(sm + EX_XH))[n * PADH + k] = __float2half_rn(w - __half2float(h));
    }
    __syncthreads();
    #pragma unroll
    for (int nf = 0; nf < 2; nf++)
        #pragma unroll
        for (int kf = 0; kf < 8; kf++) {
            uint32_t off = (uint32_t)((wid * 16 + nf * 8 + (lane & 7)) * PADH
                            + kf * 16 + (((lane >> 3) & 1) << 3)) * 2;
            ldsm_x2(B1l[nf][kf], smb + EX_XH + off);
        }

    const int eloc = tid >> 2, quad = tid & 3;
    const float bg = s_bg[0];
    const int ntiles = (E + 63) >> 6;
    for (int t = bid0; t < ntiles; t += EDGE_HALF) {
        const int tb = t * 64;
        __syncthreads();

        // ---- gather 64 edges: xe=[src|dst] fp16 hi/lo -> XH/XL ----
        for (int idx = tid; idx < 2048; idx += 256) {
            int row = idx >> 5, q = idx & 31;
            int e = tb + row;
            int hf = q >> 4, qq = q & 15;
            const float4* rp;
            if (hf == 0) {
                int si = (e < E) ? __ldg(src + e) : 0;
                rp = (const float4*)(srcx + (size_t)si * 64);
            } else {
                int di = (e < E) ? __ldg(dst + e) : 0;
                rp = (const float4*)(dstx + (size_t)di * 64);
            }
            float4 v = __ldg(rp + qq);
            int col = hf * 64 + qq * 4;
            __half h0 = __float2half_rn(v.x), h1 = __float2half_rn(v.y);
            __half h2 = __float2half_rn(v.z), h3 = __float2half_rn(v.w);
            __half l0 = __float2half_rn(v.x - __half2float(h0));
            __half l1 = __float2half_rn(v.y - __half2float(h1));
            __half l2 = __float2half_rn(v.z - __half2float(h2));
            __half l3 = __float2half_rn(v.w - __half2float(h3));
            uint32_t off = (uint32_t)(row * PADH + col) * 2;
            *(uint32_t*)(sm + EX_XH + off) = packh(h0, h1);
            *(uint32_t*)(sm + EX_XH + off + 4) = packh(h2, h3);
            *(uint32_t*)(sm + EX_XL + off) = packh(l0, l1);
            *(uint32_t*)(sm + EX_XL + off + 4) = packh(l2, l3);
        }
        if (tid < 64) {
            int e = tb + tid;
            s_dst[tid] = (e < E) ? __ldg(dst + e) : 0;
        }
        __syncthreads();

        // ---- layer1 MMA (3-term): h = relu(xe@w1+b1) -> HH fp16 ----
        #pragma unroll
        for (int mt = 0; mt < 4; mt++) {
            float c[2][4] = {};
            #pragma unroll
            for (int kf = 0; kf < 8; kf++) {
                uint32_t Ah[4], Al[4];
                uint32_t aoff = (uint32_t)((mt * 16 + (lane & 15)) * PADH
                                 + kf * 16 + ((lane >> 4) << 3)) * 2;
                ldsm_x4(Ah, smb + EX_XH + aoff);
                ldsm_x4(Al, smb + EX_XL + aoff);
                #pragma unroll
                for (int nf = 0; nf < 2; nf++) {
                    mma_f16(c[nf], Ah, B1h[nf][kf]);
                    mma_f16(c[nf], Al, B1h[nf][kf]);
                    mma_f16(c[nf], Ah, B1l[nf][kf]);
                }
            }
            int r0 = mt * 16 + (lane >> 2), r1 = r0 + 8;
            #pragma unroll
            for (int nf = 0; nf < 2; nf++) {
                int cm = wid * 16 + nf * 8 + (lane & 3) * 2;
                float ba = s_b1[cm], bb = s_b1[cm + 1];
                __half a00 = __float2half_rn(fmaxf(c[nf][0] + ba, 0.f));
                __half a01 = __float2half_rn(fmaxf(c[nf][1] + bb, 0.f));
                __half a10 = __float2half_rn(fmaxf(c[nf][2] + ba, 0.f));
                __half a11 = __float2half_rn(fmaxf(c[nf][3] + bb, 0.f));
                *(uint32_t*)(sm + EX_HH + (uint32_t)(r0 * PADH + cm) * 2) = packh(a00, a01);
                *(uint32_t*)(sm + EX_HH + (uint32_t)(r1 * PADH + cm) * 2) = packh(a10, a11);
            }
        }
        __syncthreads();

        // ---- gate via MMA (warps 0-3) ----
        if (wid < 4) {
            const int mt = wid;
            float c[4] = {0.f, 0.f, 0.f, 0.f};
            #pragma unroll
            for (int kf = 0; kf < 8; kf++) {
                uint32_t Ah[4], Bgf[2];
                uint32_t aoff = (uint32_t)((mt * 16 + (lane & 15)) * PADH
                                 + kf * 16 + ((lane >> 4) << 3)) * 2;
                ldsm_x4(Ah, smb + EX_HH + aoff);
                uint32_t goff = (uint32_t)((lane & 7) * PADH
                                 + kf * 16 + (((lane >> 3) & 1) << 3)) * 2;
                ldsm_x2(Bgf, smb + EX_WGT + goff);
                mma_f16(c, Ah, Bgf);
            }
            if ((lane & 3) == 0) {
                int r0 = mt * 16 + (lane >> 2);
                s_k[r0]     = 1.f / (1.f + __expf(-(c[0] + bg)));
                s_k[r0 + 8] = 1.f / (1.f + __expf(-(c[2] + bg)));
            }
        }
        __syncthreads();

        // ---- q += k*h (4 threads/edge); ksum ----
        {
            int e = tb + eloc;
            if (e < E) {
                float kk = s_k[eloc];
                int di = s_dst[eloc];
                float* qb = (float*)(agg + (size_t)di * 320) + quad * 32;
                uint32_t base = (uint32_t)(eloc * PADH + quad * 32) * 2;
                #pragma unroll
                for (int c4 = 0; c4 < 8; c4++) {
                    uint32_t u0 = *(uint32_t*)(sm + EX_HH + base + c4 * 8);
                    uint32_t u1 = *(uint32_t*)(sm + EX_HH + base + c4 * 8 + 4);
                    float2 f0 = __half22float2(*(__half2*)&u0);
                    float2 f1 = __half22float2(*(__half2*)&u1);
                    atomicAdd((float4*)(qb + c4 * 4),
                              make_float4(kk * f0.x, kk * f0.y, kk * f1.x, kk * f1.y));
                }
                if (quad == 0) atomicAdd((float*)(agg + (size_t)di * 320 + 256), kk);
            }
        }

        // ---- layer2 MMA (1-term, B from persistent smem): f2|f3 ----
        #pragma unroll
        for (int mt = 0; mt < 4; mt++) {
            float c[2][4] = {};
            #pragma unroll
            for (int kf = 0; kf < 8; kf++) {
                uint32_t Ah[4];
                uint32_t aoff = (uint32_t)((mt * 16 + (lane & 15)) * PADH
                                 + kf * 16 + ((lane >> 4) << 3)) * 2;
                ldsm_x4(Ah, smb + EX_HH + aoff);
                #pragma unroll
                for (int nf = 0; nf < 2; nf++) {
                    uint32_t Bf[2];
                    uint32_t boff = (uint32_t)((wid * 16 + nf * 8 + (lane & 7)) * PADH
                                     + kf * 16 + (((lane >> 3) & 1) << 3)) * 2;
                    ldsm_x2(Bf, smb + EX_W2T + boff);
                    mma_f16(c[nf], Ah, Bf);
                }
            }
            int r0 = mt * 16 + (lane >> 2), r1 = r0 + 8;
            bool v0 = tb + r0 < E, v1 = tb + r1 < E;
            float k0 = s_k[r0], k1 = s_k[r1];
            unsigned* row0 = agg + (size_t)s_dst[r0] * 320;
            unsigned* row1 = agg + (size_t)s_dst[r1] * 320;
            #pragma unroll
            for (int nf = 0; nf < 2; nf++) {
                int cm = wid * 16 + nf * 8 + (lane & 3) * 2;
                float ba = s_b2f[cm], bb = s_b2f[cm + 1];
                float v00 = (c[nf][0] + ba) * k0, v01 = (c[nf][1] + bb) * k0;
                float v10 = (c[nf][2] + ba) * k1, v11 = (c[nf][3] + bb) * k1;
                if (wid < 4) {
                    if (v0) { atomicMax(row0 + 128 + cm, fkey(v00)); atomicMax(row0 + 129 + cm, fkey(v01)); }
                    if (v1) { atomicMax(row1 + 128 + cm, fkey(v10)); atomicMax(row1 + 129 + cm, fkey(v11)); }
                } else {
                    if (v0) { atomicMin(row0 + 128 + cm, fkey(v00)); atomicMin(row0 + 129 + cm, fkey(v01)); }
                    if (v1) { atomicMin(row1 + 128 + cm, fkey(v10)); atomicMin(row1 + 129 + cm, fkey(v11)); }
                }
            }
        }
    }
}

// ---------------- finish, both dirs (launch 3) ----------------
#define FIN_SMEM 83072
__global__ void __launch_bounds__(256, 1) finish_both_kernel(
    unsigned* __restrict__ aggc, const float* __restrict__ w2a,
    const float* __restrict__ b2a, int NC,
    unsigned* __restrict__ aggs, const float* __restrict__ w2b,
    const float* __restrict__ b2b, int NS) {
    extern __shared__ float sf[];
    float* s_w1 = sf;
    float* s_w4 = sf + 8192;
    float* s_q  = sf + 16384;
    float* s_ks = sf + 20608;
    float* s_b  = sf + 20640;
    const int tid = threadIdx.x;
    const bool d2 = blockIdx.x >= 152;
    unsigned* agg = d2 ? aggs : aggc;
    const float* w2 = d2 ? w2b : w2a;
    const float* b2 = d2 ? b2b : b2a;
    const int N = d2 ? NS : NC;
    const int bid0 = blockIdx.x - (d2 ? 152 : 0);

    for (int idx = tid; idx < 128 * 64; idx += 256) {
        int k = idx >> 6, j = idx & 63;
        s_w1[idx] = __ldg(w2 + k * 257 + 1 + j);
        s_w4[idx] = __ldg(w2 + k * 257 + 193 + j);
    }
    if (tid < 64) { s_b[tid] = __ldg(b2 + 1 + tid); s_b[64 + tid] = __ldg(b2 + 193 + tid); }
    __syncthreads();
    const int n = tid >> 3, jg = tid & 7;
    const int ntiles = (N + 31) >> 5;
    for (int tile = bid0; tile < ntiles; tile += 152) {
        const int n0 = tile * 32;
        __syncthreads();
        for (int idx = tid; idx < 32 * 128; idx += 256) {
            int nn = idx >> 7, k = idx & 127, gn = n0 + nn;
            s_q[nn * 132 + k] = (gn < N) ? __uint_as_float(__ldg(agg + (size_t)gn * 320 + k)) : 0.f;
        }
        if (tid < 32) {
            int gn = n0 + tid;
            s_ks[tid] = (gn < N) ? __uint_as_float(__ldg(agg + (size_t)gn * 320 + 256)) : 0.f;
        }
        __syncthreads();
        float a1[8], a4[8];
        #pragma unroll
        for (int t = 0; t < 8; t++) { a1[t] = 0.f; a4[t] = 0.f; }
        const float* qr = s_q + n * 132;
        #pragma unroll 4
        for (int k = 0; k < 128; k++) {
            float qv = qr[k];
            const float* w1r = s_w1 + k * 64 + jg * 8;
            const float* w4r = s_w4 + k * 64 + jg * 8;
            #pragma unroll
            for (int t = 0; t < 8; t++) {
                a1[t] = fmaf(qv, w1r[t], a1[t]);
                a4[t] = fmaf(qv, w4r[t], a4[t]);
            }
        }
        float ks = s_ks[n];
        int gn = n0 + n;
        if (gn < N) {
            float* row = (float*)(agg + (size_t)gn * 320);
            #pragma unroll
            for (int t = 0; t < 8; t++) {
                row[jg * 8 + t] = a1[t] + ks * s_b[jg * 8 + t];
                row[64 + jg * 8 + t] = a4[t] + ks * s_b[64 + jg * 8 + t];
            }
        }
    }
}

// ---------------- node, both types (launch 4) ----------------
#define NODE_SMEM_FLOATS (20480 + 8192 + 4096 + 64 + 64 + 64 + 32*321 + 32*68 + 32*132)
__global__ void __launch_bounds__(256, 1) node_both_kernel(
    const float* __restrict__ gcx, const unsigned* __restrict__ aggc,
    const float* __restrict__ rwa, const float* __restrict__ rba,
    const float* __restrict__ w1a, const float* __restrict__ b1a,
    const float* __restrict__ w2a, const float* __restrict__ b2a, int NC,
    const float* __restrict__ gsx, const unsigned* __restrict__ aggs,
    const float* __restrict__ rwb, const float* __restrict__ rbb,
    const float* __restrict__ w1b, const float* __restrict__ b1b,
    const float* __restrict__ w2b, const float* __restrict__ b2b, int NS,
    float* __restrict__ out) {
    extern __shared__ float smf[];
    float* s_rw = smf;
    float* s_w1 = smf + 20480;
    float* s_w2 = smf + 28672;
    float* s_rb = smf + 32768;
    float* s_b1 = smf + 32832;
    float* s_b2 = smf + 32896;
    float* s_z  = smf + 32960;
    float* s_nx = smf + 43232;
    float* s_h  = smf + 45408;

    const int tid = threadIdx.x;
    const bool d2 = blockIdx.x >= 152;
    const float* x = d2 ? gsx : gcx;
    const unsigned* agg = d2 ? aggs : aggc;
    const float* rw = d2 ? rwb : rwa;
    const float* rb = d2 ? rbb : rba;
    const float* w1 = d2 ? w1b : w1a;
    const float* b1 = d2 ? b1b : b1a;
    const float* w2 = d2 ? w2b : w2a;
    const float* b2 = d2 ? b2b : b2a;
    const int N = d2 ? NS : NC;
    float* outp = out + (d2 ? (size_t)NC * 64 : 0);
    const int bid0 = blockIdx.x - (d2 ? 152 : 0);

    for (int i = tid; i < 5120; i += 256) ((float4*)s_rw)[i] = ((const float4*)rw)[i];
    for (int i = tid; i < 2048; i += 256) ((float4*)s_w1)[i] = ((const float4*)w1)[i];
    for (int i = tid; i < 1024; i += 256) ((float4*)s_w2)[i] = ((const float4*)w2)[i];
    if (tid < 64) { s_rb[tid] = rb[tid]; s_b1[tid] = b1[tid]; s_b2[tid] = b2[tid]; }
    __syncthreads();

    const int n = tid >> 3, jg = tid & 7;
    const int ntiles = (N + 31) >> 5;
    for (int tile = bid0; tile < ntiles; tile += 152) {
        const int n0 = tile * 32;
        for (int idx = tid; idx < 32 * 320; idx += 256) {
            int nn = idx / 320, i = idx - nn * 320;
            int gn = n0 + nn;
            float v = 0.f;
            if (gn < N) {
                if (i < 64) v = __ldg(x + (size_t)gn * 64 + i);
                else {
                    int c = i - 64;
                    const unsigned* row = agg + (size_t)gn * 320;
                    if (c < 64) v = __uint_as_float(__ldg(row + c));
                    else if (c < 128) { unsigned r = __ldg(row + 64 + c); v = r ? fdec(r) : 0.f; }
                    else if (c < 192) { unsigned r = __ldg(row + 64 + c); v = (r == 0xFFFFFFFFu) ? 0.f : fdec(r); }
                    else v = __uint_as_float(__ldg(row + c - 128));
                }
            }
            s_z[nn * 321 + i] = v;
        }
        __syncthreads();

        const float* zrow = s_z + n * 321;
        float4 A = ((float4*)s_rb)[jg * 2], B = ((float4*)s_rb)[jg * 2 + 1];
        #pragma unroll 4
        for (int i = 0; i < 320; i++) {
            float zz = zrow[i];
            float4 wA = ((float4*)s_rw)[i * 16 + jg * 2];
            float4 wB = ((float4*)s_rw)[i * 16 + jg * 2 + 1];
            A.x = fmaf(zz, wA.x, A.x); A.y = fmaf(zz, wA.y, A.y);
            A.z = fmaf(zz, wA.z, A.z); A.w = fmaf(zz, wA.w, A.w);
            B.x = fmaf(zz, wB.x, B.x); B.y = fmaf(zz, wB.y, B.y);
            B.z = fmaf(zz, wB.z, B.z); B.w = fmaf(zz, wB.w, B.w);
        }
        ((float4*)(s_nx + n * 68))[jg * 2] = A;
        ((float4*)(s_nx + n * 68))[jg * 2 + 1] = B;
        __syncwarp();

        float hacc[16];
        #pragma unroll
        for (int tt = 0; tt < 16; tt++) hacc[tt] = s_b1[jg * 16 + tt];
        #pragma unroll 2
        for (int i = 0; i < 64; i++) {
            float in = zrow[i];
            const float* wr = s_w1 + i * 64 + jg * 16;
            #pragma unroll
            for (int tt = 0; tt < 16; tt++) hacc[tt] = fmaf(in, wr[tt], hacc[tt]);
        }
        const float* nxrow = s_nx + n * 68;
        #pragma unroll 2
        for (int i = 0; i < 64; i++) {
            float in = nxrow[i];
            const float* wr = s_w1 + (64 + i) * 64 + jg * 16;
            #pragma unroll
            for (int tt = 0; tt < 16; tt++) hacc[tt] = fmaf(in, wr[tt], hacc[tt]);
        }
        #pragma unroll
        for (int tt = 0; tt < 16; tt++) s_h[n * 132 + jg * 16 + tt] = fmaxf(hacc[tt], 0.f);
        __syncwarp();

        float4 O0 = ((float4*)s_b2)[jg * 2], O1 = ((float4*)s_b2)[jg * 2 + 1];
        const float* hrow = s_h + n * 132;
        #pragma unroll 4
        for (int i = 0; i < 64; i++) {
            float hv = hrow[i];
            float4 wA = ((float4*)s_w2)[i * 16 + jg * 2];
            float4 wB = ((float4*)s_w2)[i * 16 + jg * 2 + 1];
            O0.x = fmaf(hv, wA.x, O0.x); O0.y = fmaf(hv, wA.y, O0.y);
            O0.z = fmaf(hv, wA.z, O0.z); O0.w = fmaf(hv, wA.w, O0.w);
            O1.x = fmaf(hv, wB.x, O1.x); O1.y = fmaf(hv, wB.y, O1.y);
            O1.z = fmaf(hv, wB.z, O1.z); O1.w = fmaf(hv, wB.w, O1.w);
        }
        int gn = n0 + n;
        if (gn < N) {
            ((float4*)(outp + (size_t)gn * 64 + jg * 8))[0] = O0;
            ((float4*)(outp + (size_t)gn * 64 + jg * 8))[1] = O1;
        }
        __syncthreads();
    }
}

// ---------------------------------------------------------------------------
extern "C" void kernel_launch(void* const* d_in, const int* in_sizes, int n_in,
                              void* d_out, int out_size) {
    const float* nf_gc  = (const float*)d_in[0];
    const float* nf_gs  = (const float*)d_in[1];
    const float* w_gc   = (const float*)d_in[2];
    const float* b_gc   = (const float*)d_in[3];
    const float* w_gs   = (const float*)d_in[4];
    const float* b_gs   = (const float*)d_in[5];
    const float* s2c_w1 = (const float*)d_in[6];
    const float* s2c_b1 = (const float*)d_in[7];
    const float* s2c_w2 = (const float*)d_in[8];
    const float* s2c_b2 = (const float*)d_in[9];
    const float* s2c_rw = (const float*)d_in[10];
    const float* s2c_rb = (const float*)d_in[11];
    const float* c2s_w1 = (const float*)d_in[12];
    const float* c2s_b1 = (const float*)d_in[13];
    const float* c2s_w2 = (const float*)d_in[14];
    const float* c2s_b2 = (const float*)d_in[15];
    const float* c2s_rw = (const float*)d_in[16];
    const float* c2s_rb = (const float*)d_in[17];
    const float* gc_w1  = (const float*)d_in[18];
    const float* gc_b1  = (const float*)d_in[19];
    const float* gc_w2  = (const float*)d_in[20];
    const float* gc_b2  = (const float*)d_in[21];
    const float* gs_w1  = (const float*)d_in[22];
    const float* gs_b1  = (const float*)d_in[23];
    const float* gs_w2  = (const float*)d_in[24];
    const float* gs_b2  = (const float*)d_in[25];
    const int* s2c_src  = (const int*)d_in[26];
    const int* s2c_dst  = (const int*)d_in[27];
    const int* c2s_src  = (const int*)d_in[28];
    const int* c2s_dst  = (const int*)d_in[29];

    const int FGC = in_sizes[2] / 64;
    const int FGS = in_sizes[4] / 64;
    const int NGC = in_sizes[0] / FGC;
    const int NGS = in_sizes[1] / FGS;
    const int E1 = in_sizes[26];
    const int E2 = in_sizes[28];

    float *gcx, *gsx;
    unsigned *aggc, *aggs;
    cudaGetSymbolAddress((void**)&gcx, g_gcx);
    cudaGetSymbolAddress((void**)&gsx, g_gsx);
    cudaGetSymbolAddress((void**)&aggc, g_aggc);
    cudaGetSymbolAddress((void**)&aggs, g_aggs);

    const int NODE_SMEM = NODE_SMEM_FLOATS * 4;
    cudaFuncSetAttribute(edge_both_kernel, cudaFuncAttributeMaxDynamicSharedMemorySize, EX_SMEM);
    cudaFuncSetAttribute(node_both_kernel, cudaFuncAttributeMaxDynamicSharedMemorySize, NODE_SMEM);
    cudaFuncSetAttribute(finish_both_kernel, cudaFuncAttributeMaxDynamicSharedMemorySize, FIN_SMEM);

    // [0] init both agg arrays
    int totc = NGC * 320, tots = NGS * 320;
    init_all_kernel<<<(totc + tots + 255) / 256, 256>>>(aggc, aggs, totc, tots);
    // [1] embed both node types
    embed_all_kernel<<<((NGC + NGS) * 64 + 255) / 256, 256>>>(
        nf_gc, w_gc, b_gc, gcx, NGC, FGC, nf_gs, w_gs, b_gs, gsx, NGS, FGS);
    // [2] edge, both directions (profiled slot)
    edge_both_kernel<<<608, 256, EX_SMEM>>>(
        gcx, gsx,
        s2c_src, s2c_dst, s2c_w1, s2c_w2, s2c_b1, s2c_b2, aggc, E1,
        c2s_src, c2s_dst, c2s_w1, c2s_w2, c2s_b1, c2s_b2, aggs, E2);
    // [3] finish both
    finish_both_kernel<<<304, 256, FIN_SMEM>>>(aggc, s2c_w2, s2c_b2, NGC,
                                               aggs, c2s_w2, c2s_b2, NGS);
    // [4] node both
    float* out = (float*)d_out;
    node_both_kernel<<<304, 256, NODE_SMEM>>>(
        gcx, aggc, s2c_rw, s2c_rb, gc_w1, gc_b1, gc_w2, gc_b2, NGC,
        gsx, aggs, c2s_rw, c2s_rb, gs_w1, gs_b1, gs_w2, gs_b2, NGS, out);
}

// round 12
// speedup vs baseline: 1.6145x; 1.1951x over previous
#include <cuda_runtime.h>
#include <cuda_fp16.h>
#include <cstdint>

#define NMAX 100000

__device__ float    g_gcx[NMAX * 64];
__device__ float    g_gsx[NMAX * 64];
__device__ unsigned g_aggc[NMAX * 320];  // [q 0:128 | maxkey 128:192 | minkey 192:256 | ksum 256]
__device__ unsigned g_aggs[NMAX * 320];
__device__ float    g_rweff[2][321 * 64];

__device__ __forceinline__ unsigned fkey(float f) {
    unsigned u = __float_as_uint(f);
    return (u & 0x80000000u) ? ~u : (u | 0x80000000u);
}
__device__ __forceinline__ float fdec(unsigned k) {
    unsigned u = (k & 0x80000000u) ? (k & 0x7FFFFFFFu) : ~k;
    return __uint_as_float(u);
}
__device__ __forceinline__ uint32_t smem_to_u32(const void* p) {
    uint32_t a;
    asm("{ .reg .u64 t; cvta.to.shared.u64 t, %1; cvt.u32.u64 %0, t; }" : "=r"(a) : "l"(p));
    return a;
}
__device__ __forceinline__ void ldsm_x4(uint32_t a[4], uint32_t addr) {
    asm volatile("ldmatrix.sync.aligned.m8n8.x4.shared.b16 {%0,%1,%2,%3}, [%4];"
        : "=r"(a[0]), "=r"(a[1]), "=r"(a[2]), "=r"(a[3]) : "r"(addr));
}
__device__ __forceinline__ void ldsm_x2(uint32_t b[2], uint32_t addr) {
    asm volatile("ldmatrix.sync.aligned.m8n8.x2.shared.b16 {%0,%1}, [%2];"
        : "=r"(b[0]), "=r"(b[1]) : "r"(addr));
}
__device__ __forceinline__ void mma_f16(float c[4], const uint32_t a[4], const uint32_t b[2]) {
    asm volatile("mma.sync.aligned.m16n8k16.row.col.f32.f16.f16.f32 "
        "{%0,%1,%2,%3}, {%4,%5,%6,%7}, {%8,%9}, {%0,%1,%2,%3};"
        : "+f"(c[0]), "+f"(c[1]), "+f"(c[2]), "+f"(c[3])
        : "r"(a[0]), "r"(a[1]), "r"(a[2]), "r"(a[3]), "r"(b[0]), "r"(b[1]));
}
__device__ __forceinline__ uint32_t packh(__half a, __half b) {
    return (uint32_t)__half_as_ushort(a) | ((uint32_t)__half_as_ushort(b) << 16);
}

// ---------------- combined init (launch 0) ----------------
__global__ void init_all_kernel(unsigned* __restrict__ aggc, unsigned* __restrict__ aggs,
                                int totc, int tots) {
    int idx = blockIdx.x * blockDim.x + threadIdx.x;
    if (idx < totc) {
        int col = idx % 320;
        aggc[idx] = (col >= 192 && col < 256) ? 0xFFFFFFFFu : 0u;
    } else if (idx < totc + tots) {
        int j = idx - totc;
        int col = j % 320;
        aggs[j] = (col >= 192 && col < 256) ? 0xFFFFFFFFu : 0u;
    }
}

// ---------------- combined embed (launch 1) ----------------
__global__ void embed_all_kernel(
    const float* __restrict__ nfc, const float* __restrict__ wc,
    const float* __restrict__ bc, float* __restrict__ outc, int NC, int FC,
    const float* __restrict__ nfs, const float* __restrict__ ws,
    const float* __restrict__ bs, float* __restrict__ outs, int NS, int FS) {
    int idx = blockIdx.x * blockDim.x + threadIdx.x;
    if (idx < NC * 64) {
        int n = idx >> 6, h = idx & 63;
        const float* row = nfc + (size_t)n * FC;
        float acc = bc[h];
        for (int f = 0; f < FC; f++) acc = fmaf(__ldg(row + f), __ldg(wc + f * 64 + h), acc);
        outc[idx] = acc;
    } else if (idx < (NC + NS) * 64) {
        int j = idx - NC * 64;
        int n = j >> 6, h = j & 63;
        const float* row = nfs + (size_t)n * FS;
        float acc = bs[h];
        for (int f = 0; f < FS; f++) acc = fmaf(__ldg(row + f), __ldg(ws + f * 64 + h), acc);
        outs[j] = acc;
    }
}

// ---------------- rw_eff precompute (launch 2): fold finish into recombine ---
// rw_eff[321][64] per direction:
//   rows 0..63   = rw rows 0..63                 (x)
//   rows 64..191 = W2c1@rw[64:128] + W2c4@rw[256:320]   (q)
//   rows 192..255= rw rows 128..191              (max)
//   rows 256..319= rw rows 192..255              (min)
//   row 320      = b2c1@rw[64:128] + b2c4@rw[256:320]   (ksum)
__global__ void rweff_kernel(
    const float* __restrict__ rwa, const float* __restrict__ w2a, const float* __restrict__ b2a,
    const float* __restrict__ rwb, const float* __restrict__ w2b, const float* __restrict__ b2b,
    float* __restrict__ outbase) {
    const int r = blockIdx.x % 321;
    const int d = blockIdx.x / 321;
    const int j = threadIdx.x;  // 64 threads
    const float* rw = d ? rwb : rwa;
    const float* w2 = d ? w2b : w2a;
    const float* b2 = d ? b2b : b2a;
    float* out = outbase + (size_t)d * 321 * 64;
    float acc;
    if (r < 64) {
        acc = __ldg(rw + r * 64 + j);
    } else if (r < 192) {
        int k = r - 64;
        acc = 0.f;
        for (int t = 0; t < 64; t++)
            acc = fmaf(__ldg(w2 + k * 257 + 1 + t), __ldg(rw + (64 + t) * 64 + j), acc);
        for (int t = 0; t < 64; t++)
            acc = fmaf(__ldg(w2 + k * 257 + 193 + t), __ldg(rw + (256 + t) * 64 + j), acc);
    } else if (r < 320) {
        acc = __ldg(rw + (r - 64) * 64 + j);
    } else {
        acc = 0.f;
        for (int t = 0; t < 64; t++)
            acc = fmaf(__ldg(b2 + 1 + t), __ldg(rw + (64 + t) * 64 + j), acc);
        for (int t = 0; t < 64; t++)
            acc = fmaf(__ldg(b2 + 193 + t), __ldg(rw + (256 + t) * 64 + j), acc);
    }
    out[r * 64 + j] = acc;
}

// ================= fused edge kernel, BOTH directions (launch 3) ============
#define PADH 136
#define EX_XH 0
#define EX_XL 17408
#define EX_HH 34816
#define EX_W2T 52224
#define EX_WGT 87040
#define EX_B1 89216
#define EX_B2F 89728
#define EX_K  90240
#define EX_DST 90496
#define EX_BG 90752
#define EX_SMEM 90768
#define EDGE_HALF 304

__global__ void __launch_bounds__(256, 2) edge_both_kernel(
    const float* __restrict__ gcx, const float* __restrict__ gsx,
    const int* __restrict__ src1, const int* __restrict__ dst1,
    const float* __restrict__ w1a, const float* __restrict__ w2a,
    const float* __restrict__ b1a, const float* __restrict__ b2a,
    unsigned* __restrict__ agg1, int E1,
    const int* __restrict__ src2, const int* __restrict__ dst2,
    const float* __restrict__ w1b, const float* __restrict__ w2b,
    const float* __restrict__ b1b, const float* __restrict__ b2b,
    unsigned* __restrict__ agg2, int E2) {
    extern __shared__ char sm[];
    const uint32_t smb = smem_to_u32(sm);
    const int tid = threadIdx.x, lane = tid & 31, wid = tid >> 5;
    const bool d2 = blockIdx.x >= EDGE_HALF;
    const float* srcx = d2 ? gcx : gsx;
    const float* dstx = d2 ? gsx : gcx;
    const int* src = d2 ? src2 : src1;
    const int* dst = d2 ? dst2 : dst1;
    const float* w1 = d2 ? w1b : w1a;
    const float* w2 = d2 ? w2b : w2a;
    const float* b1 = d2 ? b1b : b1a;
    const float* b2 = d2 ? b2b : b2a;
    unsigned* agg = d2 ? agg2 : agg1;
    const int E = d2 ? E2 : E1;
    const int bid0 = blockIdx.x - (d2 ? EDGE_HALF : 0);

    float* s_b1  = (float*)(sm + EX_B1);
    float* s_b2f = (float*)(sm + EX_B2F);
    float* s_k   = (float*)(sm + EX_K);
    int*   s_dst = (int*)(sm + EX_DST);
    float* s_bg  = (float*)(sm + EX_BG);

    for (int idx = tid; idx < 128 * 128; idx += 256) {
        int n = idx & 127, k = idx >> 7;
        ((__half*)(sm + EX_W2T))[n * PADH + k] = __float2half_rn(__ldg(w2 + k * 257 + 65 + n));
    }
    for (int idx = tid; idx < 8 * PADH; idx += 256)
        ((__half*)(sm + EX_WGT))[idx] = __float2half_rn(0.f);
    if (tid < 128) {
        s_b1[tid] = __ldg(b1 + tid);
        s_b2f[tid] = __ldg(b2 + 65 + tid);
    }
    if (tid == 0) s_bg[0] = __ldg(b2);
    __syncthreads();
    if (tid < 128)
        ((__half*)(sm + EX_WGT))[tid] = __float2half_rn(__ldg(w2 + tid * 257));

    uint32_t B1h[2][8][2], B1l[2][8][2];
    __syncthreads();
    for (int idx = tid; idx < 128 * 128; idx += 256) {
        int k = idx >> 7, n = idx & 127;
        ((__half*)(sm + EX_XH))[n * PADH + k] = __float2half_rn(__ldg(w1 + idx));
    }
    __syncthreads();
    #pragma unroll
    for (int nf = 0; nf < 2; nf++)
        #pragma unroll
        for (int kf = 0; kf < 8; kf++) {
            uint32_t off = (uint32_t)((wid * 16 + nf * 8 + (lane & 7)) * PADH
                            + kf * 16 + (((lane >> 3) & 1) << 3)) * 2;
            ldsm_x2(B1h[nf][kf], smb + EX_XH + off);
        }
    __syncthreads();
    for (int idx = tid; idx < 128 * 128; idx += 256) {
        int k = idx >> 7, n = idx & 127;
        float w = __ldg(w1 + idx);
        __half h = __float2half_rn(w);
        ((__half*)(sm + EX_XH))[n * PADH + k] = __float2half_rn(w - __half2float(h));
    }
    __syncthreads();
    #pragma unroll
    for (int nf = 0; nf < 2; nf++)
        #pragma unroll
        for (int kf = 0; kf < 8; kf++) {
            uint32_t off = (uint32_t)((wid * 16 + nf * 8 + (lane & 7)) * PADH
                            + kf * 16 + (((lane >> 3) & 1) << 3)) * 2;
            ldsm_x2(B1l[nf][kf], smb + EX_XH + off);
        }

    const int eloc = tid >> 2, quad = tid & 3;
    const float bg = s_bg[0];
    const int ntiles = (E + 63) >> 6;
    for (int t = bid0; t < ntiles; t += EDGE_HALF) {
        const int tb = t * 64;
        __syncthreads();

        for (int idx = tid; idx < 2048; idx += 256) {
            int row = idx >> 5, q = idx & 31;
            int e = tb + row;
            int hf = q >> 4, qq = q & 15;
            const float4* rp;
            if (hf == 0) {
                int si = (e < E) ? __ldg(src + e) : 0;
                rp = (const float4*)(srcx + (size_t)si * 64);
            } else {
                int di = (e < E) ? __ldg(dst + e) : 0;
                rp = (const float4*)(dstx + (size_t)di * 64);
            }
            float4 v = __ldg(rp + qq);
            int col = hf * 64 + qq * 4;
            __half h0 = __float2half_rn(v.x), h1 = __float2half_rn(v.y);
            __half h2 = __float2half_rn(v.z), h3 = __float2half_rn(v.w);
            __half l0 = __float2half_rn(v.x - __half2float(h0));
            __half l1 = __float2half_rn(v.y - __half2float(h1));
            __half l2 = __float2half_rn(v.z - __half2float(h2));
            __half l3 = __float2half_rn(v.w - __half2float(h3));
            uint32_t off = (uint32_t)(row * PADH + col) * 2;
            *(uint32_t*)(sm + EX_XH + off) = packh(h0, h1);
            *(uint32_t*)(sm + EX_XH + off + 4) = packh(h2, h3);
            *(uint32_t*)(sm + EX_XL + off) = packh(l0, l1);
            *(uint32_t*)(sm + EX_XL + off + 4) = packh(l2, l3);
        }
        if (tid < 64) {
            int e = tb + tid;
            s_dst[tid] = (e < E) ? __ldg(dst + e) : 0;
        }
        __syncthreads();

        #pragma unroll
        for (int mt = 0; mt < 4; mt++) {
            float c[2][4] = {};
            #pragma unroll
            for (int kf = 0; kf < 8; kf++) {
                uint32_t Ah[4], Al[4];
                uint32_t aoff = (uint32_t)((mt * 16 + (lane & 15)) * PADH
                                 + kf * 16 + ((lane >> 4) << 3)) * 2;
                ldsm_x4(Ah, smb + EX_XH + aoff);
                ldsm_x4(Al, smb + EX_XL + aoff);
                #pragma unroll
                for (int nf = 0; nf < 2; nf++) {
                    mma_f16(c[nf], Ah, B1h[nf][kf]);
                    mma_f16(c[nf], Al, B1h[nf][kf]);
                    mma_f16(c[nf], Ah, B1l[nf][kf]);
                }
            }
            int r0 = mt * 16 + (lane >> 2), r1 = r0 + 8;
            #pragma unroll
            for (int nf = 0; nf < 2; nf++) {
                int cm = wid * 16 + nf * 8 + (lane & 3) * 2;
                float ba = s_b1[cm], bb = s_b1[cm + 1];
                __half a00 = __float2half_rn(fmaxf(c[nf][0] + ba, 0.f));
                __half a01 = __float2half_rn(fmaxf(c[nf][1] + bb, 0.f));
                __half a10 = __float2half_rn(fmaxf(c[nf][2] + ba, 0.f));
                __half a11 = __float2half_rn(fmaxf(c[nf][3] + bb, 0.f));
                *(uint32_t*)(sm + EX_HH + (uint32_t)(r0 * PADH + cm) * 2) = packh(a00, a01);
                *(uint32_t*)(sm + EX_HH + (uint32_t)(r1 * PADH + cm) * 2) = packh(a10, a11);
            }
        }
        __syncthreads();

        if (wid < 4) {
            const int mt = wid;
            float c[4] = {0.f, 0.f, 0.f, 0.f};
            #pragma unroll
            for (int kf = 0; kf < 8; kf++) {
                uint32_t Ah[4], Bgf[2];
                uint32_t aoff = (uint32_t)((mt * 16 + (lane & 15)) * PADH
                                 + kf * 16 + ((lane >> 4) << 3)) * 2;
                ldsm_x4(Ah, smb + EX_HH + aoff);
                uint32_t goff = (uint32_t)((lane & 7) * PADH
                                 + kf * 16 + (((lane >> 3) & 1) << 3)) * 2;
                ldsm_x2(Bgf, smb + EX_WGT + goff);
                mma_f16(c, Ah, Bgf);
            }
            if ((lane & 3) == 0) {
                int r0 = mt * 16 + (lane >> 2);
                s_k[r0]     = 1.f / (1.f + __expf(-(c[0] + bg)));
                s_k[r0 + 8] = 1.f / (1.f + __expf(-(c[2] + bg)));
            }
        }
        __syncthreads();

        {
            int e = tb + eloc;
            if (e < E) {
                float kk = s_k[eloc];
                int di = s_dst[eloc];
                float* qb = (float*)(agg + (size_t)di * 320) + quad * 32;
                uint32_t base = (uint32_t)(eloc * PADH + quad * 32) * 2;
                #pragma unroll
                for (int c4 = 0; c4 < 8; c4++) {
                    uint32_t u0 = *(uint32_t*)(sm + EX_HH + base + c4 * 8);
                    uint32_t u1 = *(uint32_t*)(sm + EX_HH + base + c4 * 8 + 4);
                    float2 f0 = __half22float2(*(__half2*)&u0);
                    float2 f1 = __half22float2(*(__half2*)&u1);
                    atomicAdd((float4*)(qb + c4 * 4),
                              make_float4(kk * f0.x, kk * f0.y, kk * f1.x, kk * f1.y));
                }
                if (quad == 0) atomicAdd((float*)(agg + (size_t)di * 320 + 256), kk);
            }
        }

        #pragma unroll
        for (int mt = 0; mt < 4; mt++) {
            float c[2][4] = {};
            #pragma unroll
            for (int kf = 0; kf < 8; kf++) {
                uint32_t Ah[4];
                uint32_t aoff = (uint32_t)((mt * 16 + (lane & 15)) * PADH
                                 + kf * 16 + ((lane >> 4) << 3)) * 2;
                ldsm_x4(Ah, smb + EX_HH + aoff);
                #pragma unroll
                for (int nf = 0; nf < 2; nf++) {
                    uint32_t Bf[2];
                    uint32_t boff = (uint32_t)((wid * 16 + nf * 8 + (lane & 7)) * PADH
                                     + kf * 16 + (((lane >> 3) & 1) << 3)) * 2;
                    ldsm_x2(Bf, smb + EX_W2T + boff);
                    mma_f16(c[nf], Ah, Bf);
                }
            }
            int r0 = mt * 16 + (lane >> 2), r1 = r0 + 8;
            bool v0 = tb + r0 < E, v1 = tb + r1 < E;
            float k0 = s_k[r0], k1 = s_k[r1];
            unsigned* row0 = agg + (size_t)s_dst[r0] * 320;
            unsigned* row1 = agg + (size_t)s_dst[r1] * 320;
            #pragma unroll
            for (int nf = 0; nf < 2; nf++) {
                int cm = wid * 16 + nf * 8 + (lane & 3) * 2;
                float ba = s_b2f[cm], bb = s_b2f[cm + 1];
                float v00 = (c[nf][0] + ba) * k0, v01 = (c[nf][1] + bb) * k0;
                float v10 = (c[nf][2] + ba) * k1, v11 = (c[nf][3] + bb) * k1;
                if (wid < 4) {
                    if (v0) { atomicMax(row0 + 128 + cm, fkey(v00)); atomicMax(row0 + 129 + cm, fkey(v01)); }
                    if (v1) { atomicMax(row1 + 128 + cm, fkey(v10)); atomicMax(row1 + 129 + cm, fkey(v11)); }
                } else {
                    if (v0) { atomicMin(row0 + 128 + cm, fkey(v00)); atomicMin(row0 + 129 + cm, fkey(v01)); }
                    if (v1) { atomicMin(row1 + 128 + cm, fkey(v10)); atomicMin(row1 + 129 + cm, fkey(v11)); }
                }
            }
        }
    }
}

// ---------------- node, both types (launch 4): z = [x|q|max|min|ksum] -------
#define NODE_SMEM_FLOATS (20544 + 8192 + 4096 + 64 + 64 + 64 + 32*321 + 32*68 + 32*132)
__global__ void __launch_bounds__(256, 1) node_both_kernel(
    const float* __restrict__ gcx, const unsigned* __restrict__ aggc,
    const float* __restrict__ rweffbase, const float* __restrict__ rba,
    const float* __restrict__ w1a, const float* __restrict__ b1a,
    const float* __restrict__ w2a, const float* __restrict__ b2a, int NC,
    const float* __restrict__ gsx, const unsigned* __restrict__ aggs,
    const float* __restrict__ rbb,
    const float* __restrict__ w1b, const float* __restrict__ b1b,
    const float* __restrict__ w2b, const float* __restrict__ b2b, int NS,
    float* __restrict__ out) {
    extern __shared__ float smf[];
    float* s_rw = smf;            // [321][64]
    float* s_w1 = smf + 20544;
    float* s_w2 = smf + 28736;
    float* s_rb = smf + 32832;
    float* s_b1 = smf + 32896;
    float* s_b2 = smf + 32960;
    float* s_z  = smf + 33024;    // [32][321]
    float* s_nx = smf + 43296;
    float* s_h  = smf + 45472;

    const int tid = threadIdx.x;
    const bool d2 = blockIdx.x >= 152;
    const float* x = d2 ? gsx : gcx;
    const unsigned* agg = d2 ? aggs : aggc;
    const float* rw = rweffbase + (d2 ? (size_t)321 * 64 : 0);
    const float* rb = d2 ? rbb : rba;
    const float* w1 = d2 ? w1b : w1a;
    const float* b1 = d2 ? b1b : b1a;
    const float* w2 = d2 ? w2b : w2a;
    const float* b2 = d2 ? b2b : b2a;
    const int N = d2 ? NS : NC;
    float* outp = out + (d2 ? (size_t)NC * 64 : 0);
    const int bid0 = blockIdx.x - (d2 ? 152 : 0);

    for (int i = tid; i < 5136; i += 256) ((float4*)s_rw)[i] = ((const float4*)rw)[i];
    for (int i = tid; i < 2048; i += 256) ((float4*)s_w1)[i] = ((const float4*)w1)[i];
    for (int i = tid; i < 1024; i += 256) ((float4*)s_w2)[i] = ((const float4*)w2)[i];
    if (tid < 64) { s_rb[tid] = rb[tid]; s_b1[tid] = b1[tid]; s_b2[tid] = b2[tid]; }
    __syncthreads();

    const int n = tid >> 3, jg = tid & 7;
    const int ntiles = (N + 31) >> 5;
    for (int tile = bid0; tile < ntiles; tile += 152) {
        const int n0 = tile * 32;
        for (int idx = tid; idx < 32 * 321; idx += 256) {
            int nn = idx / 321, i = idx - nn * 321;
            int gn = n0 + nn;
            float v = 0.f;
            if (gn < N) {
                if (i < 64) v = __ldg(x + (size_t)gn * 64 + i);
                else {
                    int c = i - 64;  // 0..256 -> agg col c
                    unsigned r = __ldg(agg + (size_t)gn * 320 + c);
                    if (c < 128 || c == 256) v = __uint_as_float(r);           // q | ksum
                    else if (c < 192) v = r ? fdec(r) : 0.f;                    // max
                    else v = (r == 0xFFFFFFFFu) ? 0.f : fdec(r);                // min
                }
            }
            s_z[nn * 321 + i] = v;
        }
        __syncthreads();

        const float* zrow = s_z + n * 321;
        float4 A = ((float4*)s_rb)[jg * 2], B = ((float4*)s_rb)[jg * 2 + 1];
        #pragma unroll 4
        for (int i = 0; i < 321; i++) {
            float zz = zrow[i];
            float4 wA = ((float4*)s_rw)[i * 16 + jg * 2];
            float4 wB = ((float4*)s_rw)[i * 16 + jg * 2 + 1];
            A.x = fmaf(zz, wA.x, A.x); A.y = fmaf(zz, wA.y, A.y);
            A.z = fmaf(zz, wA.z, A.z); A.w = fmaf(zz, wA.w, A.w);
            B.x = fmaf(zz, wB.x, B.x); B.y = fmaf(zz, wB.y, B.y);
            B.z = fmaf(zz, wB.z, B.z); B.w = fmaf(zz, wB.w, B.w);
        }
        ((float4*)(s_nx + n * 68))[jg * 2] = A;
        ((float4*)(s_nx + n * 68))[jg * 2 + 1] = B;
        __syncwarp();

        float hacc[16];
        #pragma unroll
        for (int tt = 0; tt < 16; tt++) hacc[tt] = s_b1[jg * 16 + tt];
        #pragma unroll 2
        for (int i = 0; i < 64; i++) {
            float in = zrow[i];
            const float* wr = s_w1 + i * 64 + jg * 16;
            #pragma unroll
            for (int tt = 0; tt < 16; tt++) hacc[tt] = fmaf(in, wr[tt], hacc[tt]);
        }
        const float* nxrow = s_nx + n * 68;
        #pragma unroll 2
        for (int i = 0; i < 64; i++) {
            float in = nxrow[i];
            const float* wr = s_w1 + (64 + i) * 64 + jg * 16;
            #pragma unroll
            for (int tt = 0; tt < 16; tt++) hacc[tt] = fmaf(in, wr[tt], hacc[tt]);
        }
        #pragma unroll
        for (int tt = 0; tt < 16; tt++) s_h[n * 132 + jg * 16 + tt] = fmaxf(hacc[tt], 0.f);
        __syncwarp();

        float4 O0 = ((float4*)s_b2)[jg * 2], O1 = ((float4*)s_b2)[jg * 2 + 1];
        const float* hrow = s_h + n * 132;
        #pragma unroll 4
        for (int i = 0; i < 64; i++) {
            float hv = hrow[i];
            float4 wA = ((float4*)s_w2)[i * 16 + jg * 2];
            float4 wB = ((float4*)s_w2)[i * 16 + jg * 2 + 1];
            O0.x = fmaf(hv, wA.x, O0.x); O0.y = fmaf(hv, wA.y, O0.y);
            O0.z = fmaf(hv, wA.z, O0.z); O0.w = fmaf(hv, wA.w, O0.w);
            O1.x = fmaf(hv, wB.x, O1.x); O1.y = fmaf(hv, wB.y, O1.y);
            O1.z = fmaf(hv, wB.z, O1.z); O1.w = fmaf(hv, wB.w, O1.w);
        }
        int gn = n0 + n;
        if (gn < N) {
            ((float4*)(outp + (size_t)gn * 64 + jg * 8))[0] = O0;
            ((float4*)(outp + (size_t)gn * 64 + jg * 8))[1] = O1;
        }
        __syncthreads();
    }
}

// ---------------------------------------------------------------------------
extern "C" void kernel_launch(void* const* d_in, const int* in_sizes, int n_in,
                              void* d_out, int out_size) {
    const float* nf_gc  = (const float*)d_in[0];
    const float* nf_gs  = (const float*)d_in[1];
    const float* w_gc   = (const float*)d_in[2];
    const float* b_gc   = (const float*)d_in[3];
    const float* w_gs   = (const float*)d_in[4];
    const float* b_gs   = (const float*)d_in[5];
    const float* s2c_w1 = (const float*)d_in[6];
    const float* s2c_b1 = (const float*)d_in[7];
    const float* s2c_w2 = (const float*)d_in[8];
    const float* s2c_b2 = (const float*)d_in[9];
    const float* s2c_rw = (const float*)d_in[10];
    const float* s2c_rb = (const float*)d_in[11];
    const float* c2s_w1 = (const float*)d_in[12];
    const float* c2s_b1 = (const float*)d_in[13];
    const float* c2s_w2 = (const float*)d_in[14];
    const float* c2s_b2 = (const float*)d_in[15];
    const float* c2s_rw = (const float*)d_in[16];
    const float* c2s_rb = (const float*)d_in[17];
    const float* gc_w1  = (const float*)d_in[18];
    const float* gc_b1  = (const float*)d_in[19];
    const float* gc_w2  = (const float*)d_in[20];
    const float* gc_b2  = (const float*)d_in[21];
    const float* gs_w1  = (const float*)d_in[22];
    const float* gs_b1  = (const float*)d_in[23];
    const float* gs_w2  = (const float*)d_in[24];
    const float* gs_b2  = (const float*)d_in[25];
    const int* s2c_src  = (const int*)d_in[26];
    const int* s2c_dst  = (const int*)d_in[27];
    const int* c2s_src  = (const int*)d_in[28];
    const int* c2s_dst  = (const int*)d_in[29];

    const int FGC = in_sizes[2] / 64;
    const int FGS = in_sizes[4] / 64;
    const int NGC = in_sizes[0] / FGC;
    const int NGS = in_sizes[1] / FGS;
    const int E1 = in_sizes[26];
    const int E2 = in_sizes[28];

    float *gcx, *gsx, *rweff;
    unsigned *aggc, *aggs;
    cudaGetSymbolAddress((void**)&gcx, g_gcx);
    cudaGetSymbolAddress((void**)&gsx, g_gsx);
    cudaGetSymbolAddress((void**)&aggc, g_aggc);
    cudaGetSymbolAddress((void**)&aggs, g_aggs);
    cudaGetSymbolAddress((void**)&rweff, g_rweff);

    const int NODE_SMEM = NODE_SMEM_FLOATS * 4;
    cudaFuncSetAttribute(edge_both_kernel, cudaFuncAttributeMaxDynamicSharedMemorySize, EX_SMEM);
    cudaFuncSetAttribute(node_both_kernel, cudaFuncAttributeMaxDynamicSharedMemorySize, NODE_SMEM);

    // [0] init both agg arrays
    int totc = NGC * 320, tots = NGS * 320;
    init_all_kernel<<<(totc + tots + 255) / 256, 256>>>(aggc, aggs, totc, tots);
    // [1] embed both node types
    embed_all_kernel<<<((NGC + NGS) * 64 + 255) / 256, 256>>>(
        nf_gc, w_gc, b_gc, gcx, NGC, FGC, nf_gs, w_gs, b_gs, gsx, NGS, FGS);
    // [2] rw_eff precompute (folds finish into recombine)
    rweff_kernel<<<642, 64>>>(s2c_rw, s2c_w2, s2c_b2, c2s_rw, c2s_w2, c2s_b2, rweff);
    // [3] edge, both directions (profiled slot)
    edge_both_kernel<<<608, 256, EX_SMEM>>>(
        gcx, gsx,
        s2c_src, s2c_dst, s2c_w1, s2c_w2, s2c_b1, s2c_b2, aggc, E1,
        c2s_src, c2s_dst, c2s_w1, c2s_w2, c2s_b1, c2s_b2, aggs, E2);
    // [4] node both (consumes q/max/min/ksum directly via rw_eff)
    float* out = (float*)d_out;
    node_both_kernel<<<304, 256, NODE_SMEM>>>(
        gcx, aggc, rweff, s2c_rb, gc_w1, gc_b1, gc_w2, gc_b2, NGC,
        gsx, aggs, c2s_rb, gs_w1, gs_b1, gs_w2, gs_b2, NGS, out);
}

// round 13
// speedup vs baseline: 4.7941x; 2.9695x over previous
#include <cuda_runtime.h>
#include <cuda_fp16.h>
#include <cstdint>

#define NMAX 100000

__device__ float    g_gcx[NMAX * 64];
__device__ float    g_gsx[NMAX * 64];
__device__ unsigned g_aggc[NMAX * 320];
__device__ unsigned g_aggs[NMAX * 320];
__device__ float    g_rweff[2][321 * 64];
__device__ float    g_wh[2][336 * 64];
__device__ float    g_bh[2][64];

__device__ __forceinline__ unsigned fkey(float f) {
    unsigned u = __float_as_uint(f);
    return (u & 0x80000000u) ? ~u : (u | 0x80000000u);
}
__device__ __forceinline__ float fdec(unsigned k) {
    unsigned u = (k & 0x80000000u) ? (k & 0x7FFFFFFFu) : ~k;
    return __uint_as_float(u);
}
__device__ __forceinline__ uint32_t smem_to_u32(const void* p) {
    uint32_t a;
    asm("{ .reg .u64 t; cvta.to.shared.u64 t, %1; cvt.u32.u64 %0, t; }" : "=r"(a) : "l"(p));
    return a;
}
__device__ __forceinline__ void ldsm_x4(uint32_t a[4], uint32_t addr) {
    asm volatile("ldmatrix.sync.aligned.m8n8.x4.shared.b16 {%0,%1,%2,%3}, [%4];"
        : "=r"(a[0]), "=r"(a[1]), "=r"(a[2]), "=r"(a[3]) : "r"(addr));
}
__device__ __forceinline__ void ldsm_x2(uint32_t b[2], uint32_t addr) {
    asm volatile("ldmatrix.sync.aligned.m8n8.x2.shared.b16 {%0,%1}, [%2];"
        : "=r"(b[0]), "=r"(b[1]) : "r"(addr));
}
__device__ __forceinline__ void mma_f16(float c[4], const uint32_t a[4], const uint32_t b[2]) {
    asm volatile("mma.sync.aligned.m16n8k16.row.col.f32.f16.f16.f32 "
        "{%0,%1,%2,%3}, {%4,%5,%6,%7}, {%8,%9}, {%0,%1,%2,%3};"
        : "+f"(c[0]), "+f"(c[1]), "+f"(c[2]), "+f"(c[3])
        : "r"(a[0]), "r"(a[1]), "r"(a[2]), "r"(a[3]), "r"(b[0]), "r"(b[1]));
}
__device__ __forceinline__ uint32_t packh(__half a, __half b) {
    return (uint32_t)__half_as_ushort(a) | ((uint32_t)__half_as_ushort(b) << 16);
}

// ---------------- [0] init ----------------
__global__ void init_all_kernel(unsigned* __restrict__ aggc, unsigned* __restrict__ aggs,
                                int totc, int tots) {
    int idx = blockIdx.x * blockDim.x + threadIdx.x;
    if (idx < totc) {
        int col = idx % 320;
        aggc[idx] = (col >= 192 && col < 256) ? 0xFFFFFFFFu : 0u;
    } else if (idx < totc + tots) {
        int j = idx - totc;
        int col = j % 320;
        aggs[j] = (col >= 192 && col < 256) ? 0xFFFFFFFFu : 0u;
    }
}

// ---------------- [1] embed ----------------
__global__ void embed_all_kernel(
    const float* __restrict__ nfc, const float* __restrict__ wc,
    const float* __restrict__ bc, float* __restrict__ outc, int NC, int FC,
    const float* __restrict__ nfs, const float* __restrict__ ws,
    const float* __restrict__ bs, float* __restrict__ outs, int NS, int FS) {
    int idx = blockIdx.x * blockDim.x + threadIdx.x;
    if (idx < NC * 64) {
        int n = idx >> 6, h = idx & 63;
        const float* row = nfc + (size_t)n * FC;
        float acc = bc[h];
        for (int f = 0; f < FC; f++) acc = fmaf(__ldg(row + f), __ldg(wc + f * 64 + h), acc);
        outc[idx] = acc;
    } else if (idx < (NC + NS) * 64) {
        int j = idx - NC * 64;
        int n = j >> 6, h = j & 63;
        const float* row = nfs + (size_t)n * FS;
        float acc = bs[h];
        for (int f = 0; f < FS; f++) acc = fmaf(__ldg(row + f), __ldg(ws + f * 64 + h), acc);
        outs[j] = acc;
    }
}

// ---------------- [2] rw_eff: fold finish GEMV into recombine ----------------
__global__ void rweff_kernel(
    const float* __restrict__ rwa, const float* __restrict__ w2a, const float* __restrict__ b2a,
    const float* __restrict__ rwb, const float* __restrict__ w2b, const float* __restrict__ b2b,
    float* __restrict__ outbase) {
    const int r = blockIdx.x % 321;
    const int d = blockIdx.x / 321;
    const int j = threadIdx.x;
    const float* rw = d ? rwb : rwa;
    const float* w2 = d ? w2b : w2a;
    const float* b2 = d ? b2b : b2a;
    float* out = outbase + (size_t)d * 321 * 64;
    float acc;
    if (r < 64) {
        acc = __ldg(rw + r * 64 + j);
    } else if (r < 192) {
        int k = r - 64;
        acc = 0.f;
        for (int t = 0; t < 64; t++)
            acc = fmaf(__ldg(w2 + k * 257 + 1 + t), __ldg(rw + (64 + t) * 64 + j), acc);
        for (int t = 0; t < 64; t++)
            acc = fmaf(__ldg(w2 + k * 257 + 193 + t), __ldg(rw + (256 + t) * 64 + j), acc);
    } else if (r < 320) {
        acc = __ldg(rw + (r - 64) * 64 + j);
    } else {
        acc = 0.f;
        for (int t = 0; t < 64; t++)
            acc = fmaf(__ldg(b2 + 1 + t), __ldg(rw + (64 + t) * 64 + j), acc);
        for (int t = 0; t < 64; t++)
            acc = fmaf(__ldg(b2 + 193 + t), __ldg(rw + (256 + t) * 64 + j), acc);
    }
    out[r * 64 + j] = acc;
}

// ---------------- [3] whfold: Wh = rw_eff@w1_bot (+ w1_top), bh = b1 + rb@w1_bot
__global__ void whfold_kernel(
    const float* __restrict__ rweffbase,
    const float* __restrict__ w1a, const float* __restrict__ b1a, const float* __restrict__ rba,
    const float* __restrict__ w1b, const float* __restrict__ b1b, const float* __restrict__ rbb,
    float* __restrict__ whbase, float* __restrict__ bhbase) {
    const int r = blockIdx.x % 337;   // 0..335 = Wh row, 336 = bh
    const int d = blockIdx.x / 337;
    const int j = threadIdx.x;
    const float* rweff = rweffbase + (size_t)d * 321 * 64;
    const float* w1 = d ? w1b : w1a;
    const float* b1 = d ? b1b : b1a;
    const float* rb = d ? rbb : rba;
    float* wh = whbase + (size_t)d * 336 * 64;
    float* bh = bhbase + (size_t)d * 64;
    if (r == 336) {
        float acc = __ldg(b1 + j);
        for (int t = 0; t < 64; t++)
            acc = fmaf(__ldg(rb + t), __ldg(w1 + (64 + t) * 64 + j), acc);
        bh[j] = acc;
    } else if (r >= 321) {
        wh[r * 64 + j] = 0.f;
    } else {
        float acc = 0.f;
        for (int t = 0; t < 64; t++)
            acc = fmaf(__ldg(rweff + r * 64 + t), __ldg(w1 + (64 + t) * 64 + j), acc);
        if (r < 64) acc += __ldg(w1 + r * 64 + j);
        wh[r * 64 + j] = acc;
    }
}

// ================= [4] fused edge kernel, both directions (unchanged) =======
#define PADH 136
#define EX_XH 0
#define EX_XL 17408
#define EX_HH 34816
#define EX_W2T 52224
#define EX_WGT 87040
#define EX_B1 89216
#define EX_B2F 89728
#define EX_K  90240
#define EX_DST 90496
#define EX_BG 90752
#define EX_SMEM 90768
#define EDGE_HALF 304

__global__ void __launch_bounds__(256, 2) edge_both_kernel(
    const float* __restrict__ gcx, const float* __restrict__ gsx,
    const int* __restrict__ src1, const int* __restrict__ dst1,
    const float* __restrict__ w1a, const float* __restrict__ w2a,
    const float* __restrict__ b1a, const float* __restrict__ b2a,
    unsigned* __restrict__ agg1, int E1,
    const int* __restrict__ src2, const int* __restrict__ dst2,
    const float* __restrict__ w1b, const float* __restrict__ w2b,
    const float* __restrict__ b1b, const float* __restrict__ b2b,
    unsigned* __restrict__ agg2, int E2) {
    extern __shared__ char sm[];
    const uint32_t smb = smem_to_u32(sm);
    const int tid = threadIdx.x, lane = tid & 31, wid = tid >> 5;
    const bool d2 = blockIdx.x >= EDGE_HALF;
    const float* srcx = d2 ? gcx : gsx;
    const float* dstx = d2 ? gsx : gcx;
    const int* src = d2 ? src2 : src1;
    const int* dst = d2 ? dst2 : dst1;
    const float* w1 = d2 ? w1b : w1a;
    const float* w2 = d2 ? w2b : w2a;
    const float* b1 = d2 ? b1b : b1a;
    const float* b2 = d2 ? b2b : b2a;
    unsigned* agg = d2 ? agg2 : agg1;
    const int E = d2 ? E2 : E1;
    const int bid0 = blockIdx.x - (d2 ? EDGE_HALF : 0);

    float* s_b1  = (float*)(sm + EX_B1);
    float* s_b2f = (float*)(sm + EX_B2F);
    float* s_k   = (float*)(sm + EX_K);
    int*   s_dst = (int*)(sm + EX_DST);
    float* s_bg  = (float*)(sm + EX_BG);

    for (int idx = tid; idx < 128 * 128; idx += 256) {
        int n = idx & 127, k = idx >> 7;
        ((__half*)(sm + EX_W2T))[n * PADH + k] = __float2half_rn(__ldg(w2 + k * 257 + 65 + n));
    }
    for (int idx = tid; idx < 8 * PADH; idx += 256)
        ((__half*)(sm + EX_WGT))[idx] = __float2half_rn(0.f);
    if (tid < 128) {
        s_b1[tid] = __ldg(b1 + tid);
        s_b2f[tid] = __ldg(b2 + 65 + tid);
    }
    if (tid == 0) s_bg[0] = __ldg(b2);
    __syncthreads();
    if (tid < 128)
        ((__half*)(sm + EX_WGT))[tid] = __float2half_rn(__ldg(w2 + tid * 257));

    uint32_t B1h[2][8][2], B1l[2][8][2];
    __syncthreads();
    for (int idx = tid; idx < 128 * 128; idx += 256) {
        int k = idx >> 7, n = idx & 127;
        ((__half*)(sm + EX_XH))[n * PADH + k] = __float2half_rn(__ldg(w1 + idx));
    }
    __syncthreads();
    #pragma unroll
    for (int nf = 0; nf < 2; nf++)
        #pragma unroll
        for (int kf = 0; kf < 8; kf++) {
            uint32_t off = (uint32_t)((wid * 16 + nf * 8 + (lane & 7)) * PADH
                            + kf * 16 + (((lane >> 3) & 1) << 3)) * 2;
            ldsm_x2(B1h[nf][kf], smb + EX_XH + off);
        }
    __syncthreads();
    for (int idx = tid; idx < 128 * 128; idx += 256) {
        int k = idx >> 7, n = idx & 127;
        float w = __ldg(w1 + idx);
        __half h = __float2half_rn(w);
        ((__half*)(sm + EX_XH))[n * PADH + k] = __float2half_rn(w - __half2float(h));
    }
    __syncthreads();
    #pragma unroll
    for (int nf = 0; nf < 2; nf++)
        #pragma unroll
        for (int kf = 0; kf < 8; kf++) {
            uint32_t off = (uint32_t)((wid * 16 + nf * 8 + (lane & 7)) * PADH
                            + kf * 16 + (((lane >> 3) & 1) << 3)) * 2;
            ldsm_x2(B1l[nf][kf], smb + EX_XH + off);
        }

    const int eloc = tid >> 2, quad = tid & 3;
    const float bg = s_bg[0];
    const int ntiles = (E + 63) >> 6;
    for (int t = bid0; t < ntiles; t += EDGE_HALF) {
        const int tb = t * 64;
        __syncthreads();

        for (int idx = tid; idx < 2048; idx += 256) {
            int row = idx >> 5, q = idx & 31;
            int e = tb + row;
            int hf = q >> 4, qq = q & 15;
            const float4* rp;
            if (hf == 0) {
                int si = (e < E) ? __ldg(src + e) : 0;
                rp = (const float4*)(srcx + (size_t)si * 64);
            } else {
                int di = (e < E) ? __ldg(dst + e) : 0;
                rp = (const float4*)(dstx + (size_t)di * 64);
            }
            float4 v = __ldg(rp + qq);
            int col = hf * 64 + qq * 4;
            __half h0 = __float2half_rn(v.x), h1 = __float2half_rn(v.y);
            __half h2 = __float2half_rn(v.z), h3 = __float2half_rn(v.w);
            __half l0 = __float2half_rn(v.x - __half2float(h0));
            __half l1 = __float2half_rn(v.y - __half2float(h1));
            __half l2 = __float2half_rn(v.z - __half2float(h2));
            __half l3 = __float2half_rn(v.w - __half2float(h3));
            uint32_t off = (uint32_t)(row * PADH + col) * 2;
            *(uint32_t*)(sm + EX_XH + off) = packh(h0, h1);
            *(uint32_t*)(sm + EX_XH + off + 4) = packh(h2, h3);
            *(uint32_t*)(sm + EX_XL + off) = packh(l0, l1);
            *(uint32_t*)(sm + EX_XL + off + 4) = packh(l2, l3);
        }
        if (tid < 64) {
            int e = tb + tid;
            s_dst[tid] = (e < E) ? __ldg(dst + e) : 0;
        }
        __syncthreads();

        #pragma unroll
        for (int mt = 0; mt < 4; mt++) {
            float c[2][4] = {};
            #pragma unroll
            for (int kf = 0; kf < 8; kf++) {
                uint32_t Ah[4], Al[4];
                uint32_t aoff = (uint32_t)((mt * 16 + (lane & 15)) * PADH
                                 + kf * 16 + ((lane >> 4) << 3)) * 2;
                ldsm_x4(Ah, smb + EX_XH + aoff);
                ldsm_x4(Al, smb + EX_XL + aoff);
                #pragma unroll
                for (int nf = 0; nf < 2; nf++) {
                    mma_f16(c[nf], Ah, B1h[nf][kf]);
                    mma_f16(c[nf], Al, B1h[nf][kf]);
                    mma_f16(c[nf], Ah, B1l[nf][kf]);
                }
            }
            int r0 = mt * 16 + (lane >> 2), r1 = r0 + 8;
            #pragma unroll
            for (int nf = 0; nf < 2; nf++) {
                int cm = wid * 16 + nf * 8 + (lane & 3) * 2;
                float ba = s_b1[cm], bb = s_b1[cm + 1];
                __half a00 = __float2half_rn(fmaxf(c[nf][0] + ba, 0.f));
                __half a01 = __float2half_rn(fmaxf(c[nf][1] + bb, 0.f));
                __half a10 = __float2half_rn(fmaxf(c[nf][2] + ba, 0.f));
                __half a11 = __float2half_rn(fmaxf(c[nf][3] + bb, 0.f));
                *(uint32_t*)(sm + EX_HH + (uint32_t)(r0 * PADH + cm) * 2) = packh(a00, a01);
                *(uint32_t*)(sm + EX_HH + (uint32_t)(r1 * PADH + cm) * 2) = packh(a10, a11);
            }
        }
        __syncthreads();

        if (wid < 4) {
            const int mt = wid;
            float c[4] = {0.f, 0.f, 0.f, 0.f};
            #pragma unroll
            for (int kf = 0; kf < 8; kf++) {
                uint32_t Ah[4], Bgf[2];
                uint32_t aoff = (uint32_t)((mt * 16 + (lane & 15)) * PADH
                                 + kf * 16 + ((lane >> 4) << 3)) * 2;
                ldsm_x4(Ah, smb + EX_HH + aoff);
                uint32_t goff = (uint32_t)((lane & 7) * PADH
                                 + kf * 16 + (((lane >> 3) & 1) << 3)) * 2;
                ldsm_x2(Bgf, smb + EX_WGT + goff);
                mma_f16(c, Ah, Bgf);
            }
            if ((lane & 3) == 0) {
                int r0 = mt * 16 + (lane >> 2);
                s_k[r0]     = 1.f / (1.f + __expf(-(c[0] + bg)));
                s_k[r0 + 8] = 1.f / (1.f + __expf(-(c[2] + bg)));
            }
        }
        __syncthreads();

        {
            int e = tb + eloc;
            if (e < E) {
                float kk = s_k[eloc];
                int di = s_dst[eloc];
                float* qb = (float*)(agg + (size_t)di * 320) + quad * 32;
                uint32_t base = (uint32_t)(eloc * PADH + quad * 32) * 2;
                #pragma unroll
                for (int c4 = 0; c4 < 8; c4++) {
                    uint32_t u0 = *(uint32_t*)(sm + EX_HH + base + c4 * 8);
                    uint32_t u1 = *(uint32_t*)(sm + EX_HH + base + c4 * 8 + 4);
                    float2 f0 = __half22float2(*(__half2*)&u0);
                    float2 f1 = __half22float2(*(__half2*)&u1);
                    atomicAdd((float4*)(qb + c4 * 4),
                              make_float4(kk * f0.x, kk * f0.y, kk * f1.x, kk * f1.y));
                }
                if (quad == 0) atomicAdd((float*)(agg + (size_t)di * 320 + 256), kk);
            }
        }

        #pragma unroll
        for (int mt = 0; mt < 4; mt++) {
            float c[2][4] = {};
            #pragma unroll
            for (int kf = 0; kf < 8; kf++) {
                uint32_t Ah[4];
                uint32_t aoff = (uint32_t)((mt * 16 + (lane & 15)) * PADH
                                 + kf * 16 + ((lane >> 4) << 3)) * 2;
                ldsm_x4(Ah, smb + EX_HH + aoff);
                #pragma unroll
                for (int nf = 0; nf < 2; nf++) {
                    uint32_t Bf[2];
                    uint32_t boff = (uint32_t)((wid * 16 + nf * 8 + (lane & 7)) * PADH
                                     + kf * 16 + (((lane >> 3) & 1) << 3)) * 2;
                    ldsm_x2(Bf, smb + EX_W2T + boff);
                    mma_f16(c[nf], Ah, Bf);
                }
            }
            int r0 = mt * 16 + (lane >> 2), r1 = r0 + 8;
            bool v0 = tb + r0 < E, v1 = tb + r1 < E;
            float k0 = s_k[r0], k1 = s_k[r1];
            unsigned* row0 = agg + (size_t)s_dst[r0] * 320;
            unsigned* row1 = agg + (size_t)s_dst[r1] * 320;
            #pragma unroll
            for (int nf = 0; nf < 2; nf++) {
                int cm = wid * 16 + nf * 8 + (lane & 3) * 2;
                float ba = s_b2f[cm], bb = s_b2f[cm + 1];
                float v00 = (c[nf][0] + ba) * k0, v01 = (c[nf][1] + bb) * k0;
                float v10 = (c[nf][2] + ba) * k1, v11 = (c[nf][3] + bb) * k1;
                if (wid < 4) {
                    if (v0) { atomicMax(row0 + 128 + cm, fkey(v00)); atomicMax(row0 + 129 + cm, fkey(v01)); }
                    if (v1) { atomicMax(row1 + 128 + cm, fkey(v10)); atomicMax(row1 + 129 + cm, fkey(v11)); }
                } else {
                    if (v0) { atomicMin(row0 + 128 + cm, fkey(v00)); atomicMin(row0 + 129 + cm, fkey(v01)); }
                    if (v1) { atomicMin(row1 + 128 + cm, fkey(v10)); atomicMin(row1 + 129 + cm, fkey(v11)); }
                }
            }
        }
    }
}

// ================= [5] node MMA kernel: out = relu(z@Wh+bh)@w2 + b2 =========
// 64-node tiles; z fp16 hi/lo (2-term A); Wh/w2 single fp16 B hoisted; occ 2.
#define NPAD1 344
#define NPAD2 72
#define NZ_H 0
#define NZ_L 44032
#define NH_H 88064
#define NH_L 97280
#define NB_BH 106496
#define NB_B2 106752
#define N_SMEM 107008
#define NODE_HALF 304

__global__ void __launch_bounds__(256, 2) node_mma_kernel(
    const float* __restrict__ gcx, const unsigned* __restrict__ aggc,
    const float* __restrict__ w2a, const float* __restrict__ b2a, int NC,
    const float* __restrict__ gsx, const unsigned* __restrict__ aggs,
    const float* __restrict__ w2b, const float* __restrict__ b2b, int NS,
    const float* __restrict__ whbase, const float* __restrict__ bhbase,
    float* __restrict__ out) {
    extern __shared__ char sm[];
    const uint32_t smb = smem_to_u32(sm);
    const int tid = threadIdx.x, lane = tid & 31, wid = tid >> 5;
    const bool d2 = blockIdx.x >= NODE_HALF;
    const float* x = d2 ? gsx : gcx;
    const unsigned* agg = d2 ? aggs : aggc;
    const float* w2 = d2 ? w2b : w2a;
    const float* b2v = d2 ? b2b : b2a;
    const float* wh = whbase + (d2 ? (size_t)336 * 64 : 0);
    const float* bh = bhbase + (d2 ? 64 : 0);
    const int N = d2 ? NS : NC;
    float* outp = out + (d2 ? (size_t)NC * 64 : 0);
    const int bid0 = blockIdx.x - (d2 ? NODE_HALF : 0);

    float* s_bh = (float*)(sm + NB_BH);
    float* s_b2 = (float*)(sm + NB_B2);

    // stage Wh [336k x 64n] -> smem [n][k] fp16 (ZH region), hoist BW
    for (int idx = tid; idx < 64 * 344; idx += 256) {
        int n = idx / 344, k = idx - n * 344;
        float w = (k < 336) ? __ldg(wh + k * 64 + n) : 0.f;
        ((__half*)(sm + NZ_H))[n * NPAD1 + k] = __float2half_rn(w);
    }
    // stage w2 [64k x 64n] -> smem [n][k] fp16 (HH region)
    for (int idx = tid; idx < 64 * 72; idx += 256) {
        int n = idx / 72, k = idx - n * 72;
        float w = (k < 64) ? __ldg(w2 + k * 64 + n) : 0.f;
        ((__half*)(sm + NH_H))[n * NPAD2 + k] = __float2half_rn(w);
    }
    if (tid < 64) { s_bh[tid] = __ldg(bh + tid); s_b2[tid] = __ldg(b2v + tid); }
    __syncthreads();

    uint32_t BW[21][2], W2F[4][2];
    #pragma unroll
    for (int kf = 0; kf < 21; kf++) {
        uint32_t off = (uint32_t)((wid * 8 + (lane & 7)) * NPAD1
                        + kf * 16 + (((lane >> 3) & 1) << 3)) * 2;
        ldsm_x2(BW[kf], smb + NZ_H + off);
    }
    #pragma unroll
    for (int kf = 0; kf < 4; kf++) {
        uint32_t off = (uint32_t)((wid * 8 + (lane & 7)) * NPAD2
                        + kf * 16 + (((lane >> 3) & 1) << 3)) * 2;
        ldsm_x2(W2F[kf], smb + NH_H + off);
    }
    __syncthreads();  // weight smem now reusable

    const int ntiles = (N + 63) >> 6;
    for (int t = bid0; t < ntiles; t += NODE_HALF) {
        const int n0 = t * 64;

        // load z tile [64 x 336], split fp16 hi/lo -> ZH/ZL
        for (int idx = tid; idx < 64 * 336; idx += 256) {
            int row = idx / 336, i = idx - row * 336;
            int gn = n0 + row;
            float v = 0.f;
            if (gn < N && i < 321) {
                if (i < 64) v = __ldg(x + (size_t)gn * 64 + i);
                else {
                    int c = i - 64;
                    unsigned r = __ldg(agg + (size_t)gn * 320 + c);
                    if (c < 128 || c == 256) v = __uint_as_float(r);
                    else if (c < 192) v = r ? fdec(r) : 0.f;
                    else v = (r == 0xFFFFFFFFu) ? 0.f : fdec(r);
                }
            }
            __half h = __float2half_rn(v);
            __half l = __float2half_rn(v - __half2float(h));
            ((__half*)(sm + NZ_H))[row * NPAD1 + i] = h;
            ((__half*)(sm + NZ_L))[row * NPAD1 + i] = l;
        }
        __syncthreads();  // also guards prev tile's GEMM2 H reads vs new GEMM1 H writes

        // GEMM1: h = relu(z@Wh + bh) -> HH/HL fp16
        #pragma unroll
        for (int mt = 0; mt < 4; mt++) {
            float c[4] = {0.f, 0.f, 0.f, 0.f};
            #pragma unroll
            for (int kf = 0; kf < 21; kf++) {
                uint32_t Ah[4], Al[4];
                uint32_t aoff = (uint32_t)((mt * 16 + (lane & 15)) * NPAD1
                                 + kf * 16 + ((lane >> 4) << 3)) * 2;
                ldsm_x4(Ah, smb + NZ_H + aoff);
                ldsm_x4(Al, smb + NZ_L + aoff);
                mma_f16(c, Ah, BW[kf]);
                mma_f16(c, Al, BW[kf]);
            }
            int r0 = mt * 16 + (lane >> 2), r1 = r0 + 8;
            int cm = wid * 8 + (lane & 3) * 2;
            float ba = s_bh[cm], bb = s_bh[cm + 1];
            float h00 = fmaxf(c[0] + ba, 0.f), h01 = fmaxf(c[1] + bb, 0.f);
            float h10 = fmaxf(c[2] + ba, 0.f), h11 = fmaxf(c[3] + bb, 0.f);
            __half a00 = __float2half_rn(h00), a01 = __float2half_rn(h01);
            __half a10 = __float2half_rn(h10), a11 = __float2half_rn(h11);
            __half q00 = __float2half_rn(h00 - __half2float(a00));
            __half q01 = __float2half_rn(h01 - __half2float(a01));
            __half q10 = __float2half_rn(h10 - __half2float(a10));
            __half q11 = __float2half_rn(h11 - __half2float(a11));
            *(uint32_t*)(sm + NH_H + (uint32_t)(r0 * NPAD2 + cm) * 2) = packh(a00, a01);
            *(uint32_t*)(sm + NH_L + (uint32_t)(r0 * NPAD2 + cm) * 2) = packh(q00, q01);
            *(uint32_t*)(sm + NH_H + (uint32_t)(r1 * NPAD2 + cm) * 2) = packh(a10, a11);
            *(uint32_t*)(sm + NH_L + (uint32_t)(r1 * NPAD2 + cm) * 2) = packh(q10, q11);
        }
        __syncthreads();

        // GEMM2: out = h@w2 + b2 -> gmem
        #pragma unroll
        for (int mt = 0; mt < 4; mt++) {
            float c[4] = {0.f, 0.f, 0.f, 0.f};
            #pragma unroll
            for (int kf = 0; kf < 4; kf++) {
                uint32_t Ah[4], Al[4];
                uint32_t aoff = (uint32_t)((mt * 16 + (lane & 15)) * NPAD2
                                 + kf * 16 + ((lane >> 4) << 3)) * 2;
                ldsm_x4(Ah, smb + NH_H + aoff);
                ldsm_x4(Al, smb + NH_L + aoff);
                mma_f16(c, Ah, W2F[kf]);
                mma_f16(c, Al, W2F[kf]);
            }
            int r0 = mt * 16 + (lane >> 2), r1 = r0 + 8;
            int cm = wid * 8 + (lane & 3) * 2;
            float ba = s_b2[cm], bb = s_b2[cm + 1];
            int gn0 = n0 + r0, gn1 = n0 + r1;
            if (gn0 < N) *(float2*)(outp + (size_t)gn0 * 64 + cm) = make_float2(c[0] + ba, c[1] + bb);
            if (gn1 < N) *(float2*)(outp + (size_t)gn1 * 64 + cm) = make_float2(c[2] + ba, c[3] + bb);
        }
        __syncthreads();
    }
}

// ---------------------------------------------------------------------------
extern "C" void kernel_launch(void* const* d_in, const int* in_sizes, int n_in,
                              void* d_out, int out_size) {
    const float* nf_gc  = (const float*)d_in[0];
    const float* nf_gs  = (const float*)d_in[1];
    const float* w_gc   = (const float*)d_in[2];
    const float* b_gc   = (const float*)d_in[3];
    const float* w_gs   = (const float*)d_in[4];
    const float* b_gs   = (const float*)d_in[5];
    const float* s2c_w1 = (const float*)d_in[6];
    const float* s2c_b1 = (const float*)d_in[7];
    const float* s2c_w2 = (const float*)d_in[8];
    const float* s2c_b2 = (const float*)d_in[9];
    const float* s2c_rw = (const float*)d_in[10];
    const float* s2c_rb = (const float*)d_in[11];
    const float* c2s_w1 = (const float*)d_in[12];
    const float* c2s_b1 = (const float*)d_in[13];
    const float* c2s_w2 = (const float*)d_in[14];
    const float* c2s_b2 = (const float*)d_in[15];
    const float* c2s_rw = (const float*)d_in[16];
    const float* c2s_rb = (const float*)d_in[17];
    const float* gc_w1  = (const float*)d_in[18];
    const float* gc_b1  = (const float*)d_in[19];
    const float* gc_w2  = (const float*)d_in[20];
    const float* gc_b2  = (const float*)d_in[21];
    const float* gs_w1  = (const float*)d_in[22];
    const float* gs_b1  = (const float*)d_in[23];
    const float* gs_w2  = (const float*)d_in[24];
    const float* gs_b2  = (const float*)d_in[25];
    const int* s2c_src  = (const int*)d_in[26];
    const int* s2c_dst  = (const int*)d_in[27];
    const int* c2s_src  = (const int*)d_in[28];
    const int* c2s_dst  = (const int*)d_in[29];

    const int FGC = in_sizes[2] / 64;
    const int FGS = in_sizes[4] / 64;
    const int NGC = in_sizes[0] / FGC;
    const int NGS = in_sizes[1] / FGS;
    const int E1 = in_sizes[26];
    const int E2 = in_sizes[28];

    float *gcx, *gsx, *rweff, *whp, *bhp;
    unsigned *aggc, *aggs;
    cudaGetSymbolAddress((void**)&gcx, g_gcx);
    cudaGetSymbolAddress((void**)&gsx, g_gsx);
    cudaGetSymbolAddress((void**)&aggc, g_aggc);
    cudaGetSymbolAddress((void**)&aggs, g_aggs);
    cudaGetSymbolAddress((void**)&rweff, g_rweff);
    cudaGetSymbolAddress((void**)&whp, g_wh);
    cudaGetSymbolAddress((void**)&bhp, g_bh);

    cudaFuncSetAttribute(edge_both_kernel, cudaFuncAttributeMaxDynamicSharedMemorySize, EX_SMEM);
    cudaFuncSetAttribute(node_mma_kernel, cudaFuncAttributeMaxDynamicSharedMemorySize, N_SMEM);

    // [0] init
    int totc = NGC * 320, tots = NGS * 320;
    init_all_kernel<<<(totc + tots + 255) / 256, 256>>>(aggc, aggs, totc, tots);
    // [1] embed
    embed_all_kernel<<<((NGC + NGS) * 64 + 255) / 256, 256>>>(
        nf_gc, w_gc, b_gc, gcx, NGC, FGC, nf_gs, w_gs, b_gs, gsx, NGS, FGS);
    // [2] rw_eff
    rweff_kernel<<<642, 64>>>(s2c_rw, s2c_w2, s2c_b2, c2s_rw, c2s_w2, c2s_b2, rweff);
    // [3] whfold (uses OUTPUT-MLP w1/b1 per node type)
    whfold_kernel<<<674, 64>>>(rweff, gc_w1, gc_b1, s2c_rb, gs_w1, gs_b1, c2s_rb, whp, bhp);
    // [4] edge both
    edge_both_kernel<<<608, 256, EX_SMEM>>>(
        gcx, gsx,
        s2c_src, s2c_dst, s2c_w1, s2c_w2, s2c_b1, s2c_b2, aggc, E1,
        c2s_src, c2s_dst, c2s_w1, c2s_w2, c2s_b1, c2s_b2, aggs, E2);
    // [5] node MMA (profiled slot)
    float* out = (float*)d_out;
    node_mma_kernel<<<608, 256, N_SMEM>>>(
        gcx, aggc, gc_w2, gc_b2, NGC,
        gsx, aggs, gs_w2, gs_b2, NGS, whp, bhp, out);
}

// round 14
// speedup vs baseline: 5.4773x; 1.1425x over previous
#include <cuda_runtime.h>
#include <cuda_fp16.h>
#include <cstdint>

#define NMAX 100000

__device__ float    g_gcx[NMAX * 64];
__device__ float    g_gsx[NMAX * 64];
__device__ unsigned g_aggc[NMAX * 320];
__device__ unsigned g_aggs[NMAX * 320];
__device__ float    g_wh[2][336 * 64];
__device__ float    g_bh[2][64];

__device__ __forceinline__ unsigned fkey(float f) {
    unsigned u = __float_as_uint(f);
    return (u & 0x80000000u) ? ~u : (u | 0x80000000u);
}
__device__ __forceinline__ float fdec(unsigned k) {
    unsigned u = (k & 0x80000000u) ? (k & 0x7FFFFFFFu) : ~k;
    return __uint_as_float(u);
}
__device__ __forceinline__ uint32_t smem_to_u32(const void* p) {
    uint32_t a;
    asm("{ .reg .u64 t; cvta.to.shared.u64 t, %1; cvt.u32.u64 %0, t; }" : "=r"(a) : "l"(p));
    return a;
}
__device__ __forceinline__ void ldsm_x4(uint32_t a[4], uint32_t addr) {
    asm volatile("ldmatrix.sync.aligned.m8n8.x4.shared.b16 {%0,%1,%2,%3}, [%4];"
        : "=r"(a[0]), "=r"(a[1]), "=r"(a[2]), "=r"(a[3]) : "r"(addr));
}
__device__ __forceinline__ void ldsm_x2(uint32_t b[2], uint32_t addr) {
    asm volatile("ldmatrix.sync.aligned.m8n8.x2.shared.b16 {%0,%1}, [%2];"
        : "=r"(b[0]), "=r"(b[1]) : "r"(addr));
}
__device__ __forceinline__ void mma_f16(float c[4], const uint32_t a[4], const uint32_t b[2]) {
    asm volatile("mma.sync.aligned.m16n8k16.row.col.f32.f16.f16.f32 "
        "{%0,%1,%2,%3}, {%4,%5,%6,%7}, {%8,%9}, {%0,%1,%2,%3};"
        : "+f"(c[0]), "+f"(c[1]), "+f"(c[2]), "+f"(c[3])
        : "r"(a[0]), "r"(a[1]), "r"(a[2]), "r"(a[3]), "r"(b[0]), "r"(b[1]));
}
__device__ __forceinline__ uint32_t packh(__half a, __half b) {
    return (uint32_t)__half_as_ushort(a) | ((uint32_t)__half_as_ushort(b) << 16);
}

// ---------------- [0] init (257 live cols) + embed, one launch --------------
__global__ void init_embed_kernel(
    unsigned* __restrict__ aggc, unsigned* __restrict__ aggs, int NC, int NS,
    const float* __restrict__ nfc, const float* __restrict__ wc,
    const float* __restrict__ bc, float* __restrict__ outc, int FC,
    const float* __restrict__ nfs, const float* __restrict__ ws,
    const float* __restrict__ bs, float* __restrict__ outs, int FS) {
    int idx = blockIdx.x * blockDim.x + threadIdx.x;
    const int initTot = (NC + NS) * 257;
    if (idx < initTot) {
        int node = idx / 257, col = idx - node * 257;
        unsigned val = (col >= 192 && col < 256) ? 0xFFFFFFFFu : 0u;
        if (node < NC) aggc[(size_t)node * 320 + col] = val;
        else aggs[(size_t)(node - NC) * 320 + col] = val;
        return;
    }
    idx -= initTot;
    if (idx < NC * 64) {
        int n = idx >> 6, h = idx & 63;
        const float* row = nfc + (size_t)n * FC;
        float acc = bc[h];
        for (int f = 0; f < FC; f++) acc = fmaf(__ldg(row + f), __ldg(wc + f * 64 + h), acc);
        outc[idx] = acc;
    } else if (idx < (NC + NS) * 64) {
        int j = idx - NC * 64;
        int n = j >> 6, h = j & 63;
        const float* row = nfs + (size_t)n * FS;
        float acc = bs[h];
        for (int f = 0; f < FS; f++) acc = fmaf(__ldg(row + f), __ldg(ws + f * 64 + h), acc);
        outs[j] = acc;
    }
}

// ---------------- [1] whfold_direct: Wh/bh straight from rw,w2,b2,w1,b1,rb --
// Wh rows: 0..63 x | 64..191 q | 192..255 max | 256..319 min | 320 ksum | 321..335 pad
__global__ void whfold_kernel(
    const float* __restrict__ rwa, const float* __restrict__ w2a, const float* __restrict__ b2a,
    const float* __restrict__ w1a, const float* __restrict__ b1a, const float* __restrict__ rba,
    const float* __restrict__ rwb, const float* __restrict__ w2b, const float* __restrict__ b2b,
    const float* __restrict__ w1b, const float* __restrict__ b1b, const float* __restrict__ rbb,
    float* __restrict__ whbase, float* __restrict__ bhbase) {
    const int r = blockIdx.x % 337;
    const int d = blockIdx.x / 337;
    const int j = threadIdx.x;  // 64 threads
    const float* rw = d ? rwb : rwa;
    const float* w2 = d ? w2b : w2a;
    const float* b2 = d ? b2b : b2a;
    const float* w1 = d ? w1b : w1a;
    const float* b1 = d ? b1b : b1a;
    const float* rb = d ? rbb : rba;
    float* wh = whbase + (size_t)d * 336 * 64;
    float* bh = bhbase + (size_t)d * 64;
    __shared__ float srow[64];

    if (r == 336) {
        float acc = __ldg(b1 + j);
        for (int t = 0; t < 64; t++)
            acc = fmaf(__ldg(rb + t), __ldg(w1 + (64 + t) * 64 + j), acc);
        bh[j] = acc;
        return;
    }
    if (r >= 321) { wh[r * 64 + j] = 0.f; return; }

    // srow[j] = rweff[r][j]
    float rv;
    if (r < 64) rv = __ldg(rw + r * 64 + j);
    else if (r < 192) {
        int k = r - 64;
        rv = 0.f;
        for (int s = 0; s < 64; s++)
            rv = fmaf(__ldg(w2 + k * 257 + 1 + s), __ldg(rw + (64 + s) * 64 + j), rv);
        for (int s = 0; s < 64; s++)
            rv = fmaf(__ldg(w2 + k * 257 + 193 + s), __ldg(rw + (256 + s) * 64 + j), rv);
    } else if (r < 320) rv = __ldg(rw + (r - 64) * 64 + j);
    else {
        rv = 0.f;
        for (int s = 0; s < 64; s++)
            rv = fmaf(__ldg(b2 + 1 + s), __ldg(rw + (64 + s) * 64 + j), rv);
        for (int s = 0; s < 64; s++)
            rv = fmaf(__ldg(b2 + 193 + s), __ldg(rw + (256 + s) * 64 + j), rv);
    }
    srow[j] = rv;
    __syncthreads();

    float acc = (r < 64) ? __ldg(w1 + r * 64 + j) : 0.f;
    for (int t = 0; t < 64; t++)
        acc = fmaf(srow[t], __ldg(w1 + (64 + t) * 64 + j), acc);
    wh[r * 64 + j] = acc;
}

// ================= [2] fused edge kernel, both directions (unchanged) =======
#define PADH 136
#define EX_XH 0
#define EX_XL 17408
#define EX_HH 34816
#define EX_W2T 52224
#define EX_WGT 87040
#define EX_B1 89216
#define EX_B2F 89728
#define EX_K  90240
#define EX_DST 90496
#define EX_BG 90752
#define EX_SMEM 90768
#define EDGE_HALF 304

__global__ void __launch_bounds__(256, 2) edge_both_kernel(
    const float* __restrict__ gcx, const float* __restrict__ gsx,
    const int* __restrict__ src1, const int* __restrict__ dst1,
    const float* __restrict__ w1a, const float* __restrict__ w2a,
    const float* __restrict__ b1a, const float* __restrict__ b2a,
    unsigned* __restrict__ agg1, int E1,
    const int* __restrict__ src2, const int* __restrict__ dst2,
    const float* __restrict__ w1b, const float* __restrict__ w2b,
    const float* __restrict__ b1b, const float* __restrict__ b2b,
    unsigned* __restrict__ agg2, int E2) {
    extern __shared__ char sm[];
    const uint32_t smb = smem_to_u32(sm);
    const int tid = threadIdx.x, lane = tid & 31, wid = tid >> 5;
    const bool d2 = blockIdx.x >= EDGE_HALF;
    const float* srcx = d2 ? gcx : gsx;
    const float* dstx = d2 ? gsx : gcx;
    const int* src = d2 ? src2 : src1;
    const int* dst = d2 ? dst2 : dst1;
    const float* w1 = d2 ? w1b : w1a;
    const float* w2 = d2 ? w2b : w2a;
    const float* b1 = d2 ? b1b : b1a;
    const float* b2 = d2 ? b2b : b2a;
    unsigned* agg = d2 ? agg2 : agg1;
    const int E = d2 ? E2 : E1;
    const int bid0 = blockIdx.x - (d2 ? EDGE_HALF : 0);

    float* s_b1  = (float*)(sm + EX_B1);
    float* s_b2f = (float*)(sm + EX_B2F);
    float* s_k   = (float*)(sm + EX_K);
    int*   s_dst = (int*)(sm + EX_DST);
    float* s_bg  = (float*)(sm + EX_BG);

    for (int idx = tid; idx < 128 * 128; idx += 256) {
        int n = idx & 127, k = idx >> 7;
        ((__half*)(sm + EX_W2T))[n * PADH + k] = __float2half_rn(__ldg(w2 + k * 257 + 65 + n));
    }
    for (int idx = tid; idx < 8 * PADH; idx += 256)
        ((__half*)(sm + EX_WGT))[idx] = __float2half_rn(0.f);
    if (tid < 128) {
        s_b1[tid] = __ldg(b1 + tid);
        s_b2f[tid] = __ldg(b2 + 65 + tid);
    }
    if (tid == 0) s_bg[0] = __ldg(b2);
    __syncthreads();
    if (tid < 128)
        ((__half*)(sm + EX_WGT))[tid] = __float2half_rn(__ldg(w2 + tid * 257));

    uint32_t B1h[2][8][2], B1l[2][8][2];
    __syncthreads();
    for (int idx = tid; idx < 128 * 128; idx += 256) {
        int k = idx >> 7, n = idx & 127;
        ((__half*)(sm + EX_XH))[n * PADH + k] = __float2half_rn(__ldg(w1 + idx));
    }
    __syncthreads();
    #pragma unroll
    for (int nf = 0; nf < 2; nf++)
        #pragma unroll
        for (int kf = 0; kf < 8; kf++) {
            uint32_t off = (uint32_t)((wid * 16 + nf * 8 + (lane & 7)) * PADH
                            + kf * 16 + (((lane >> 3) & 1) << 3)) * 2;
            ldsm_x2(B1h[nf][kf], smb + EX_XH + off);
        }
    __syncthreads();
    for (int idx = tid; idx < 128 * 128; idx += 256) {
        int k = idx >> 7, n = idx & 127;
        float w = __ldg(w1 + idx);
        __half h = __float2half_rn(w);
        ((__half*)(sm + EX_XH))[n * PADH + k] = __float2half_rn(w - __half2float(h));
    }
    __syncthreads();
    #pragma unroll
    for (int nf = 0; nf < 2; nf++)
        #pragma unroll
        for (int kf = 0; kf < 8; kf++) {
            uint32_t off = (uint32_t)((wid * 16 + nf * 8 + (lane & 7)) * PADH
                            + kf * 16 + (((lane >> 3) & 1) << 3)) * 2;
            ldsm_x2(B1l[nf][kf], smb + EX_XH + off);
        }

    const int eloc = tid >> 2, quad = tid & 3;
    const float bg = s_bg[0];
    const int ntiles = (E + 63) >> 6;
    for (int t = bid0; t < ntiles; t += EDGE_HALF) {
        const int tb = t * 64;
        __syncthreads();

        for (int idx = tid; idx < 2048; idx += 256) {
            int row = idx >> 5, q = idx & 31;
            int e = tb + row;
            int hf = q >> 4, qq = q & 15;
            const float4* rp;
            if (hf == 0) {
                int si = (e < E) ? __ldg(src + e) : 0;
                rp = (const float4*)(srcx + (size_t)si * 64);
            } else {
                int di = (e < E) ? __ldg(dst + e) : 0;
                rp = (const float4*)(dstx + (size_t)di * 64);
            }
            float4 v = __ldg(rp + qq);
            int col = hf * 64 + qq * 4;
            __half h0 = __float2half_rn(v.x), h1 = __float2half_rn(v.y);
            __half h2 = __float2half_rn(v.z), h3 = __float2half_rn(v.w);
            __half l0 = __float2half_rn(v.x - __half2float(h0));
            __half l1 = __float2half_rn(v.y - __half2float(h1));
            __half l2 = __float2half_rn(v.z - __half2float(h2));
            __half l3 = __float2half_rn(v.w - __half2float(h3));
            uint32_t off = (uint32_t)(row * PADH + col) * 2;
            *(uint32_t*)(sm + EX_XH + off) = packh(h0, h1);
            *(uint32_t*)(sm + EX_XH + off + 4) = packh(h2, h3);
            *(uint32_t*)(sm + EX_XL + off) = packh(l0, l1);
            *(uint32_t*)(sm + EX_XL + off + 4) = packh(l2, l3);
        }
        if (tid < 64) {
            int e = tb + tid;
            s_dst[tid] = (e < E) ? __ldg(dst + e) : 0;
        }
        __syncthreads();

        #pragma unroll
        for (int mt = 0; mt < 4; mt++) {
            float c[2][4] = {};
            #pragma unroll
            for (int kf = 0; kf < 8; kf++) {
                uint32_t Ah[4], Al[4];
                uint32_t aoff = (uint32_t)((mt * 16 + (lane & 15)) * PADH
                                 + kf * 16 + ((lane >> 4) << 3)) * 2;
                ldsm_x4(Ah, smb + EX_XH + aoff);
                ldsm_x4(Al, smb + EX_XL + aoff);
                #pragma unroll
                for (int nf = 0; nf < 2; nf++) {
                    mma_f16(c[nf], Ah, B1h[nf][kf]);
                    mma_f16(c[nf], Al, B1h[nf][kf]);
                    mma_f16(c[nf], Ah, B1l[nf][kf]);
                }
            }
            int r0 = mt * 16 + (lane >> 2), r1 = r0 + 8;
            #pragma unroll
            for (int nf = 0; nf < 2; nf++) {
                int cm = wid * 16 + nf * 8 + (lane & 3) * 2;
                float ba = s_b1[cm], bb = s_b1[cm + 1];
                __half a00 = __float2half_rn(fmaxf(c[nf][0] + ba, 0.f));
                __half a01 = __float2half_rn(fmaxf(c[nf][1] + bb, 0.f));
                __half a10 = __float2half_rn(fmaxf(c[nf][2] + ba, 0.f));
                __half a11 = __float2half_rn(fmaxf(c[nf][3] + bb, 0.f));
                *(uint32_t*)(sm + EX_HH + (uint32_t)(r0 * PADH + cm) * 2) = packh(a00, a01);
                *(uint32_t*)(sm + EX_HH + (uint32_t)(r1 * PADH + cm) * 2) = packh(a10, a11);
            }
        }
        __syncthreads();

        if (wid < 4) {
            const int mt = wid;
            float c[4] = {0.f, 0.f, 0.f, 0.f};
            #pragma unroll
            for (int kf = 0; kf < 8; kf++) {
                uint32_t Ah[4], Bgf[2];
                uint32_t aoff = (uint32_t)((mt * 16 + (lane & 15)) * PADH
                                 + kf * 16 + ((lane >> 4) << 3)) * 2;
                ldsm_x4(Ah, smb + EX_HH + aoff);
                uint32_t goff = (uint32_t)((lane & 7) * PADH
                                 + kf * 16 + (((lane >> 3) & 1) << 3)) * 2;
                ldsm_x2(Bgf, smb + EX_WGT + goff);
                mma_f16(c, Ah, Bgf);
            }
            if ((lane & 3) == 0) {
                int r0 = mt * 16 + (lane >> 2);
                s_k[r0]     = 1.f / (1.f + __expf(-(c[0] + bg)));
                s_k[r0 + 8] = 1.f / (1.f + __expf(-(c[2] + bg)));
            }
        }
        __syncthreads();

        {
            int e = tb + eloc;
            if (e < E) {
                float kk = s_k[eloc];
                int di = s_dst[eloc];
                float* qb = (float*)(agg + (size_t)di * 320) + quad * 32;
                uint32_t base = (uint32_t)(eloc * PADH + quad * 32) * 2;
                #pragma unroll
                for (int c4 = 0; c4 < 8; c4++) {
                    uint32_t u0 = *(uint32_t*)(sm + EX_HH + base + c4 * 8);
                    uint32_t u1 = *(uint32_t*)(sm + EX_HH + base + c4 * 8 + 4);
                    float2 f0 = __half22float2(*(__half2*)&u0);
                    float2 f1 = __half22float2(*(__half2*)&u1);
                    atomicAdd((float4*)(qb + c4 * 4),
                              make_float4(kk * f0.x, kk * f0.y, kk * f1.x, kk * f1.y));
                }
                if (quad == 0) atomicAdd((float*)(agg + (size_t)di * 320 + 256), kk);
            }
        }

        #pragma unroll
        for (int mt = 0; mt < 4; mt++) {
            float c[2][4] = {};
            #pragma unroll
            for (int kf = 0; kf < 8; kf++) {
                uint32_t Ah[4];
                uint32_t aoff = (uint32_t)((mt * 16 + (lane & 15)) * PADH
                                 + kf * 16 + ((lane >> 4) << 3)) * 2;
                ldsm_x4(Ah, smb + EX_HH + aoff);
                #pragma unroll
                for (int nf = 0; nf < 2; nf++) {
                    uint32_t Bf[2];
                    uint32_t boff = (uint32_t)((wid * 16 + nf * 8 + (lane & 7)) * PADH
                                     + kf * 16 + (((lane >> 3) & 1) << 3)) * 2;
                    ldsm_x2(Bf, smb + EX_W2T + boff);
                    mma_f16(c[nf], Ah, Bf);
                }
            }
            int r0 = mt * 16 + (lane >> 2), r1 = r0 + 8;
            bool v0 = tb + r0 < E, v1 = tb + r1 < E;
            float k0 = s_k[r0], k1 = s_k[r1];
            unsigned* row0 = agg + (size_t)s_dst[r0] * 320;
            unsigned* row1 = agg + (size_t)s_dst[r1] * 320;
            #pragma unroll
            for (int nf = 0; nf < 2; nf++) {
                int cm = wid * 16 + nf * 8 + (lane & 3) * 2;
                float ba = s_b2f[cm], bb = s_b2f[cm + 1];
                float v00 = (c[nf][0] + ba) * k0, v01 = (c[nf][1] + bb) * k0;
                float v10 = (c[nf][2] + ba) * k1, v11 = (c[nf][3] + bb) * k1;
                if (wid < 4) {
                    if (v0) { atomicMax(row0 + 128 + cm, fkey(v00)); atomicMax(row0 + 129 + cm, fkey(v01)); }
                    if (v1) { atomicMax(row1 + 128 + cm, fkey(v10)); atomicMax(row1 + 129 + cm, fkey(v11)); }
                } else {
                    if (v0) { atomicMin(row0 + 128 + cm, fkey(v00)); atomicMin(row0 + 129 + cm, fkey(v01)); }
                    if (v1) { atomicMin(row1 + 128 + cm, fkey(v10)); atomicMin(row1 + 129 + cm, fkey(v11)); }
                }
            }
        }
    }
}

// ================= [3] node MMA kernel (profiled slot) ======================
#define NPAD1 344
#define NPAD2 72
#define NZ_H 0
#define NZ_L 44032
#define NH_H 88064
#define NH_L 97280
#define NB_BH 106496
#define NB_B2 106752
#define N_SMEM 107008
#define NODE_HALF 304

__global__ void __launch_bounds__(256, 2) node_mma_kernel(
    const float* __restrict__ gcx, const unsigned* __restrict__ aggc,
    const float* __restrict__ w2a, const float* __restrict__ b2a, int NC,
    const float* __restrict__ gsx, const unsigned* __restrict__ aggs,
    const float* __restrict__ w2b, const float* __restrict__ b2b, int NS,
    const float* __restrict__ whbase, const float* __restrict__ bhbase,
    float* __restrict__ out) {
    extern __shared__ char sm[];
    const uint32_t smb = smem_to_u32(sm);
    const int tid = threadIdx.x, lane = tid & 31, wid = tid >> 5;
    const bool d2 = blockIdx.x >= NODE_HALF;
    const float* x = d2 ? gsx : gcx;
    const unsigned* agg = d2 ? aggs : aggc;
    const float* w2 = d2 ? w2b : w2a;
    const float* b2v = d2 ? b2b : b2a;
    const float* wh = whbase + (d2 ? (size_t)336 * 64 : 0);
    const float* bh = bhbase + (d2 ? 64 : 0);
    const int N = d2 ? NS : NC;
    float* outp = out + (d2 ? (size_t)NC * 64 : 0);
    const int bid0 = blockIdx.x - (d2 ? NODE_HALF : 0);

    float* s_bh = (float*)(sm + NB_BH);
    float* s_b2 = (float*)(sm + NB_B2);

    for (int idx = tid; idx < 64 * 344; idx += 256) {
        int n = idx / 344, k = idx - n * 344;
        float w = (k < 336) ? __ldg(wh + k * 64 + n) : 0.f;
        ((__half*)(sm + NZ_H))[n * NPAD1 + k] = __float2half_rn(w);
    }
    for (int idx = tid; idx < 64 * 72; idx += 256) {
        int n = idx / 72, k = idx - n * 72;
        float w = (k < 64) ? __ldg(w2 + k * 64 + n) : 0.f;
        ((__half*)(sm + NH_H))[n * NPAD2 + k] = __float2half_rn(w);
    }
    if (tid < 64) { s_bh[tid] = __ldg(bh + tid); s_b2[tid] = __ldg(b2v + tid); }
    __syncthreads();

    uint32_t BW[21][2], W2F[4][2];
    #pragma unroll
    for (int kf = 0; kf < 21; kf++) {
        uint32_t off = (uint32_t)((wid * 8 + (lane & 7)) * NPAD1
                        + kf * 16 + (((lane >> 3) & 1) << 3)) * 2;
        ldsm_x2(BW[kf], smb + NZ_H + off);
    }
    #pragma unroll
    for (int kf = 0; kf < 4; kf++) {
        uint32_t off = (uint32_t)((wid * 8 + (lane & 7)) * NPAD2
                        + kf * 16 + (((lane >> 3) & 1) << 3)) * 2;
        ldsm_x2(W2F[kf], smb + NH_H + off);
    }
    __syncthreads();

    // pre-zero pad cols 322..335 of z (hi+lo) once
    for (int idx = tid; idx < 64 * 7; idx += 256) {
        int row = idx / 7, pp = idx - row * 7;
        uint32_t off = (uint32_t)(row * NPAD1 + 322 + pp * 2) * 2;
        *(uint32_t*)(sm + NZ_H + off) = 0u;
        *(uint32_t*)(sm + NZ_L + off) = 0u;
    }

    const int ntiles = (N + 63) >> 6;
    for (int t = bid0; t < ntiles; t += NODE_HALF) {
        const int n0 = t * 64;
        __syncthreads();

        // z tile [64 x 321 (+pad to 322)], paired cols, fp16 hi/lo
        for (int idx = tid; idx < 64 * 161; idx += 256) {
            int row = idx / 161, p = idx - row * 161;
            int i = p * 2;
            float v0 = 0.f, v1 = 0.f;
            int gn = n0 + row;
            if (gn < N) {
                if (i < 64) {
                    float2 xv = *(const float2*)(x + (size_t)gn * 64 + i);
                    v0 = xv.x; v1 = xv.y;
                } else if (i < 320) {
                    int c = i - 64;
                    uint2 r2 = *(const uint2*)(agg + (size_t)gn * 320 + c);
                    if (c < 128) { v0 = __uint_as_float(r2.x); v1 = __uint_as_float(r2.y); }
                    else if (c < 192) {
                        v0 = r2.x ? fdec(r2.x) : 0.f;
                        v1 = r2.y ? fdec(r2.y) : 0.f;
                    } else {
                        v0 = (r2.x == 0xFFFFFFFFu) ? 0.f : fdec(r2.x);
                        v1 = (r2.y == 0xFFFFFFFFu) ? 0.f : fdec(r2.y);
                    }
                } else {  // i == 320 -> (ksum, 0)
                    v0 = __uint_as_float(__ldg(agg + (size_t)gn * 320 + 256));
                }
            }
            __half h0 = __float2half_rn(v0), h1 = __float2half_rn(v1);
            __half l0 = __float2half_rn(v0 - __half2float(h0));
            __half l1 = __float2half_rn(v1 - __half2float(h1));
            uint32_t off = (uint32_t)(row * NPAD1 + i) * 2;
            *(uint32_t*)(sm + NZ_H + off) = packh(h0, h1);
            *(uint32_t*)(sm + NZ_L + off) = packh(l0, l1);
        }
        __syncthreads();

        // GEMM1: h = relu(z@Wh + bh) -> HH/HL fp16
        #pragma unroll
        for (int mt = 0; mt < 4; mt++) {
            float c[4] = {0.f, 0.f, 0.f, 0.f};
            #pragma unroll
            for (int kf = 0; kf < 21; kf++) {
                uint32_t Ah[4], Al[4];
                uint32_t aoff = (uint32_t)((mt * 16 + (lane & 15)) * NPAD1
                                 + kf * 16 + ((lane >> 4) << 3)) * 2;
                ldsm_x4(Ah, smb + NZ_H + aoff);
                ldsm_x4(Al, smb + NZ_L + aoff);
                mma_f16(c, Ah, BW[kf]);
                mma_f16(c, Al, BW[kf]);
            }
            int r0 = mt * 16 + (lane >> 2), r1 = r0 + 8;
            int cm = wid * 8 + (lane & 3) * 2;
            float ba = s_bh[cm], bb = s_bh[cm + 1];
            float h00 = fmaxf(c[0] + ba, 0.f), h01 = fmaxf(c[1] + bb, 0.f);
            float h10 = fmaxf(c[2] + ba, 0.f), h11 = fmaxf(c[3] + bb, 0.f);
            __half a00 = __float2half_rn(h00), a01 = __float2half_rn(h01);
            __half a10 = __float2half_rn(h10), a11 = __float2half_rn(h11);
            __half q00 = __float2half_rn(h00 - __half2float(a00));
            __half q01 = __float2half_rn(h01 - __half2float(a01));
            __half q10 = __float2half_rn(h10 - __half2float(a10));
            __half q11 = __float2half_rn(h11 - __half2float(a11));
            *(uint32_t*)(sm + NH_H + (uint32_t)(r0 * NPAD2 + cm) * 2) = packh(a00, a01);
            *(uint32_t*)(sm + NH_L + (uint32_t)(r0 * NPAD2 + cm) * 2) = packh(q00, q01);
            *(uint32_t*)(sm + NH_H + (uint32_t)(r1 * NPAD2 + cm) * 2) = packh(a10, a11);
            *(uint32_t*)(sm + NH_L + (uint32_t)(r1 * NPAD2 + cm) * 2) = packh(q10, q11);
        }
        __syncthreads();

        // GEMM2: out = h@w2 + b2
        #pragma unroll
        for (int mt = 0; mt < 4; mt++) {
            float c[4] = {0.f, 0.f, 0.f, 0.f};
            #pragma unroll
            for (int kf = 0; kf < 4; kf++) {
                uint32_t Ah[4], Al[4];
                uint32_t aoff = (uint32_t)((mt * 16 + (lane & 15)) * NPAD2
                                 + kf * 16 + ((lane >> 4) << 3)) * 2;
                ldsm_x4(Ah, smb + NH_H + aoff);
                ldsm_x4(Al, smb + NH_L + aoff);
                mma_f16(c, Ah, W2F[kf]);
                mma_f16(c, Al, W2F[kf]);
            }
            int r0 = mt * 16 + (lane >> 2), r1 = r0 + 8;
            int cm = wid * 8 + (lane & 3) * 2;
            float ba = s_b2[cm], bb = s_b2[cm + 1];
            int gn0 = n0 + r0, gn1 = n0 + r1;
            if (gn0 < N) *(float2*)(outp + (size_t)gn0 * 64 + cm) = make_float2(c[0] + ba, c[1] + bb);
            if (gn1 < N) *(float2*)(outp + (size_t)gn1 * 64 + cm) = make_float2(c[2] + ba, c[3] + bb);
        }
    }
}

// ---------------------------------------------------------------------------
extern "C" void kernel_launch(void* const* d_in, const int* in_sizes, int n_in,
                              void* d_out, int out_size) {
    const float* nf_gc  = (const float*)d_in[0];
    const float* nf_gs  = (const float*)d_in[1];
    const float* w_gc   = (const float*)d_in[2];
    const float* b_gc   = (const float*)d_in[3];
    const float* w_gs   = (const float*)d_in[4];
    const float* b_gs   = (const float*)d_in[5];
    const float* s2c_w1 = (const float*)d_in[6];
    const float* s2c_b1 = (const float*)d_in[7];
    const float* s2c_w2 = (const float*)d_in[8];
    const float* s2c_b2 = (const float*)d_in[9];
    const float* s2c_rw = (const float*)d_in[10];
    const float* s2c_rb = (const float*)d_in[11];
    const float* c2s_w1 = (const float*)d_in[12];
    const float* c2s_b1 = (const float*)d_in[13];
    const float* c2s_w2 = (const float*)d_in[14];
    const float* c2s_b2 = (const float*)d_in[15];
    const float* c2s_rw = (const float*)d_in[16];
    const float* c2s_rb = (const float*)d_in[17];
    const float* gc_w1  = (const float*)d_in[18];
    const float* gc_b1  = (const float*)d_in[19];
    const float* gc_w2  = (const float*)d_in[20];
    const float* gc_b2  = (const float*)d_in[21];
    const float* gs_w1  = (const float*)d_in[22];
    const float* gs_b1  = (const float*)d_in[23];
    const float* gs_w2  = (const float*)d_in[24];
    const float* gs_b2  = (const float*)d_in[25];
    const int* s2c_src  = (const int*)d_in[26];
    const int* s2c_dst  = (const int*)d_in[27];
    const int* c2s_src  = (const int*)d_in[28];
    const int* c2s_dst  = (const int*)d_in[29];

    const int FGC = in_sizes[2] / 64;
    const int FGS = in_sizes[4] / 64;
    const int NGC = in_sizes[0] / FGC;
    const int NGS = in_sizes[1] / FGS;
    const int E1 = in_sizes[26];
    const int E2 = in_sizes[28];

    float *gcx, *gsx, *whp, *bhp;
    unsigned *aggc, *aggs;
    cudaGetSymbolAddress((void**)&gcx, g_gcx);
    cudaGetSymbolAddress((void**)&gsx, g_gsx);
    cudaGetSymbolAddress((void**)&aggc, g_aggc);
    cudaGetSymbolAddress((void**)&aggs, g_aggs);
    cudaGetSymbolAddress((void**)&whp, g_wh);
    cudaGetSymbolAddress((void**)&bhp, g_bh);

    cudaFuncSetAttribute(edge_both_kernel, cudaFuncAttributeMaxDynamicSharedMemorySize, EX_SMEM);
    cudaFuncSetAttribute(node_mma_kernel, cudaFuncAttributeMaxDynamicSharedMemorySize, N_SMEM);

    // [0] init (257 live cols) + embed, fused
    int total0 = (NGC + NGS) * 257 + (NGC + NGS) * 64;
    init_embed_kernel<<<(total0 + 255) / 256, 256>>>(
        aggc, aggs, NGC, NGS,
        nf_gc, w_gc, b_gc, gcx, FGC, nf_gs, w_gs, b_gs, gsx, FGS);
    // [1] whfold direct
    whfold_kernel<<<674, 64>>>(
        s2c_rw, s2c_w2, s2c_b2, gc_w1, gc_b1, s2c_rb,
        c2s_rw, c2s_w2, c2s_b2, gs_w1, gs_b1, c2s_rb, whp, bhp);
    // [2] edge both
    edge_both_kernel<<<608, 256, EX_SMEM>>>(
        gcx, gsx,
        s2c_src, s2c_dst, s2c_w1, s2c_w2, s2c_b1, s2c_b2, aggc, E1,
        c2s_src, c2s_dst, c2s_w1, c2s_w2, c2s_b1, c2s_b2, aggs, E2);
    // [3] node MMA (profiled slot)
    float* out = (float*)d_out;
    node_mma_kernel<<<608, 256, N_SMEM>>>(
        gcx, aggc, gc_w2, gc_b2, NGC,
        gsx, aggs, gs_w2, gs_b2, NGS, whp, bhp, out);
}

// round 15
// speedup vs baseline: 7.0705x; 1.2909x over previous
#include <cuda_runtime.h>
#include <cuda_fp16.h>
#include <cstdint>

#define NMAX 100000

__device__ float    g_gcx[NMAX * 64];
__device__ float    g_gsx[NMAX * 64];
__device__ unsigned g_aggc[NMAX * 320];
__device__ unsigned g_aggs[NMAX * 320];
__device__ float    g_wh[2][336 * 64];
__device__ float    g_bh[2][64];

__device__ __forceinline__ unsigned fkey(float f) {
    unsigned u = __float_as_uint(f);
    return (u & 0x80000000u) ? ~u : (u | 0x80000000u);
}
__device__ __forceinline__ float fdec(unsigned k) {
    unsigned u = (k & 0x80000000u) ? (k & 0x7FFFFFFFu) : ~k;
    return __uint_as_float(u);
}
__device__ __forceinline__ uint32_t smem_to_u32(const void* p) {
    uint32_t a;
    asm("{ .reg .u64 t; cvta.to.shared.u64 t, %1; cvt.u32.u64 %0, t; }" : "=r"(a) : "l"(p));
    return a;
}
__device__ __forceinline__ void ldsm_x4(uint32_t a[4], uint32_t addr) {
    asm volatile("ldmatrix.sync.aligned.m8n8.x4.shared.b16 {%0,%1,%2,%3}, [%4];"
        : "=r"(a[0]), "=r"(a[1]), "=r"(a[2]), "=r"(a[3]) : "r"(addr));
}
__device__ __forceinline__ void ldsm_x2(uint32_t b[2], uint32_t addr) {
    asm volatile("ldmatrix.sync.aligned.m8n8.x2.shared.b16 {%0,%1}, [%2];"
        : "=r"(b[0]), "=r"(b[1]) : "r"(addr));
}
__device__ __forceinline__ void mma_f16(float c[4], const uint32_t a[4], const uint32_t b[2]) {
    asm volatile("mma.sync.aligned.m16n8k16.row.col.f32.f16.f16.f32 "
        "{%0,%1,%2,%3}, {%4,%5,%6,%7}, {%8,%9}, {%0,%1,%2,%3};"
        : "+f"(c[0]), "+f"(c[1]), "+f"(c[2]), "+f"(c[3])
        : "r"(a[0]), "r"(a[1]), "r"(a[2]), "r"(a[3]), "r"(b[0]), "r"(b[1]));
}
__device__ __forceinline__ uint32_t packh(__half a, __half b) {
    return (uint32_t)__half_as_ushort(a) | ((uint32_t)__half_as_ushort(b) << 16);
}
// split-store a float pair as fp16 hi/lo u32s
__device__ __forceinline__ void st_pair(char* sm, uint32_t offH, uint32_t offL, float a, float b) {
    __half h0 = __float2half_rn(a), h1 = __float2half_rn(b);
    __half l0 = __float2half_rn(a - __half2float(h0));
    __half l1 = __float2half_rn(b - __half2float(h1));
    *(uint32_t*)(sm + offH) = packh(h0, h1);
    *(uint32_t*)(sm + offL) = packh(l0, l1);
}

// ---------------- [0] init (257 live cols) + embed, one launch --------------
__global__ void init_embed_kernel(
    unsigned* __restrict__ aggc, unsigned* __restrict__ aggs, int NC, int NS,
    const float* __restrict__ nfc, const float* __restrict__ wc,
    const float* __restrict__ bc, float* __restrict__ outc, int FC,
    const float* __restrict__ nfs, const float* __restrict__ ws,
    const float* __restrict__ bs, float* __restrict__ outs, int FS) {
    int idx = blockIdx.x * blockDim.x + threadIdx.x;
    const int initTot = (NC + NS) * 257;
    if (idx < initTot) {
        int node = idx / 257, col = idx - node * 257;
        unsigned val = (col >= 192 && col < 256) ? 0xFFFFFFFFu : 0u;
        if (node < NC) aggc[(size_t)node * 320 + col] = val;
        else aggs[(size_t)(node - NC) * 320 + col] = val;
        return;
    }
    idx -= initTot;
    if (idx < NC * 64) {
        int n = idx >> 6, h = idx & 63;
        const float* row = nfc + (size_t)n * FC;
        float acc = bc[h];
        for (int f = 0; f < FC; f++) acc = fmaf(__ldg(row + f), __ldg(wc + f * 64 + h), acc);
        outc[idx] = acc;
    } else if (idx < (NC + NS) * 64) {
        int j = idx - NC * 64;
        int n = j >> 6, h = j & 63;
        const float* row = nfs + (size_t)n * FS;
        float acc = bs[h];
        for (int f = 0; f < FS; f++) acc = fmaf(__ldg(row + f), __ldg(ws + f * 64 + h), acc);
        outs[j] = acc;
    }
}

// ---------------- [1] whfold_direct -----------------------------------------
__global__ void whfold_kernel(
    const float* __restrict__ rwa, const float* __restrict__ w2a, const float* __restrict__ b2a,
    const float* __restrict__ w1a, const float* __restrict__ b1a, const float* __restrict__ rba,
    const float* __restrict__ rwb, const float* __restrict__ w2b, const float* __restrict__ b2b,
    const float* __restrict__ w1b, const float* __restrict__ b1b, const float* __restrict__ rbb,
    float* __restrict__ whbase, float* __restrict__ bhbase) {
    const int r = blockIdx.x % 337;
    const int d = blockIdx.x / 337;
    const int j = threadIdx.x;
    const float* rw = d ? rwb : rwa;
    const float* w2 = d ? w2b : w2a;
    const float* b2 = d ? b2b : b2a;
    const float* w1 = d ? w1b : w1a;
    const float* b1 = d ? b1b : b1a;
    const float* rb = d ? rbb : rba;
    float* wh = whbase + (size_t)d * 336 * 64;
    float* bh = bhbase + (size_t)d * 64;
    __shared__ float srow[64];

    if (r == 336) {
        float acc = __ldg(b1 + j);
        for (int t = 0; t < 64; t++)
            acc = fmaf(__ldg(rb + t), __ldg(w1 + (64 + t) * 64 + j), acc);
        bh[j] = acc;
        return;
    }
    if (r >= 321) { wh[r * 64 + j] = 0.f; return; }

    float rv;
    if (r < 64) rv = __ldg(rw + r * 64 + j);
    else if (r < 192) {
        int k = r - 64;
        rv = 0.f;
        for (int s = 0; s < 64; s++)
            rv = fmaf(__ldg(w2 + k * 257 + 1 + s), __ldg(rw + (64 + s) * 64 + j), rv);
        for (int s = 0; s < 64; s++)
            rv = fmaf(__ldg(w2 + k * 257 + 193 + s), __ldg(rw + (256 + s) * 64 + j), rv);
    } else if (r < 320) rv = __ldg(rw + (r - 64) * 64 + j);
    else {
        rv = 0.f;
        for (int s = 0; s < 64; s++)
            rv = fmaf(__ldg(b2 + 1 + s), __ldg(rw + (64 + s) * 64 + j), rv);
        for (int s = 0; s < 64; s++)
            rv = fmaf(__ldg(b2 + 193 + s), __ldg(rw + (256 + s) * 64 + j), rv);
    }
    srow[j] = rv;
    __syncthreads();

    float acc = (r < 64) ? __ldg(w1 + r * 64 + j) : 0.f;
    for (int t = 0; t < 64; t++)
        acc = fmaf(srow[t], __ldg(w1 + (64 + t) * 64 + j), acc);
    wh[r * 64 + j] = acc;
}

// ================= [2] fused edge kernel (unchanged, verified) ==============
#define PADH 136
#define EX_XH 0
#define EX_XL 17408
#define EX_HH 34816
#define EX_W2T 52224
#define EX_WGT 87040
#define EX_B1 89216
#define EX_B2F 89728
#define EX_K  90240
#define EX_DST 90496
#define EX_BG 90752
#define EX_SMEM 90768
#define EDGE_HALF 304

__global__ void __launch_bounds__(256, 2) edge_both_kernel(
    const float* __restrict__ gcx, const float* __restrict__ gsx,
    const int* __restrict__ src1, const int* __restrict__ dst1,
    const float* __restrict__ w1a, const float* __restrict__ w2a,
    const float* __restrict__ b1a, const float* __restrict__ b2a,
    unsigned* __restrict__ agg1, int E1,
    const int* __restrict__ src2, const int* __restrict__ dst2,
    const float* __restrict__ w1b, const float* __restrict__ w2b,
    const float* __restrict__ b1b, const float* __restrict__ b2b,
    unsigned* __restrict__ agg2, int E2) {
    extern __shared__ char sm[];
    const uint32_t smb = smem_to_u32(sm);
    const int tid = threadIdx.x, lane = tid & 31, wid = tid >> 5;
    const bool d2 = blockIdx.x >= EDGE_HALF;
    const float* srcx = d2 ? gcx : gsx;
    const float* dstx = d2 ? gsx : gcx;
    const int* src = d2 ? src2 : src1;
    const int* dst = d2 ? dst2 : dst1;
    const float* w1 = d2 ? w1b : w1a;
    const float* w2 = d2 ? w2b : w2a;
    const float* b1 = d2 ? b1b : b1a;
    const float* b2 = d2 ? b2b : b2a;
    unsigned* agg = d2 ? agg2 : agg1;
    const int E = d2 ? E2 : E1;
    const int bid0 = blockIdx.x - (d2 ? EDGE_HALF : 0);

    float* s_b1  = (float*)(sm + EX_B1);
    float* s_b2f = (float*)(sm + EX_B2F);
    float* s_k   = (float*)(sm + EX_K);
    int*   s_dst = (int*)(sm + EX_DST);
    float* s_bg  = (float*)(sm + EX_BG);

    for (int idx = tid; idx < 128 * 128; idx += 256) {
        int n = idx & 127, k = idx >> 7;
        ((__half*)(sm + EX_W2T))[n * PADH + k] = __float2half_rn(__ldg(w2 + k * 257 + 65 + n));
    }
    for (int idx = tid; idx < 8 * PADH; idx += 256)
        ((__half*)(sm + EX_WGT))[idx] = __float2half_rn(0.f);
    if (tid < 128) {
        s_b1[tid] = __ldg(b1 + tid);
        s_b2f[tid] = __ldg(b2 + 65 + tid);
    }
    if (tid == 0) s_bg[0] = __ldg(b2);
    __syncthreads();
    if (tid < 128)
        ((__half*)(sm + EX_WGT))[tid] = __float2half_rn(__ldg(w2 + tid * 257));

    uint32_t B1h[2][8][2], B1l[2][8][2];
    __syncthreads();
    for (int idx = tid; idx < 128 * 128; idx += 256) {
        int k = idx >> 7, n = idx & 127;
        ((__half*)(sm + EX_XH))[n * PADH + k] = __float2half_rn(__ldg(w1 + idx));
    }
    __syncthreads();
    #pragma unroll
    for (int nf = 0; nf < 2; nf++)
        #pragma unroll
        for (int kf = 0; kf < 8; kf++) {
            uint32_t off = (uint32_t)((wid * 16 + nf * 8 + (lane & 7)) * PADH
                            + kf * 16 + (((lane >> 3) & 1) << 3)) * 2;
            ldsm_x2(B1h[nf][kf], smb + EX_XH + off);
        }
    __syncthreads();
    for (int idx = tid; idx < 128 * 128; idx += 256) {
        int k = idx >> 7, n = idx & 127;
        float w = __ldg(w1 + idx);
        __half h = __float2half_rn(w);
        ((__half*)(sm + EX_XH))[n * PADH + k] = __float2half_rn(w - __half2float(h));
    }
    __syncthreads();
    #pragma unroll
    for (int nf = 0; nf < 2; nf++)
        #pragma unroll
        for (int kf = 0; kf < 8; kf++) {
            uint32_t off = (uint32_t)((wid * 16 + nf * 8 + (lane & 7)) * PADH
                            + kf * 16 + (((lane >> 3) & 1) << 3)) * 2;
            ldsm_x2(B1l[nf][kf], smb + EX_XH + off);
        }

    const int eloc = tid >> 2, quad = tid & 3;
    const float bg = s_bg[0];
    const int ntiles = (E + 63) >> 6;
    for (int t = bid0; t < ntiles; t += EDGE_HALF) {
        const int tb = t * 64;
        __syncthreads();

        for (int idx = tid; idx < 2048; idx += 256) {
            int row = idx >> 5, q = idx & 31;
            int e = tb + row;
            int hf = q >> 4, qq = q & 15;
            const float4* rp;
            if (hf == 0) {
                int si = (e < E) ? __ldg(src + e) : 0;
                rp = (const float4*)(srcx + (size_t)si * 64);
            } else {
                int di = (e < E) ? __ldg(dst + e) : 0;
                rp = (const float4*)(dstx + (size_t)di * 64);
            }
            float4 v = __ldg(rp + qq);
            int col = hf * 64 + qq * 4;
            __half h0 = __float2half_rn(v.x), h1 = __float2half_rn(v.y);
            __half h2 = __float2half_rn(v.z), h3 = __float2half_rn(v.w);
            __half l0 = __float2half_rn(v.x - __half2float(h0));
            __half l1 = __float2half_rn(v.y - __half2float(h1));
            __half l2 = __float2half_rn(v.z - __half2float(h2));
            __half l3 = __float2half_rn(v.w - __half2float(h3));
            uint32_t off = (uint32_t)(row * PADH + col) * 2;
            *(uint32_t*)(sm + EX_XH + off) = packh(h0, h1);
            *(uint32_t*)(sm + EX_XH + off + 4) = packh(h2, h3);
            *(uint32_t*)(sm + EX_XL + off) = packh(l0, l1);
            *(uint32_t*)(sm + EX_XL + off + 4) = packh(l2, l3);
        }
        if (tid < 64) {
            int e = tb + tid;
            s_dst[tid] = (e < E) ? __ldg(dst + e) : 0;
        }
        __syncthreads();

        #pragma unroll
        for (int mt = 0; mt < 4; mt++) {
            float c[2][4] = {};
            #pragma unroll
            for (int kf = 0; kf < 8; kf++) {
                uint32_t Ah[4], Al[4];
                uint32_t aoff = (uint32_t)((mt * 16 + (lane & 15)) * PADH
                                 + kf * 16 + ((lane >> 4) << 3)) * 2;
                ldsm_x4(Ah, smb + EX_XH + aoff);
                ldsm_x4(Al, smb + EX_XL + aoff);
                #pragma unroll
                for (int nf = 0; nf < 2; nf++) {
                    mma_f16(c[nf], Ah, B1h[nf][kf]);
                    mma_f16(c[nf], Al, B1h[nf][kf]);
                    mma_f16(c[nf], Ah, B1l[nf][kf]);
                }
            }
            int r0 = mt * 16 + (lane >> 2), r1 = r0 + 8;
            #pragma unroll
            for (int nf = 0; nf < 2; nf++) {
                int cm = wid * 16 + nf * 8 + (lane & 3) * 2;
                float ba = s_b1[cm], bb = s_b1[cm + 1];
                __half a00 = __float2half_rn(fmaxf(c[nf][0] + ba, 0.f));
                __half a01 = __float2half_rn(fmaxf(c[nf][1] + bb, 0.f));
                __half a10 = __float2half_rn(fmaxf(c[nf][2] + ba, 0.f));
                __half a11 = __float2half_rn(fmaxf(c[nf][3] + bb, 0.f));
                *(uint32_t*)(sm + EX_HH + (uint32_t)(r0 * PADH + cm) * 2) = packh(a00, a01);
                *(uint32_t*)(sm + EX_HH + (uint32_t)(r1 * PADH + cm) * 2) = packh(a10, a11);
            }
        }
        __syncthreads();

        if (wid < 4) {
            const int mt = wid;
            float c[4] = {0.f, 0.f, 0.f, 0.f};
            #pragma unroll
            for (int kf = 0; kf < 8; kf++) {
                uint32_t Ah[4], Bgf[2];
                uint32_t aoff = (uint32_t)((mt * 16 + (lane & 15)) * PADH
                                 + kf * 16 + ((lane >> 4) << 3)) * 2;
                ldsm_x4(Ah, smb + EX_HH + aoff);
                uint32_t goff = (uint32_t)((lane & 7) * PADH
                                 + kf * 16 + (((lane >> 3) & 1) << 3)) * 2;
                ldsm_x2(Bgf, smb + EX_WGT + goff);
                mma_f16(c, Ah, Bgf);
            }
            if ((lane & 3) == 0) {
                int r0 = mt * 16 + (lane >> 2);
                s_k[r0]     = 1.f / (1.f + __expf(-(c[0] + bg)));
                s_k[r0 + 8] = 1.f / (1.f + __expf(-(c[2] + bg)));
            }
        }
        __syncthreads();

        {
            int e = tb + eloc;
            if (e < E) {
                float kk = s_k[eloc];
                int di = s_dst[eloc];
                float* qb = (float*)(agg + (size_t)di * 320) + quad * 32;
                uint32_t base = (uint32_t)(eloc * PADH + quad * 32) * 2;
                #pragma unroll
                for (int c4 = 0; c4 < 8; c4++) {
                    uint32_t u0 = *(uint32_t*)(sm + EX_HH + base + c4 * 8);
                    uint32_t u1 = *(uint32_t*)(sm + EX_HH + base + c4 * 8 + 4);
                    float2 f0 = __half22float2(*(__half2*)&u0);
                    float2 f1 = __half22float2(*(__half2*)&u1);
                    atomicAdd((float4*)(qb + c4 * 4),
                              make_float4(kk * f0.x, kk * f0.y, kk * f1.x, kk * f1.y));
                }
                if (quad == 0) atomicAdd((float*)(agg + (size_t)di * 320 + 256), kk);
            }
        }

        #pragma unroll
        for (int mt = 0; mt < 4; mt++) {
            float c[2][4] = {};
            #pragma unroll
            for (int kf = 0; kf < 8; kf++) {
                uint32_t Ah[4];
                uint32_t aoff = (uint32_t)((mt * 16 + (lane & 15)) * PADH
                                 + kf * 16 + ((lane >> 4) << 3)) * 2;
                ldsm_x4(Ah, smb + EX_HH + aoff);
                #pragma unroll
                for (int nf = 0; nf < 2; nf++) {
                    uint32_t Bf[2];
                    uint32_t boff = (uint32_t)((wid * 16 + nf * 8 + (lane & 7)) * PADH
                                     + kf * 16 + (((lane >> 3) & 1) << 3)) * 2;
                    ldsm_x2(Bf, smb + EX_W2T + boff);
                    mma_f16(c[nf], Ah, Bf);
                }
            }
            int r0 = mt * 16 + (lane >> 2), r1 = r0 + 8;
            bool v0 = tb + r0 < E, v1 = tb + r1 < E;
            float k0 = s_k[r0], k1 = s_k[r1];
            unsigned* row0 = agg + (size_t)s_dst[r0] * 320;
            unsigned* row1 = agg + (size_t)s_dst[r1] * 320;
            #pragma unroll
            for (int nf = 0; nf < 2; nf++) {
                int cm = wid * 16 + nf * 8 + (lane & 3) * 2;
                float ba = s_b2f[cm], bb = s_b2f[cm + 1];
                float v00 = (c[nf][0] + ba) * k0, v01 = (c[nf][1] + bb) * k0;
                float v10 = (c[nf][2] + ba) * k1, v11 = (c[nf][3] + bb) * k1;
                if (wid < 4) {
                    if (v0) { atomicMax(row0 + 128 + cm, fkey(v00)); atomicMax(row0 + 129 + cm, fkey(v01)); }
                    if (v1) { atomicMax(row1 + 128 + cm, fkey(v10)); atomicMax(row1 + 129 + cm, fkey(v11)); }
                } else {
                    if (v0) { atomicMin(row0 + 128 + cm, fkey(v00)); atomicMin(row0 + 129 + cm, fkey(v01)); }
                    if (v1) { atomicMin(row1 + 128 + cm, fkey(v10)); atomicMin(row1 + 129 + cm, fkey(v11)); }
                }
            }
        }
    }
}

// ================= [3] node MMA kernel (profiled slot) ======================
#define NPAD1 344
#define NPAD2 72
#define NZ_H 0
#define NZ_L 44032
#define NH_H 88064
#define NH_L 97280
#define NB_BH 106496
#define NB_B2 106752
#define N_SMEM 107008
#define NODE_HALF 304

__global__ void __launch_bounds__(256, 2) node_mma_kernel(
    const float* __restrict__ gcx, const unsigned* __restrict__ aggc,
    const float* __restrict__ w2a, const float* __restrict__ b2a, int NC,
    const float* __restrict__ gsx, const unsigned* __restrict__ aggs,
    const float* __restrict__ w2b, const float* __restrict__ b2b, int NS,
    const float* __restrict__ whbase, const float* __restrict__ bhbase,
    float* __restrict__ out) {
    extern __shared__ char sm[];
    const uint32_t smb = smem_to_u32(sm);
    const int tid = threadIdx.x, lane = tid & 31, wid = tid >> 5;
    const bool d2 = blockIdx.x >= NODE_HALF;
    const float* x = d2 ? gsx : gcx;
    const unsigned* agg = d2 ? aggs : aggc;
    const float* w2 = d2 ? w2b : w2a;
    const float* b2v = d2 ? b2b : b2a;
    const float* wh = whbase + (d2 ? (size_t)336 * 64 : 0);
    const float* bh = bhbase + (d2 ? 64 : 0);
    const int N = d2 ? NS : NC;
    float* outp = out + (d2 ? (size_t)NC * 64 : 0);
    const int bid0 = blockIdx.x - (d2 ? NODE_HALF : 0);

    float* s_bh = (float*)(sm + NB_BH);
    float* s_b2 = (float*)(sm + NB_B2);

    for (int idx = tid; idx < 64 * 344; idx += 256) {
        int n = idx / 344, k = idx - n * 344;
        float w = (k < 336) ? __ldg(wh + k * 64 + n) : 0.f;
        ((__half*)(sm + NZ_H))[n * NPAD1 + k] = __float2half_rn(w);
    }
    for (int idx = tid; idx < 64 * 72; idx += 256) {
        int n = idx / 72, k = idx - n * 72;
        float w = (k < 64) ? __ldg(w2 + k * 64 + n) : 0.f;
        ((__half*)(sm + NH_H))[n * NPAD2 + k] = __float2half_rn(w);
    }
    if (tid < 64) { s_bh[tid] = __ldg(bh + tid); s_b2[tid] = __ldg(b2v + tid); }
    __syncthreads();

    uint32_t BW[21][2], W2F[4][2];
    #pragma unroll
    for (int kf = 0; kf < 21; kf++) {
        uint32_t off = (uint32_t)((wid * 8 + (lane & 7)) * NPAD1
                        + kf * 16 + (((lane >> 3) & 1) << 3)) * 2;
        ldsm_x2(BW[kf], smb + NZ_H + off);
    }
    #pragma unroll
    for (int kf = 0; kf < 4; kf++) {
        uint32_t off = (uint32_t)((wid * 8 + (lane & 7)) * NPAD2
                        + kf * 16 + (((lane >> 3) & 1) << 3)) * 2;
        ldsm_x2(W2F[kf], smb + NH_H + off);
    }
    __syncthreads();

    // pre-zero pad cols 322..335 of z (hi+lo) once
    for (int idx = tid; idx < 64 * 7; idx += 256) {
        int row = idx / 7, pp = idx - row * 7;
        uint32_t off = (uint32_t)(row * NPAD1 + 322 + pp * 2) * 2;
        *(uint32_t*)(sm + NZ_H + off) = 0u;
        *(uint32_t*)(sm + NZ_L + off) = 0u;
    }

    const int ntiles = (N + 63) >> 6;
    for (int t = bid0; t < ntiles; t += NODE_HALF) {
        const int n0 = t * 64;
        __syncthreads();

        // z staging: warp handles rows wid*8..+7; per row 5 static-region
        // coalesced 8B loads issued up-front (branch-free decode per slot).
        {
            const int wr0 = wid * 8;
            const uint32_t ln2 = (uint32_t)(lane * 2);
            #pragma unroll 2
            for (int rr = 0; rr < 8; rr++) {
                const int row = wr0 + rr;
                const int gn = n0 + row;
                const bool ok = gn < N;
                const float* xr = x + (size_t)gn * 64;
                const unsigned* ar = agg + (size_t)gn * 320;
                float2 xv = ok ? __ldg((const float2*)(xr + ln2)) : make_float2(0.f, 0.f);
                uint2 q1 = ok ? __ldg((const uint2*)(ar + ln2)) : make_uint2(0u, 0u);
                uint2 q2 = ok ? __ldg((const uint2*)(ar + 64 + ln2)) : make_uint2(0u, 0u);
                uint2 mx = ok ? __ldg((const uint2*)(ar + 128 + ln2)) : make_uint2(0u, 0u);
                uint2 mn = ok ? __ldg((const uint2*)(ar + 192 + ln2))
                              : make_uint2(0xFFFFFFFFu, 0xFFFFFFFFu);
                float ks = (ok && lane == 0) ? __uint_as_float(__ldg(ar + 256)) : 0.f;

                float vmx0 = mx.x ? fdec(mx.x) : 0.f;
                float vmx1 = mx.y ? fdec(mx.y) : 0.f;
                float vmn0 = (mn.x == 0xFFFFFFFFu) ? 0.f : fdec(mn.x);
                float vmn1 = (mn.y == 0xFFFFFFFFu) ? 0.f : fdec(mn.y);

                uint32_t rb2 = (uint32_t)(row * NPAD1 + lane * 2) * 2;
                st_pair(sm, NZ_H + rb2,             NZ_L + rb2,             xv.x, xv.y);
                st_pair(sm, NZ_H + rb2 + 64 * 2,    NZ_L + rb2 + 64 * 2,
                        __uint_as_float(q1.x), __uint_as_float(q1.y));
                st_pair(sm, NZ_H + rb2 + 128 * 2,   NZ_L + rb2 + 128 * 2,
                        __uint_as_float(q2.x), __uint_as_float(q2.y));
                st_pair(sm, NZ_H + rb2 + 192 * 2,   NZ_L + rb2 + 192 * 2, vmx0, vmx1);
                st_pair(sm, NZ_H + rb2 + 256 * 2,   NZ_L + rb2 + 256 * 2, vmn0, vmn1);
                if (lane == 0) {
                    uint32_t kb = (uint32_t)(row * NPAD1 + 320) * 2;
                    st_pair(sm, NZ_H + kb, NZ_L + kb, ks, 0.f);
                }
            }
        }
        __syncthreads();

        // GEMM1: h = relu(z@Wh + bh) -> HH/HL fp16
        #pragma unroll
        for (int mt = 0; mt < 4; mt++) {
            float c[4] = {0.f, 0.f, 0.f, 0.f};
            #pragma unroll
            for (int kf = 0; kf < 21; kf++) {
                uint32_t Ah[4], Al[4];
                uint32_t aoff = (uint32_t)((mt * 16 + (lane & 15)) * NPAD1
                                 + kf * 16 + ((lane >> 4) << 3)) * 2;
                ldsm_x4(Ah, smb + NZ_H + aoff);
                ldsm_x4(Al, smb + NZ_L + aoff);
                mma_f16(c, Ah, BW[kf]);
                mma_f16(c, Al, BW[kf]);
            }
            int r0 = mt * 16 + (lane >> 2), r1 = r0 + 8;
            int cm = wid * 8 + (lane & 3) * 2;
            float ba = s_bh[cm], bb = s_bh[cm + 1];
            float h00 = fmaxf(c[0] + ba, 0.f), h01 = fmaxf(c[1] + bb, 0.f);
            float h10 = fmaxf(c[2] + ba, 0.f), h11 = fmaxf(c[3] + bb, 0.f);
            st_pair(sm, NH_H + (uint32_t)(r0 * NPAD2 + cm) * 2,
                        NH_L + (uint32_t)(r0 * NPAD2 + cm) * 2, h00, h01);
            st_pair(sm, NH_H + (uint32_t)(r1 * NPAD2 + cm) * 2,
                        NH_L + (uint32_t)(r1 * NPAD2 + cm) * 2, h10, h11);
        }
        __syncthreads();

        // GEMM2: out = h@w2 + b2
        #pragma unroll
        for (int mt = 0; mt < 4; mt++) {
            float c[4] = {0.f, 0.f, 0.f, 0.f};
            #pragma unroll
            for (int kf = 0; kf < 4; kf++) {
                uint32_t Ah[4], Al[4];
                uint32_t aoff = (uint32_t)((mt * 16 + (lane & 15)) * NPAD2
                                 + kf * 16 + ((lane >> 4) << 3)) * 2;
                ldsm_x4(Ah, smb + NH_H + aoff);
                ldsm_x4(Al, smb + NH_L + aoff);
                mma_f16(c, Ah, W2F[kf]);
                mma_f16(c, Al, W2F[kf]);
            }
            int r0 = mt * 16 + (lane >> 2), r1 = r0 + 8;
            int cm = wid * 8 + (lane & 3) * 2;
            float ba = s_b2[cm], bb = s_b2[cm + 1];
            int gn0 = n0 + r0, gn1 = n0 + r1;
            if (gn0 < N) *(float2*)(outp + (size_t)gn0 * 64 + cm) = make_float2(c[0] + ba, c[1] + bb);
            if (gn1 < N) *(float2*)(outp + (size_t)gn1 * 64 + cm) = make_float2(c[2] + ba, c[3] + bb);
        }
    }
}

// ---------------------------------------------------------------------------
extern "C" void kernel_launch(void* const* d_in, const int* in_sizes, int n_in,
                              void* d_out, int out_size) {
    const float* nf_gc  = (const float*)d_in[0];
    const float* nf_gs  = (const float*)d_in[1];
    const float* w_gc   = (const float*)d_in[2];
    const float* b_gc   = (const float*)d_in[3];
    const float* w_gs   = (const float*)d_in[4];
    const float* b_gs   = (const float*)d_in[5];
    const float* s2c_w1 = (const float*)d_in[6];
    const float* s2c_b1 = (const float*)d_in[7];
    const float* s2c_w2 = (const float*)d_in[8];
    const float* s2c_b2 = (const float*)d_in[9];
    const float* s2c_rw = (const float*)d_in[10];
    const float* s2c_rb = (const float*)d_in[11];
    const float* c2s_w1 = (const float*)d_in[12];
    const float* c2s_b1 = (const float*)d_in[13];
    const float* c2s_w2 = (const float*)d_in[14];
    const float* c2s_b2 = (const float*)d_in[15];
    const float* c2s_rw = (const float*)d_in[16];
    const float* c2s_rb = (const float*)d_in[17];
    const float* gc_w1  = (const float*)d_in[18];
    const float* gc_b1  = (const float*)d_in[19];
    const float* gc_w2  = (const float*)d_in[20];
    const float* gc_b2  = (const float*)d_in[21];
    const float* gs_w1  = (const float*)d_in[22];
    const float* gs_b1  = (const float*)d_in[23];
    const float* gs_w2  = (const float*)d_in[24];
    const float* gs_b2  = (const float*)d_in[25];
    const int* s2c_src  = (const int*)d_in[26];
    const int* s2c_dst  = (const int*)d_in[27];
    const int* c2s_src  = (const int*)d_in[28];
    const int* c2s_dst  = (const int*)d_in[29];

    const int FGC = in_sizes[2] / 64;
    const int FGS = in_sizes[4] / 64;
    const int NGC = in_sizes[0] / FGC;
    const int NGS = in_sizes[1] / FGS;
    const int E1 = in_sizes[26];
    const int E2 = in_sizes[28];

    float *gcx, *gsx, *whp, *bhp;
    unsigned *aggc, *aggs;
    cudaGetSymbolAddress((void**)&gcx, g_gcx);
    cudaGetSymbolAddress((void**)&gsx, g_gsx);
    cudaGetSymbolAddress((void**)&aggc, g_aggc);
    cudaGetSymbolAddress((void**)&aggs, g_aggs);
    cudaGetSymbolAddress((void**)&whp, g_wh);
    cudaGetSymbolAddress((void**)&bhp, g_bh);

    cudaFuncSetAttribute(edge_both_kernel, cudaFuncAttributeMaxDynamicSharedMemorySize, EX_SMEM);
    cudaFuncSetAttribute(node_mma_kernel, cudaFuncAttributeMaxDynamicSharedMemorySize, N_SMEM);

    // [0] init + embed
    int total0 = (NGC + NGS) * 257 + (NGC + NGS) * 64;
    init_embed_kernel<<<(total0 + 255) / 256, 256>>>(
        aggc, aggs, NGC, NGS,
        nf_gc, w_gc, b_gc, gcx, FGC, nf_gs, w_gs, b_gs, gsx, FGS);
    // [1] whfold
    whfold_kernel<<<674, 64>>>(
        s2c_rw, s2c_w2, s2c_b2, gc_w1, gc_b1, s2c_rb,
        c2s_rw, c2s_w2, c2s_b2, gs_w1, gs_b1, c2s_rb, whp, bhp);
    // [2] edge both
    edge_both_kernel<<<608, 256, EX_SMEM>>>(
        gcx, gsx,
        s2c_src, s2c_dst, s2c_w1, s2c_w2, s2c_b1, s2c_b2, aggc, E1,
        c2s_src, c2s_dst, c2s_w1, c2s_w2, c2s_b1, c2s_b2, aggs, E2);
    // [3] node MMA (profiled slot)
    float* out = (float*)d_out;
    node_mma_kernel<<<608, 256, N_SMEM>>>(
        gcx, aggc, gc_w2, gc_b2, NGC,
        gsx, aggs, gs_w2, gs_b2, NGS, whp, bhp, out);
}

// round 16
// speedup vs baseline: 7.2728x; 1.0286x over previous
#include <cuda_runtime.h>
#include <cuda_fp16.h>
#include <cstdint>

#define NMAX 100000

__device__ float    g_gcx[NMAX * 64];
__device__ float    g_gsx[NMAX * 64];
__device__ unsigned g_aggc[NMAX * 320];
__device__ unsigned g_aggs[NMAX * 320];
__device__ float    g_wh[2][336 * 64];
__device__ float    g_bh[2][64];

__device__ __forceinline__ unsigned fkey(float f) {
    unsigned u = __float_as_uint(f);
    return (u & 0x80000000u) ? ~u : (u | 0x80000000u);
}
__device__ __forceinline__ float fdec(unsigned k) {
    unsigned u = (k & 0x80000000u) ? (k & 0x7FFFFFFFu) : ~k;
    return __uint_as_float(u);
}
__device__ __forceinline__ uint32_t smem_to_u32(const void* p) {
    uint32_t a;
    asm("{ .reg .u64 t; cvta.to.shared.u64 t, %1; cvt.u32.u64 %0, t; }" : "=r"(a) : "l"(p));
    return a;
}
__device__ __forceinline__ void ldsm_x4(uint32_t a[4], uint32_t addr) {
    asm volatile("ldmatrix.sync.aligned.m8n8.x4.shared.b16 {%0,%1,%2,%3}, [%4];"
        : "=r"(a[0]), "=r"(a[1]), "=r"(a[2]), "=r"(a[3]) : "r"(addr));
}
__device__ __forceinline__ void ldsm_x2(uint32_t b[2], uint32_t addr) {
    asm volatile("ldmatrix.sync.aligned.m8n8.x2.shared.b16 {%0,%1}, [%2];"
        : "=r"(b[0]), "=r"(b[1]) : "r"(addr));
}
__device__ __forceinline__ void mma_f16(float c[4], const uint32_t a[4], const uint32_t b[2]) {
    asm volatile("mma.sync.aligned.m16n8k16.row.col.f32.f16.f16.f32 "
        "{%0,%1,%2,%3}, {%4,%5,%6,%7}, {%8,%9}, {%0,%1,%2,%3};"
        : "+f"(c[0]), "+f"(c[1]), "+f"(c[2]), "+f"(c[3])
        : "r"(a[0]), "r"(a[1]), "r"(a[2]), "r"(a[3]), "r"(b[0]), "r"(b[1]));
}
__device__ __forceinline__ uint32_t packh(__half a, __half b) {
    return (uint32_t)__half_as_ushort(a) | ((uint32_t)__half_as_ushort(b) << 16);
}
__device__ __forceinline__ void st_pair(char* sm, uint32_t offH, uint32_t offL, float a, float b) {
    __half h0 = __float2half_rn(a), h1 = __float2half_rn(b);
    __half l0 = __float2half_rn(a - __half2float(h0));
    __half l1 = __float2half_rn(b - __half2float(h1));
    *(uint32_t*)(sm + offH) = packh(h0, h1);
    *(uint32_t*)(sm + offL) = packh(l0, l1);
}

// ---------------- [0] init (257 live cols) + embed ----------------
__global__ void init_embed_kernel(
    unsigned* __restrict__ aggc, unsigned* __restrict__ aggs, int NC, int NS,
    const float* __restrict__ nfc, const float* __restrict__ wc,
    const float* __restrict__ bc, float* __restrict__ outc, int FC,
    const float* __restrict__ nfs, const float* __restrict__ ws,
    const float* __restrict__ bs, float* __restrict__ outs, int FS) {
    int idx = blockIdx.x * blockDim.x + threadIdx.x;
    const int initTot = (NC + NS) * 257;
    if (idx < initTot) {
        int node = idx / 257, col = idx - node * 257;
        unsigned val = (col >= 192 && col < 256) ? 0xFFFFFFFFu : 0u;
        if (node < NC) aggc[(size_t)node * 320 + col] = val;
        else aggs[(size_t)(node - NC) * 320 + col] = val;
        return;
    }
    idx -= initTot;
    if (idx < NC * 64) {
        int n = idx >> 6, h = idx & 63;
        const float* row = nfc + (size_t)n * FC;
        float acc = bc[h];
        for (int f = 0; f < FC; f++) acc = fmaf(__ldg(row + f), __ldg(wc + f * 64 + h), acc);
        outc[idx] = acc;
    } else if (idx < (NC + NS) * 64) {
        int j = idx - NC * 64;
        int n = j >> 6, h = j & 63;
        const float* row = nfs + (size_t)n * FS;
        float acc = bs[h];
        for (int f = 0; f < FS; f++) acc = fmaf(__ldg(row + f), __ldg(ws + f * 64 + h), acc);
        outs[j] = acc;
    }
}

// ---------------- [1] whfold_direct ----------------
__global__ void whfold_kernel(
    const float* __restrict__ rwa, const float* __restrict__ w2a, const float* __restrict__ b2a,
    const float* __restrict__ w1a, const float* __restrict__ b1a, const float* __restrict__ rba,
    const float* __restrict__ rwb, const float* __restrict__ w2b, const float* __restrict__ b2b,
    const float* __restrict__ w1b, const float* __restrict__ b1b, const float* __restrict__ rbb,
    float* __restrict__ whbase, float* __restrict__ bhbase) {
    const int r = blockIdx.x % 337;
    const int d = blockIdx.x / 337;
    const int j = threadIdx.x;
    const float* rw = d ? rwb : rwa;
    const float* w2 = d ? w2b : w2a;
    const float* b2 = d ? b2b : b2a;
    const float* w1 = d ? w1b : w1a;
    const float* b1 = d ? b1b : b1a;
    const float* rb = d ? rbb : rba;
    float* wh = whbase + (size_t)d * 336 * 64;
    float* bh = bhbase + (size_t)d * 64;
    __shared__ float srow[64];

    if (r == 336) {
        float acc = __ldg(b1 + j);
        for (int t = 0; t < 64; t++)
            acc = fmaf(__ldg(rb + t), __ldg(w1 + (64 + t) * 64 + j), acc);
        bh[j] = acc;
        return;
    }
    if (r >= 321) { wh[r * 64 + j] = 0.f; return; }

    float rv;
    if (r < 64) rv = __ldg(rw + r * 64 + j);
    else if (r < 192) {
        int k = r - 64;
        rv = 0.f;
        for (int s = 0; s < 64; s++)
            rv = fmaf(__ldg(w2 + k * 257 + 1 + s), __ldg(rw + (64 + s) * 64 + j), rv);
        for (int s = 0; s < 64; s++)
            rv = fmaf(__ldg(w2 + k * 257 + 193 + s), __ldg(rw + (256 + s) * 64 + j), rv);
    } else if (r < 320) rv = __ldg(rw + (r - 64) * 64 + j);
    else {
        rv = 0.f;
        for (int s = 0; s < 64; s++)
            rv = fmaf(__ldg(b2 + 1 + s), __ldg(rw + (64 + s) * 64 + j), rv);
        for (int s = 0; s < 64; s++)
            rv = fmaf(__ldg(b2 + 193 + s), __ldg(rw + (256 + s) * 64 + j), rv);
    }
    srow[j] = rv;
    __syncthreads();

    float acc = (r < 64) ? __ldg(w1 + r * 64 + j) : 0.f;
    for (int t = 0; t < 64; t++)
        acc = fmaf(srow[t], __ldg(w1 + (64 + t) * 64 + j), acc);
    wh[r * 64 + j] = acc;
}

// ================= [2] fused edge kernel: 2-term l1, hoisted l2 B ===========
#define PADH 136
#define EX_XH 0
#define EX_XL 17408
#define EX_HH 34816
#define EX_W2T 52224
#define EX_WGT 87040
#define EX_B1 89216
#define EX_B2F 89728
#define EX_K  90240
#define EX_DST 90496
#define EX_BG 90752
#define EX_SMEM 90768
#define EDGE_HALF 304

__global__ void __launch_bounds__(256, 2) edge_both_kernel(
    const float* __restrict__ gcx, const float* __restrict__ gsx,
    const int* __restrict__ src1, const int* __restrict__ dst1,
    const float* __restrict__ w1a, const float* __restrict__ w2a,
    const float* __restrict__ b1a, const float* __restrict__ b2a,
    unsigned* __restrict__ agg1, int E1,
    const int* __restrict__ src2, const int* __restrict__ dst2,
    const float* __restrict__ w1b, const float* __restrict__ w2b,
    const float* __restrict__ b1b, const float* __restrict__ b2b,
    unsigned* __restrict__ agg2, int E2) {
    extern __shared__ char sm[];
    const uint32_t smb = smem_to_u32(sm);
    const int tid = threadIdx.x, lane = tid & 31, wid = tid >> 5;
    const bool d2 = blockIdx.x >= EDGE_HALF;
    const float* srcx = d2 ? gcx : gsx;
    const float* dstx = d2 ? gsx : gcx;
    const int* src = d2 ? src2 : src1;
    const int* dst = d2 ? dst2 : dst1;
    const float* w1 = d2 ? w1b : w1a;
    const float* w2 = d2 ? w2b : w2a;
    const float* b1 = d2 ? b1b : b1a;
    const float* b2 = d2 ? b2b : b2a;
    unsigned* agg = d2 ? agg2 : agg1;
    const int E = d2 ? E2 : E1;
    const int bid0 = blockIdx.x - (d2 ? EDGE_HALF : 0);

    float* s_b1  = (float*)(sm + EX_B1);
    float* s_b2f = (float*)(sm + EX_B2F);
    float* s_k   = (float*)(sm + EX_K);
    int*   s_dst = (int*)(sm + EX_DST);
    float* s_bg  = (float*)(sm + EX_BG);

    // stage W2 max/min tile (persistent) + wg tile
    for (int idx = tid; idx < 128 * 128; idx += 256) {
        int n = idx & 127, k = idx >> 7;
        ((__half*)(sm + EX_W2T))[n * PADH + k] = __float2half_rn(__ldg(w2 + k * 257 + 65 + n));
    }
    for (int idx = tid; idx < 8 * PADH; idx += 256)
        ((__half*)(sm + EX_WGT))[idx] = __float2half_rn(0.f);
    if (tid < 128) {
        s_b1[tid] = __ldg(b1 + tid);
        s_b2f[tid] = __ldg(b2 + 65 + tid);
    }
    if (tid == 0) s_bg[0] = __ldg(b2);
    __syncthreads();
    if (tid < 128)
        ((__half*)(sm + EX_WGT))[tid] = __float2half_rn(__ldg(w2 + tid * 257));

    // stage w1-hi through XH region, hoist B1h (single-fp16 w1)
    uint32_t B1h[2][8][2], B2w[2][8][2];
    __syncthreads();
    for (int idx = tid; idx < 128 * 128; idx += 256) {
        int k = idx >> 7, n = idx & 127;
        ((__half*)(sm + EX_XH))[n * PADH + k] = __float2half_rn(__ldg(w1 + idx));
    }
    __syncthreads();
    #pragma unroll
    for (int nf = 0; nf < 2; nf++)
        #pragma unroll
        for (int kf = 0; kf < 8; kf++) {
            uint32_t off = (uint32_t)((wid * 16 + nf * 8 + (lane & 7)) * PADH
                            + kf * 16 + (((lane >> 3) & 1) << 3)) * 2;
            ldsm_x2(B1h[nf][kf], smb + EX_XH + off);
            uint32_t boff = (uint32_t)((wid * 16 + nf * 8 + (lane & 7)) * PADH
                             + kf * 16 + (((lane >> 3) & 1) << 3)) * 2;
            ldsm_x2(B2w[nf][kf], smb + EX_W2T + boff);
        }

    const int eloc = tid >> 2, quad = tid & 3;
    const float bg = s_bg[0];
    const int ntiles = (E + 63) >> 6;
    for (int t = bid0; t < ntiles; t += EDGE_HALF) {
        const int tb = t * 64;
        __syncthreads();

        // gather 64 edges: xe=[src|dst] fp16 hi/lo -> XH/XL
        for (int idx = tid; idx < 2048; idx += 256) {
            int row = idx >> 5, q = idx & 31;
            int e = tb + row;
            int hf = q >> 4, qq = q & 15;
            const float4* rp;
            if (hf == 0) {
                int si = (e < E) ? __ldg(src + e) : 0;
                rp = (const float4*)(srcx + (size_t)si * 64);
            } else {
                int di = (e < E) ? __ldg(dst + e) : 0;
                rp = (const float4*)(dstx + (size_t)di * 64);
            }
            float4 v = __ldg(rp + qq);
            int col = hf * 64 + qq * 4;
            uint32_t off = (uint32_t)(row * PADH + col) * 2;
            st_pair(sm, EX_XH + off, EX_XL + off, v.x, v.y);
            st_pair(sm, EX_XH + off + 4, EX_XL + off + 4, v.z, v.w);
        }
        if (tid < 64) {
            int e = tb + tid;
            s_dst[tid] = (e < E) ? __ldg(dst + e) : 0;
        }
        __syncthreads();

        // l1 MMA (2-term): h = relu(xe@w1+b1) -> HH fp16
        #pragma unroll
        for (int mt = 0; mt < 4; mt++) {
            float c[2][4] = {};
            #pragma unroll
            for (int kf = 0; kf < 8; kf++) {
                uint32_t Ah[4], Al[4];
                uint32_t aoff = (uint32_t)((mt * 16 + (lane & 15)) * PADH
                                 + kf * 16 + ((lane >> 4) << 3)) * 2;
                ldsm_x4(Ah, smb + EX_XH + aoff);
                ldsm_x4(Al, smb + EX_XL + aoff);
                #pragma unroll
                for (int nf = 0; nf < 2; nf++) {
                    mma_f16(c[nf], Ah, B1h[nf][kf]);
                    mma_f16(c[nf], Al, B1h[nf][kf]);
                }
            }
            int r0 = mt * 16 + (lane >> 2), r1 = r0 + 8;
            #pragma unroll
            for (int nf = 0; nf < 2; nf++) {
                int cm = wid * 16 + nf * 8 + (lane & 3) * 2;
                float ba = s_b1[cm], bb = s_b1[cm + 1];
                __half a00 = __float2half_rn(fmaxf(c[nf][0] + ba, 0.f));
                __half a01 = __float2half_rn(fmaxf(c[nf][1] + bb, 0.f));
                __half a10 = __float2half_rn(fmaxf(c[nf][2] + ba, 0.f));
                __half a11 = __float2half_rn(fmaxf(c[nf][3] + bb, 0.f));
                *(uint32_t*)(sm + EX_HH + (uint32_t)(r0 * PADH + cm) * 2) = packh(a00, a01);
                *(uint32_t*)(sm + EX_HH + (uint32_t)(r1 * PADH + cm) * 2) = packh(a10, a11);
            }
        }
        __syncthreads();

        // gate via MMA (warps 0-3)
        if (wid < 4) {
            const int mt = wid;
            float c[4] = {0.f, 0.f, 0.f, 0.f};
            #pragma unroll
            for (int kf = 0; kf < 8; kf++) {
                uint32_t Ah[4], Bgf[2];
                uint32_t aoff = (uint32_t)((mt * 16 + (lane & 15)) * PADH
                                 + kf * 16 + ((lane >> 4) << 3)) * 2;
                ldsm_x4(Ah, smb + EX_HH + aoff);
                uint32_t goff = (uint32_t)((lane & 7) * PADH
                                 + kf * 16 + (((lane >> 3) & 1) << 3)) * 2;
                ldsm_x2(Bgf, smb + EX_WGT + goff);
                mma_f16(c, Ah, Bgf);
            }
            if ((lane & 3) == 0) {
                int r0 = mt * 16 + (lane >> 2);
                s_k[r0]     = 1.f / (1.f + __expf(-(c[0] + bg)));
                s_k[r0 + 8] = 1.f / (1.f + __expf(-(c[2] + bg)));
            }
        }
        __syncthreads();

        // q += k*h; ksum += k
        {
            int e = tb + eloc;
            if (e < E) {
                float kk = s_k[eloc];
                int di = s_dst[eloc];
                float* qb = (float*)(agg + (size_t)di * 320) + quad * 32;
                uint32_t base = (uint32_t)(eloc * PADH + quad * 32) * 2;
                #pragma unroll
                for (int c4 = 0; c4 < 8; c4++) {
                    uint32_t u0 = *(uint32_t*)(sm + EX_HH + base + c4 * 8);
                    uint32_t u1 = *(uint32_t*)(sm + EX_HH + base + c4 * 8 + 4);
                    float2 f0 = __half22float2(*(__half2*)&u0);
                    float2 f1 = __half22float2(*(__half2*)&u1);
                    atomicAdd((float4*)(qb + c4 * 4),
                              make_float4(kk * f0.x, kk * f0.y, kk * f1.x, kk * f1.y));
                }
                if (quad == 0) atomicAdd((float*)(agg + (size_t)di * 320 + 256), kk);
            }
        }

        // l2 MMA (hoisted B): f2|f3 -> atomicMax/Min
        #pragma unroll
        for (int mt = 0; mt < 4; mt++) {
            float c[2][4] = {};
            #pragma unroll
            for (int kf = 0; kf < 8; kf++) {
                uint32_t Ah[4];
                uint32_t aoff = (uint32_t)((mt * 16 + (lane & 15)) * PADH
                                 + kf * 16 + ((lane >> 4) << 3)) * 2;
                ldsm_x4(Ah, smb + EX_HH + aoff);
                #pragma unroll
                for (int nf = 0; nf < 2; nf++)
                    mma_f16(c[nf], Ah, B2w[nf][kf]);
            }
            int r0 = mt * 16 + (lane >> 2), r1 = r0 + 8;
            bool v0 = tb + r0 < E, v1 = tb + r1 < E;
            float k0 = s_k[r0], k1 = s_k[r1];
            unsigned* row0 = agg + (size_t)s_dst[r0] * 320;
            unsigned* row1 = agg + (size_t)s_dst[r1] * 320;
            #pragma unroll
            for (int nf = 0; nf < 2; nf++) {
                int cm = wid * 16 + nf * 8 + (lane & 3) * 2;
                float ba = s_b2f[cm], bb = s_b2f[cm + 1];
                float v00 = (c[nf][0] + ba) * k0, v01 = (c[nf][1] + bb) * k0;
                float v10 = (c[nf][2] + ba) * k1, v11 = (c[nf][3] + bb) * k1;
                if (wid < 4) {
                    if (v0) { atomicMax(row0 + 128 + cm, fkey(v00)); atomicMax(row0 + 129 + cm, fkey(v01)); }
                    if (v1) { atomicMax(row1 + 128 + cm, fkey(v10)); atomicMax(row1 + 129 + cm, fkey(v11)); }
                } else {
                    if (v0) { atomicMin(row0 + 128 + cm, fkey(v00)); atomicMin(row0 + 129 + cm, fkey(v01)); }
                    if (v1) { atomicMin(row1 + 128 + cm, fkey(v10)); atomicMin(row1 + 129 + cm, fkey(v11)); }
                }
            }
        }
    }
}

// ================= [3] node MMA kernel (unchanged, 198us verified) ==========
#define NPAD1 344
#define NPAD2 72
#define NZ_H 0
#define NZ_L 44032
#define NH_H 88064
#define NH_L 97280
#define NB_BH 106496
#define NB_B2 106752
#define N_SMEM 107008
#define NODE_HALF 304

__global__ void __launch_bounds__(256, 2) node_mma_kernel(
    const float* __restrict__ gcx, const unsigned* __restrict__ aggc,
    const float* __restrict__ w2a, const float* __restrict__ b2a, int NC,
    const float* __restrict__ gsx, const unsigned* __restrict__ aggs,
    const float* __restrict__ w2b, const float* __restrict__ b2b, int NS,
    const float* __restrict__ whbase, const float* __restrict__ bhbase,
    float* __restrict__ out) {
    extern __shared__ char sm[];
    const uint32_t smb = smem_to_u32(sm);
    const int tid = threadIdx.x, lane = tid & 31, wid = tid >> 5;
    const bool d2 = blockIdx.x >= NODE_HALF;
    const float* x = d2 ? gsx : gcx;
    const unsigned* agg = d2 ? aggs : aggc;
    const float* w2 = d2 ? w2b : w2a;
    const float* b2v = d2 ? b2b : b2a;
    const float* wh = whbase + (d2 ? (size_t)336 * 64 : 0);
    const float* bh = bhbase + (d2 ? 64 : 0);
    const int N = d2 ? NS : NC;
    float* outp = out + (d2 ? (size_t)NC * 64 : 0);
    const int bid0 = blockIdx.x - (d2 ? NODE_HALF : 0);

    float* s_bh = (float*)(sm + NB_BH);
    float* s_b2 = (float*)(sm + NB_B2);

    for (int idx = tid; idx < 64 * 344; idx += 256) {
        int n = idx / 344, k = idx - n * 344;
        float w = (k < 336) ? __ldg(wh + k * 64 + n) : 0.f;
        ((__half*)(sm + NZ_H))[n * NPAD1 + k] = __float2half_rn(w);
    }
    for (int idx = tid; idx < 64 * 72; idx += 256) {
        int n = idx / 72, k = idx - n * 72;
        float w = (k < 64) ? __ldg(w2 + k * 64 + n) : 0.f;
        ((__half*)(sm + NH_H))[n * NPAD2 + k] = __float2half_rn(w);
    }
    if (tid < 64) { s_bh[tid] = __ldg(bh + tid); s_b2[tid] = __ldg(b2v + tid); }
    __syncthreads();

    uint32_t BW[21][2], W2F[4][2];
    #pragma unroll
    for (int kf = 0; kf < 21; kf++) {
        uint32_t off = (uint32_t)((wid * 8 + (lane & 7)) * NPAD1
                        + kf * 16 + (((lane >> 3) & 1) << 3)) * 2;
        ldsm_x2(BW[kf], smb + NZ_H + off);
    }
    #pragma unroll
    for (int kf = 0; kf < 4; kf++) {
        uint32_t off = (uint32_t)((wid * 8 + (lane & 7)) * NPAD2
                        + kf * 16 + (((lane >> 3) & 1) << 3)) * 2;
        ldsm_x2(W2F[kf], smb + NH_H + off);
    }
    __syncthreads();

    for (int idx = tid; idx < 64 * 7; idx += 256) {
        int row = idx / 7, pp = idx - row * 7;
        uint32_t off = (uint32_t)(row * NPAD1 + 322 + pp * 2) * 2;
        *(uint32_t*)(sm + NZ_H + off) = 0u;
        *(uint32_t*)(sm + NZ_L + off) = 0u;
    }

    const int ntiles = (N + 63) >> 6;
    for (int t = bid0; t < ntiles; t += NODE_HALF) {
        const int n0 = t * 64;
        __syncthreads();

        {
            const int wr0 = wid * 8;
            const uint32_t ln2 = (uint32_t)(lane * 2);
            #pragma unroll 2
            for (int rr = 0; rr < 8; rr++) {
                const int row = wr0 + rr;
                const int gn = n0 + row;
                const bool ok = gn < N;
                const float* xr = x + (size_t)gn * 64;
                const unsigned* ar = agg + (size_t)gn * 320;
                float2 xv = ok ? __ldg((const float2*)(xr + ln2)) : make_float2(0.f, 0.f);
                uint2 q1 = ok ? __ldg((const uint2*)(ar + ln2)) : make_uint2(0u, 0u);
                uint2 q2 = ok ? __ldg((const uint2*)(ar + 64 + ln2)) : make_uint2(0u, 0u);
                uint2 mx = ok ? __ldg((const uint2*)(ar + 128 + ln2)) : make_uint2(0u, 0u);
                uint2 mn = ok ? __ldg((const uint2*)(ar + 192 + ln2))
                              : make_uint2(0xFFFFFFFFu, 0xFFFFFFFFu);
                float ks = (ok && lane == 0) ? __uint_as_float(__ldg(ar + 256)) : 0.f;

                float vmx0 = mx.x ? fdec(mx.x) : 0.f;
                float vmx1 = mx.y ? fdec(mx.y) : 0.f;
                float vmn0 = (mn.x == 0xFFFFFFFFu) ? 0.f : fdec(mn.x);
                float vmn1 = (mn.y == 0xFFFFFFFFu) ? 0.f : fdec(mn.y);

                uint32_t rb2 = (uint32_t)(row * NPAD1 + lane * 2) * 2;
                st_pair(sm, NZ_H + rb2,           NZ_L + rb2,           xv.x, xv.y);
                st_pair(sm, NZ_H + rb2 + 64 * 2,  NZ_L + rb2 + 64 * 2,
                        __uint_as_float(q1.x), __uint_as_float(q1.y));
                st_pair(sm, NZ_H + rb2 + 128 * 2, NZ_L + rb2 + 128 * 2,
                        __uint_as_float(q2.x), __uint_as_float(q2.y));
                st_pair(sm, NZ_H + rb2 + 192 * 2, NZ_L + rb2 + 192 * 2, vmx0, vmx1);
                st_pair(sm, NZ_H + rb2 + 256 * 2, NZ_L + rb2 + 256 * 2, vmn0, vmn1);
                if (lane == 0) {
                    uint32_t kb = (uint32_t)(row * NPAD1 + 320) * 2;
                    st_pair(sm, NZ_H + kb, NZ_L + kb, ks, 0.f);
                }
            }
        }
        __syncthreads();

        #pragma unroll
        for (int mt = 0; mt < 4; mt++) {
            float c[4] = {0.f, 0.f, 0.f, 0.f};
            #pragma unroll
            for (int kf = 0; kf < 21; kf++) {
                uint32_t Ah[4], Al[4];
                uint32_t aoff = (uint32_t)((mt * 16 + (lane & 15)) * NPAD1
                                 + kf * 16 + ((lane >> 4) << 3)) * 2;
                ldsm_x4(Ah, smb + NZ_H + aoff);
                ldsm_x4(Al, smb + NZ_L + aoff);
                mma_f16(c, Ah, BW[kf]);
                mma_f16(c, Al, BW[kf]);
            }
            int r0 = mt * 16 + (lane >> 2), r1 = r0 + 8;
            int cm = wid * 8 + (lane & 3) * 2;
            float ba = s_bh[cm], bb = s_bh[cm + 1];
            float h00 = fmaxf(c[0] + ba, 0.f), h01 = fmaxf(c[1] + bb, 0.f);
            float h10 = fmaxf(c[2] + ba, 0.f), h11 = fmaxf(c[3] + bb, 0.f);
            st_pair(sm, NH_H + (uint32_t)(r0 * NPAD2 + cm) * 2,
                        NH_L + (uint32_t)(r0 * NPAD2 + cm) * 2, h00, h01);
            st_pair(sm, NH_H + (uint32_t)(r1 * NPAD2 + cm) * 2,
                        NH_L + (uint32_t)(r1 * NPAD2 + cm) * 2, h10, h11);
        }
        __syncthreads();

        #pragma unroll
        for (int mt = 0; mt < 4; mt++) {
            float c[4] = {0.f, 0.f, 0.f, 0.f};
            #pragma unroll
            for (int kf = 0; kf < 4; kf++) {
                uint32_t Ah[4], Al[4];
                uint32_t aoff = (uint32_t)((mt * 16 + (lane & 15)) * NPAD2
                                 + kf * 16 + ((lane >> 4) << 3)) * 2;
                ldsm_x4(Ah, smb + NH_H + aoff);
                ldsm_x4(Al, smb + NH_L + aoff);
                mma_f16(c, Ah, W2F[kf]);
                mma_f16(c, Al, W2F[kf]);
            }
            int r0 = mt * 16 + (lane >> 2), r1 = r0 + 8;
            int cm = wid * 8 + (lane & 3) * 2;
            float ba = s_b2[cm], bb = s_b2[cm + 1];
            int gn0 = n0 + r0, gn1 = n0 + r1;
            if (gn0 < N) *(float2*)(outp + (size_t)gn0 * 64 + cm) = make_float2(c[0] + ba, c[1] + bb);
            if (gn1 < N) *(float2*)(outp + (size_t)gn1 * 64 + cm) = make_float2(c[2] + ba, c[3] + bb);
        }
    }
}

// ---------------------------------------------------------------------------
extern "C" void kernel_launch(void* const* d_in, const int* in_sizes, int n_in,
                              void* d_out, int out_size) {
    const float* nf_gc  = (const float*)d_in[0];
    const float* nf_gs  = (const float*)d_in[1];
    const float* w_gc   = (const float*)d_in[2];
    const float* b_gc   = (const float*)d_in[3];
    const float* w_gs   = (const float*)d_in[4];
    const float* b_gs   = (const float*)d_in[5];
    const float* s2c_w1 = (const float*)d_in[6];
    const float* s2c_b1 = (const float*)d_in[7];
    const float* s2c_w2 = (const float*)d_in[8];
    const float* s2c_b2 = (const float*)d_in[9];
    const float* s2c_rw = (const float*)d_in[10];
    const float* s2c_rb = (const float*)d_in[11];
    const float* c2s_w1 = (const float*)d_in[12];
    const float* c2s_b1 = (const float*)d_in[13];
    const float* c2s_w2 = (const float*)d_in[14];
    const float* c2s_b2 = (const float*)d_in[15];
    const float* c2s_rw = (const float*)d_in[16];
    const float* c2s_rb = (const float*)d_in[17];
    const float* gc_w1  = (const float*)d_in[18];
    const float* gc_b1  = (const float*)d_in[19];
    const float* gc_w2  = (const float*)d_in[20];
    const float* gc_b2  = (const float*)d_in[21];
    const float* gs_w1  = (const float*)d_in[22];
    const float* gs_b1  = (const float*)d_in[23];
    const float* gs_w2  = (const float*)d_in[24];
    const float* gs_b2  = (const float*)d_in[25];
    const int* s2c_src  = (const int*)d_in[26];
    const int* s2c_dst  = (const int*)d_in[27];
    const int* c2s_src  = (const int*)d_in[28];
    const int* c2s_dst  = (const int*)d_in[29];

    const int FGC = in_sizes[2] / 64;
    const int FGS = in_sizes[4] / 64;
    const int NGC = in_sizes[0] / FGC;
    const int NGS = in_sizes[1] / FGS;
    const int E1 = in_sizes[26];
    const int E2 = in_sizes[28];

    float *gcx, *gsx, *whp, *bhp;
    unsigned *aggc, *aggs;
    cudaGetSymbolAddress((void**)&gcx, g_gcx);
    cudaGetSymbolAddress((void**)&gsx, g_gsx);
    cudaGetSymbolAddress((void**)&aggc, g_aggc);
    cudaGetSymbolAddress((void**)&aggs, g_aggs);
    cudaGetSymbolAddress((void**)&whp, g_wh);
    cudaGetSymbolAddress((void**)&bhp, g_bh);

    cudaFuncSetAttribute(edge_both_kernel, cudaFuncAttributeMaxDynamicSharedMemorySize, EX_SMEM);
    cudaFuncSetAttribute(node_mma_kernel, cudaFuncAttributeMaxDynamicSharedMemorySize, N_SMEM);

    // [0] init + embed
    int total0 = (NGC + NGS) * 257 + (NGC + NGS) * 64;
    init_embed_kernel<<<(total0 + 255) / 256, 256>>>(
        aggc, aggs, NGC, NGS,
        nf_gc, w_gc, b_gc, gcx, FGC, nf_gs, w_gs, b_gs, gsx, FGS);
    // [1] whfold
    whfold_kernel<<<674, 64>>>(
        s2c_rw, s2c_w2, s2c_b2, gc_w1, gc_b1, s2c_rb,
        c2s_rw, c2s_w2, c2s_b2, gs_w1, gs_b1, c2s_rb, whp, bhp);
    // [2] edge both
    edge_both_kernel<<<608, 256, EX_SMEM>>>(
        gcx, gsx,
        s2c_src, s2c_dst, s2c_w1, s2c_w2, s2c_b1, s2c_b2, aggc, E1,
        c2s_src, c2s_dst, c2s_w1, c2s_w2, c2s_b1, c2s_b2, aggs, E2);
    // [3] node MMA (profiled slot)
    float* out = (float*)d_out;
    node_mma_kernel<<<608, 256, N_SMEM>>>(
        gcx, aggc, gc_w2, gc_b2, NGC,
        gsx, aggs, gs_w2, gs_b2, NGS, whp, bhp, out);
}